// round 6
// baseline (speedup 1.0000x reference)
#include <cuda_runtime.h>
#include <cuda_bf16.h>
#include <cuda_fp16.h>
#include <cstdint>

// Problem constants
#define Bsz   4
#define Ssz   2048
#define HID   2048
#define HEADS 16
#define HDIM  128
#define MBsz  16
#define NCH   128
#define Mrows (Bsz*Ssz)    // 8192
#define Kdim  2048
#define Ndim  2048

// Scratch (device globals: allocation-free rule). Element type is 16-bit;
// interpreted as fp16 for the k/v GEMMs and bf16 for the output GEMM.
__device__ float g_k[(size_t)Mrows * HID];
__device__ float g_v[(size_t)Mrows * HID];
__device__ float g_o[(size_t)Mrows * HID];
__device__ uint16_t g_ahi[(size_t)Mrows * HID];
__device__ uint16_t g_alo[(size_t)Mrows * HID];
__device__ uint16_t g_whi[(size_t)HID * HID];
__device__ uint16_t g_wlo[(size_t)HID * HID];

// ---------------------------------------------------------------------------
// helpers (baseline PTX only: cp.async / ldmatrix / mma.sync — sm_80 features)
// ---------------------------------------------------------------------------
__device__ __forceinline__ uint32_t smem_u32(const void* p) {
    uint32_t a;
    asm("{ .reg .u64 t; cvta.to.shared.u64 t, %1; cvt.u32.u64 %0, t; }"
        : "=r"(a) : "l"(p));
    return a;
}

#define SWZ(x) ((x) ^ (((x) >> 3) & 0x70))

__device__ __forceinline__ void cp16(uint32_t dst, const void* src) {
    asm volatile("cp.async.cg.shared.global [%0], [%1], 16;\n"
                 :: "r"(dst), "l"(src) : "memory");
}
__device__ __forceinline__ void cp_commit() {
    asm volatile("cp.async.commit_group;\n" ::: "memory");
}
template <int N> __device__ __forceinline__ void cp_wait() {
    asm volatile("cp.async.wait_group %0;\n" :: "n"(N) : "memory");
}

__device__ __forceinline__ void ldsm4(uint32_t r[4], uint32_t a) {
    asm volatile("ldmatrix.sync.aligned.m8n8.x4.shared.b16 {%0,%1,%2,%3}, [%4];"
                 : "=r"(r[0]), "=r"(r[1]), "=r"(r[2]), "=r"(r[3]) : "r"(a));
}

// bf16 mma
__device__ __forceinline__ void mma16816(float c[4], const uint32_t a[4],
                                         const uint32_t b0, const uint32_t b1) {
    asm volatile(
        "mma.sync.aligned.m16n8k16.row.col.f32.bf16.bf16.f32 "
        "{%0,%1,%2,%3}, {%4,%5,%6,%7}, {%8,%9}, {%0,%1,%2,%3};"
        : "+f"(c[0]), "+f"(c[1]), "+f"(c[2]), "+f"(c[3])
        : "r"(a[0]), "r"(a[1]), "r"(a[2]), "r"(a[3]), "r"(b0), "r"(b1));
}
// fp16 mma
__device__ __forceinline__ void mma16816h(float c[4], const uint32_t a[4],
                                          const uint32_t b0, const uint32_t b1) {
    asm volatile(
        "mma.sync.aligned.m16n8k16.row.col.f32.f16.f16.f32 "
        "{%0,%1,%2,%3}, {%4,%5,%6,%7}, {%8,%9}, {%0,%1,%2,%3};"
        : "+f"(c[0]), "+f"(c[1]), "+f"(c[2]), "+f"(c[3])
        : "r"(a[0]), "r"(a[1]), "r"(a[2]), "r"(a[3]), "r"(b0), "r"(b1));
}

__device__ __forceinline__ void bsplit(float x, uint16_t& h, uint16_t& l) {
    __nv_bfloat16 hb = __float2bfloat16_rn(x);
    __nv_bfloat16 lb = __float2bfloat16_rn(x - __bfloat162float(hb));
    h = *(uint16_t*)&hb;
    l = *(uint16_t*)&lb;
}
__device__ __forceinline__ void hsplit(float x, uint16_t& h, uint16_t& l) {
    __half hb = __float2half_rn(x);
    __half lb = __float2half_rn(x - __half2float(hb));
    h = *(uint16_t*)&hb;
    l = *(uint16_t*)&lb;
}

// ---------------------------------------------------------------------------
// converters
// ---------------------------------------------------------------------------
__global__ __launch_bounds__(256)
void cvt_hilo_bf(const float* __restrict__ s,
                 uint16_t* __restrict__ hi,
                 uint16_t* __restrict__ lo, int n4)
{
    int i = blockIdx.x * blockDim.x + threadIdx.x;
    if (i >= n4) return;
    float4 v = ((const float4*)s)[i];
    uint16_t h[4], l[4];
    bsplit(v.x, h[0], l[0]); bsplit(v.y, h[1], l[1]);
    bsplit(v.z, h[2], l[2]); bsplit(v.w, h[3], l[3]);
    *(uint64_t*)(hi + 4 * (size_t)i) = *(uint64_t*)h;
    *(uint64_t*)(lo + 4 * (size_t)i) = *(uint64_t*)l;
}

__global__ __launch_bounds__(256)
void cvt_hilo_h(const float* __restrict__ s,
                uint16_t* __restrict__ hi,
                uint16_t* __restrict__ lo, int n4)
{
    int i = blockIdx.x * blockDim.x + threadIdx.x;
    if (i >= n4) return;
    float4 v = ((const float4*)s)[i];
    uint16_t h[4], l[4];
    hsplit(v.x, h[0], l[0]); hsplit(v.y, h[1], l[1]);
    hsplit(v.z, h[2], l[2]); hsplit(v.w, h[3], l[3]);
    *(uint64_t*)(hi + 4 * (size_t)i) = *(uint64_t*)h;
    *(uint64_t*)(lo + 4 * (size_t)i) = *(uint64_t*)l;
}

__global__ __launch_bounds__(256)
void cvt_hi_h(const float* __restrict__ s,
              uint16_t* __restrict__ hi, int n4)
{
    int i = blockIdx.x * blockDim.x + threadIdx.x;
    if (i >= n4) return;
    float4 v = ((const float4*)s)[i];
    uint16_t h[4];
    __half a = __float2half_rn(v.x), b = __float2half_rn(v.y);
    __half c = __float2half_rn(v.z), d = __float2half_rn(v.w);
    h[0] = *(uint16_t*)&a; h[1] = *(uint16_t*)&b;
    h[2] = *(uint16_t*)&c; h[3] = *(uint16_t*)&d;
    *(uint64_t*)(hi + 4 * (size_t)i) = *(uint64_t*)h;
}

// ---------------------------------------------------------------------------
// fp16 2-product GEMM: C = (Ah+Al) @ Bh^T.  CTA tile 128x128, BK=64, GS=2,
// 2 CTAs/SM, 8 warps, warp tile 64(m) x 32(n).
// ---------------------------------------------------------------------------
#define TILE_B   16384
#define H2_STAGE (3 * TILE_B)            // Ahi, Alo, Bh = 48KB
#define H2_SMEM  (1024 + 2 * H2_STAGE)   // 99328
#define KTILES   (Kdim / 64)             // 32

__global__ __launch_bounds__(256, 2)
void gemm_h2_kernel(const uint16_t* __restrict__ Ahi,
                    const uint16_t* __restrict__ Alo,
                    const uint16_t* __restrict__ Bh,
                    float* __restrict__ C)
{
    extern __shared__ uint8_t smraw[];
    const uint32_t s0 = (smem_u32(smraw) + 1023u) & ~1023u;

    const int tid  = threadIdx.x;
    const int wid  = tid >> 5;
    const int lane = tid & 31;
    const int wm   = wid & 1;        // 2 m-warps, 64 rows
    const int wn   = wid >> 1;       // 4 n-warps, 32 cols
    const int m0 = blockIdx.y * 128;
    const int n0 = blockIdx.x * 128;

    uint32_t aBase[4];
    {
        int amat = lane >> 3, al = lane & 7;
        int rofs = ((amat & 1) << 3) + al;
        uint32_t akb = (uint32_t)((amat >> 1) << 4);
#pragma unroll
        for (int mf = 0; mf < 4; ++mf) {
            uint32_t r = (uint32_t)(wm * 64 + mf * 16 + rofs) * 128u;
            aBase[mf] = SWZ(r) ^ akb;
        }
    }
    uint32_t bBase[2];
    {
        int bmat = lane >> 3, bl = lane & 7;
        int rofs = ((bmat >> 1) << 3) + bl;
        uint32_t bkb = (uint32_t)((bmat & 1) << 4);
#pragma unroll
        for (int nfp = 0; nfp < 2; ++nfp) {
            uint32_t r = (uint32_t)(wn * 32 + nfp * 16 + rofs) * 128u;
            bBase[nfp] = SWZ(r) ^ bkb;
        }
    }

    auto load_stage = [&](int kt) {
        uint32_t sb = s0 + (uint32_t)(kt & 1) * H2_STAGE;
        const size_t kof = (size_t)kt * 64;
#pragma unroll
        for (int j = 0; j < 4; ++j) {
            int q = j * 256 + tid;
            int row = q >> 3, ch = q & 7;
            uint32_t so = SWZ((uint32_t)(row * 128 + ch * 16));
            size_t ga = (size_t)(m0 + row) * Kdim + kof + (size_t)ch * 8;
            size_t gb = (size_t)(n0 + row) * Kdim + kof + (size_t)ch * 8;
            cp16(sb + so,              Ahi + ga);
            cp16(sb + TILE_B + so,     Alo + ga);
            cp16(sb + 2 * TILE_B + so, Bh + gb);
        }
        cp_commit();
    };

    float acc[4][4][4];
#pragma unroll
    for (int i = 0; i < 4; ++i)
#pragma unroll
        for (int j = 0; j < 4; ++j)
#pragma unroll
            for (int r = 0; r < 4; ++r) acc[i][j][r] = 0.f;

    load_stage(0);

    for (int it = 0; it < KTILES; ++it) {
        cp_wait<0>();
        __syncthreads();          // stage `it` resident; buffer (it+1)&1 free
        if (it + 1 < KTILES) load_stage(it + 1);

        const uint32_t sb = s0 + (uint32_t)(it & 1) * H2_STAGE;
#pragma unroll
        for (int kk = 0; kk < 4; ++kk) {
            const uint32_t kx = (uint32_t)(kk * 32);
            uint32_t ah[4][4], al[4][4];
#pragma unroll
            for (int mf = 0; mf < 4; ++mf) {
                ldsm4(ah[mf], sb + (aBase[mf] ^ kx));
                ldsm4(al[mf], sb + TILE_B + (aBase[mf] ^ kx));
            }
            uint32_t bh[4][2];
#pragma unroll
            for (int nfp = 0; nfp < 2; ++nfp) {
                uint32_t t[4];
                ldsm4(t, sb + 2 * TILE_B + (bBase[nfp] ^ kx));
                bh[2 * nfp][0] = t[0]; bh[2 * nfp][1] = t[1];
                bh[2 * nfp + 1][0] = t[2]; bh[2 * nfp + 1][1] = t[3];
            }
#pragma unroll
            for (int mf = 0; mf < 4; ++mf)
#pragma unroll
                for (int nf = 0; nf < 4; ++nf) {
                    mma16816h(acc[mf][nf], ah[mf], bh[nf][0], bh[nf][1]);
                    mma16816h(acc[mf][nf], al[mf], bh[nf][0], bh[nf][1]);
                }
        }
        __syncthreads();          // all warps done reading stage `it`
    }

    const int cm = (lane >> 2);
    const int cn = (lane & 3) * 2;
#pragma unroll
    for (int mf = 0; mf < 4; ++mf) {
        const int row = m0 + wm * 64 + mf * 16 + cm;
#pragma unroll
        for (int nf = 0; nf < 4; ++nf) {
            const int col = n0 + wn * 32 + nf * 8 + cn;
            *(float2*)(C + (size_t)row * Ndim + col) =
                make_float2(acc[mf][nf][0], acc[mf][nf][1]);
            *(float2*)(C + (size_t)(row + 8) * Ndim + col) =
                make_float2(acc[mf][nf][2], acc[mf][nf][3]);
        }
    }
}

// ---------------------------------------------------------------------------
// bf16 3-product GEMM (R4-proven): C = A @ B^T + Res
// ---------------------------------------------------------------------------
#define GS      3
#define STAGE_B (4 * TILE_B)
#define GEMM_SMEM (1024 + GS * STAGE_B)

__global__ __launch_bounds__(256, 1)
void gemm_mma_kernel(const uint16_t* __restrict__ Ahi,
                     const uint16_t* __restrict__ Alo,
                     const uint16_t* __restrict__ Bhi,
                     const uint16_t* __restrict__ Blo,
                     float* __restrict__ C,
                     const float* __restrict__ Res)
{
    extern __shared__ uint8_t smraw[];
    const uint32_t s0 = (smem_u32(smraw) + 1023u) & ~1023u;

    const int tid  = threadIdx.x;
    const int wid  = tid >> 5;
    const int lane = tid & 31;
    const int wm   = wid & 1;
    const int wn   = wid >> 1;
    const int m0 = blockIdx.y * 128;
    const int n0 = blockIdx.x * 128;

    uint32_t aBase[4];
    {
        int amat = lane >> 3, al = lane & 7;
        int rofs = ((amat & 1) << 3) + al;
        uint32_t akb = (uint32_t)((amat >> 1) << 4);
#pragma unroll
        for (int mf = 0; mf < 4; ++mf) {
            uint32_t r = (uint32_t)(wm * 64 + mf * 16 + rofs) * 128u;
            aBase[mf] = SWZ(r) ^ akb;
        }
    }
    uint32_t bBase[2];
    {
        int bmat = lane >> 3, bl = lane & 7;
        int rofs = ((bmat >> 1) << 3) + bl;
        uint32_t bkb = (uint32_t)((bmat & 1) << 4);
#pragma unroll
        for (int nfp = 0; nfp < 2; ++nfp) {
            uint32_t r = (uint32_t)(wn * 32 + nfp * 16 + rofs) * 128u;
            bBase[nfp] = SWZ(r) ^ bkb;
        }
    }

    auto load_stage = [&](int kt) {
        uint32_t sb = s0 + (uint32_t)(kt % GS) * STAGE_B;
        const size_t kof = (size_t)kt * 64;
#pragma unroll
        for (int j = 0; j < 4; ++j) {
            int q = j * 256 + tid;
            int row = q >> 3, ch = q & 7;
            uint32_t so = SWZ((uint32_t)(row * 128 + ch * 16));
            size_t ga = (size_t)(m0 + row) * Kdim + kof + (size_t)ch * 8;
            size_t gb = (size_t)(n0 + row) * Kdim + kof + (size_t)ch * 8;
            cp16(sb + so,              Ahi + ga);
            cp16(sb + TILE_B + so,     Alo + ga);
            cp16(sb + 2 * TILE_B + so, Bhi + gb);
            cp16(sb + 3 * TILE_B + so, Blo + gb);
        }
        cp_commit();
    };

    float acc[4][4][4];
#pragma unroll
    for (int i = 0; i < 4; ++i)
#pragma unroll
        for (int j = 0; j < 4; ++j)
#pragma unroll
            for (int r = 0; r < 4; ++r) acc[i][j][r] = 0.f;

    load_stage(0);
    load_stage(1);

    for (int it = 0; it < KTILES; ++it) {
        cp_wait<1>();
        __syncthreads();
        if (it + 2 < KTILES) load_stage(it + 2);

        const uint32_t sb = s0 + (uint32_t)(it % GS) * STAGE_B;
#pragma unroll
        for (int kk = 0; kk < 4; ++kk) {
            const uint32_t kx = (uint32_t)(kk * 32);
            uint32_t ah[4][4], al[4][4];
#pragma unroll
            for (int mf = 0; mf < 4; ++mf) {
                ldsm4(ah[mf], sb + (aBase[mf] ^ kx));
                ldsm4(al[mf], sb + TILE_B + (aBase[mf] ^ kx));
            }
            uint32_t bh[4][2], bl[4][2];
#pragma unroll
            for (int nfp = 0; nfp < 2; ++nfp) {
                uint32_t t[4];
                ldsm4(t, sb + 2 * TILE_B + (bBase[nfp] ^ kx));
                bh[2 * nfp][0] = t[0]; bh[2 * nfp][1] = t[1];
                bh[2 * nfp + 1][0] = t[2]; bh[2 * nfp + 1][1] = t[3];
                ldsm4(t, sb + 3 * TILE_B + (bBase[nfp] ^ kx));
                bl[2 * nfp][0] = t[0]; bl[2 * nfp][1] = t[1];
                bl[2 * nfp + 1][0] = t[2]; bl[2 * nfp + 1][1] = t[3];
            }
#pragma unroll
            for (int mf = 0; mf < 4; ++mf)
#pragma unroll
                for (int nf = 0; nf < 4; ++nf) {
                    mma16816(acc[mf][nf], ah[mf], bh[nf][0], bh[nf][1]);
                    mma16816(acc[mf][nf], ah[mf], bl[nf][0], bl[nf][1]);
                    mma16816(acc[mf][nf], al[mf], bh[nf][0], bh[nf][1]);
                }
        }
    }

    const int cm = (lane >> 2);
    const int cn = (lane & 3) * 2;
#pragma unroll
    for (int mf = 0; mf < 4; ++mf) {
        const int row = m0 + wm * 64 + mf * 16 + cm;
#pragma unroll
        for (int nf = 0; nf < 4; ++nf) {
            const int col = n0 + wn * 32 + nf * 8 + cn;
            float2 v0 = make_float2(acc[mf][nf][0], acc[mf][nf][1]);
            float2 v1 = make_float2(acc[mf][nf][2], acc[mf][nf][3]);
            if (Res) {
                float2 r0 = *(const float2*)(Res + (size_t)row * Ndim + col);
                float2 r1 = *(const float2*)(Res + (size_t)(row + 8) * Ndim + col);
                v0.x += r0.x; v0.y += r0.y;
                v1.x += r1.x; v1.y += r1.y;
            }
            *(float2*)(C + (size_t)row * Ndim + col)       = v0;
            *(float2*)(C + (size_t)(row + 8) * Ndim + col) = v1;
        }
    }
}

// ---------------------------------------------------------------------------
// RoPE on g_k
// ---------------------------------------------------------------------------
__global__ void rope_kernel(float* __restrict__ k)
{
    const int gid = blockIdx.x * blockDim.x + threadIdx.x;
    const int total = Bsz * Ssz * HEADS * (HDIM / 2);
    if (gid >= total) return;
    const int i   = gid & 63;
    const int h   = (gid >> 6) & (HEADS - 1);
    const int row = gid >> 10;
    const int s   = row & (Ssz - 1);

    const float c = 0.20762050593046013f;   // log2(10000)/64
    const float inv = exp2f(-c * (float)i);
    const float ang = (float)s * inv;
    float sn = sinf(ang), cs = cosf(ang);

    float* p = k + (size_t)row * HID + h * HDIM;
    const float k1 = p[i];
    const float k2 = p[i + 64];
    p[i]      = k1 * cs - k2 * sn;
    p[i + 64] = k2 * cs + k1 * sn;
}

// ---------------------------------------------------------------------------
// Tensor-core TTT scan (R4-validated). Grid (64 bh, 2 e-halves), 128 threads.
// ---------------------------------------------------------------------------
#define OFF_RAWK   0
#define OFF_RAWV   16384
#define OFF_KHI    24576
#define OFF_KLO    32768
#define OFF_KTHI   40960
#define OFF_KTLO   47104
#define OFF_ETHI   53248
#define OFF_ETLO   56320
#define OFF_WTHI   59392
#define OFF_WTLO   75776
#define SCAN2_SMEM 92160

__global__ __launch_bounds__(128, 1)
void ttt_scan_mma(const float* __restrict__ gk,
                  const float* __restrict__ gv,
                  const float* __restrict__ W0,
                  float*       __restrict__ go)
{
    extern __shared__ __align__(16) char sm[];
    const uint32_t sb = smem_u32(sm);

    const int tid  = threadIdx.x;
    const int wid  = tid >> 5;
    const int lane = tid & 31;
    const int bh = blockIdx.x;
    const int eh = blockIdx.y;
    const int b  = bh >> 4, h = bh & 15;
    const int e0 = eh * 64;

    const int mat = lane >> 3, ml = lane & 7;
    const int arow = ((mat & 1) << 3) + ml;
    const uint32_t akb = (uint32_t)((mat >> 1) << 4);
    const int brow = ((mat >> 1) << 3) + ml;
    const uint32_t bkb = (uint32_t)((mat & 1) << 4);

    const uint32_t aBaseK = SWZ((uint32_t)(arow * 128)) ^ akb;
    const uint32_t bBaseW = SWZ((uint32_t)((16 * wid + brow) * 128)) ^ bkb;

    const int cr = lane >> 2;
    const int cc = (lane & 3) * 2;

    float W[2][8][4];
    {
        const float* W0p = W0 + (size_t)bh * (HDIM * HDIM);
#pragma unroll
        for (int t2 = 0; t2 < 2; ++t2) {
            int dt = 32 * wid + 16 * t2;
#pragma unroll
            for (int j = 0; j < 8; ++j) {
                int e = e0 + 8 * j + cc;
                W[t2][j][0] = W0p[(size_t)(dt + cr) * 128 + e];
                W[t2][j][1] = W0p[(size_t)(dt + cr) * 128 + e + 1];
                W[t2][j][2] = W0p[(size_t)(dt + cr + 8) * 128 + e];
                W[t2][j][3] = W0p[(size_t)(dt + cr + 8) * 128 + e + 1];
            }
        }
    }

    const float* kbase = gk + (size_t)b * Ssz * HID + h * HDIM;
    const float* vbase = gv + (size_t)b * Ssz * HID + h * HDIM + e0;
    float*       obase = go + (size_t)b * Ssz * HID + h * HDIM + e0;

    auto dumpW = [&]() {
#pragma unroll
        for (int t2 = 0; t2 < 2; ++t2) {
            int dt = 32 * wid + 16 * t2;
#pragma unroll
            for (int j = 0; j < 8; ++j) {
                int e = 8 * j + cc;
#pragma unroll
                for (int q = 0; q < 4; ++q) {
                    int d  = dt + cr + ((q >> 1) << 3);
                    int ee = e + (q & 1);
                    uint16_t hh, ll;
                    bsplit(W[t2][j][q], hh, ll);
                    uint32_t half = (uint32_t)(d >> 6);
                    uint32_t a = SWZ((uint32_t)(ee * 128 + (d & 63) * 2));
                    *(uint16_t*)(sm + OFF_WTHI + half * 8192 + a) = hh;
                    *(uint16_t*)(sm + OFF_WTLO + half * 8192 + a) = ll;
                }
            }
        }
    };

    auto loadKV = [&](int c) {
        int buf = c & 1;
        const float* ks = kbase + (size_t)(c * 16) * HID;
        const float* vs = vbase + (size_t)(c * 16) * HID;
#pragma unroll
        for (int j = 0; j < 4; ++j) {
            int q = j * 128 + tid;
            int row = q >> 5, ch = q & 31;
            cp16(sb + OFF_RAWK + buf * 8192 + (uint32_t)(row * 512 + ch * 16),
                 ks + (size_t)row * HID + ch * 4);
        }
#pragma unroll
        for (int j = 0; j < 2; ++j) {
            int q = j * 128 + tid;
            int row = q >> 4, ch = q & 15;
            cp16(sb + OFF_RAWV + buf * 4096 + (uint32_t)(row * 256 + ch * 16),
                 vs + (size_t)row * HID + ch * 4);
        }
        cp_commit();
    };

    auto convK = [&](int c) {
        int buf = c & 1;
        const float* rk = (const float*)(sm + OFF_RAWK + buf * 8192);
        int m = tid >> 3, c16 = (tid & 7) * 16;
        __align__(16) uint16_t hb[16], lb[16];
#pragma unroll
        for (int i = 0; i < 16; ++i) bsplit(rk[m * 128 + c16 + i], hb[i], lb[i]);
        uint32_t half = (uint32_t)(c16 >= 64);
        uint32_t ccl  = (uint32_t)((c16 & 63) * 2);
        uint32_t a0 = SWZ((uint32_t)(m * 128) + ccl);
        uint32_t a1 = SWZ((uint32_t)(m * 128) + ccl + 16);
        uint32_t kb = (uint32_t)(OFF_KHI + buf * 4096 + half * 2048);
        *(uint4*)(sm + kb + a0) = *(uint4*)&hb[0];
        *(uint4*)(sm + kb + a1) = *(uint4*)&hb[8];
        kb = (uint32_t)(OFF_KLO + buf * 4096 + half * 2048);
        *(uint4*)(sm + kb + a0) = *(uint4*)&lb[0];
        *(uint4*)(sm + kb + a1) = *(uint4*)&lb[8];
    };

    auto convKT = [&](int c) {
        int buf = c & 1;
        const float* rk = (const float*)(sm + OFF_RAWK + buf * 8192);
        int d = tid;
        __align__(16) uint16_t th[16], tl[16];
#pragma unroll
        for (int m = 0; m < 16; ++m) bsplit(rk[m * 128 + d], th[m], tl[m]);
        *(uint4*)(sm + OFF_KTHI + d * 48)      = *(uint4*)&th[0];
        *(uint4*)(sm + OFF_KTHI + d * 48 + 16) = *(uint4*)&th[8];
        *(uint4*)(sm + OFF_KTLO + d * 48)      = *(uint4*)&tl[0];
        *(uint4*)(sm + OFF_KTLO + d * 48 + 16) = *(uint4*)&tl[8];
    };

    float P[2][4];

    auto predOnly = [&](int buf, float acc[2][4]) {
#pragma unroll
        for (int f = 0; f < 2; ++f)
#pragma unroll
            for (int q = 0; q < 4; ++q) acc[f][q] = 0.f;
#pragma unroll
        for (int kk = 0; kk < 8; ++kk) {
            uint32_t half = (uint32_t)(kk >> 2);
            uint32_t kx   = (uint32_t)((kk & 3) * 32);
            uint32_t ah[4], al[4], t[4], bh[2][2], bl[2][2];
            ldsm4(ah, sb + OFF_KHI + buf * 4096 + half * 2048 + (aBaseK ^ kx));
            ldsm4(al, sb + OFF_KLO + buf * 4096 + half * 2048 + (aBaseK ^ kx));
            ldsm4(t, sb + OFF_WTHI + half * 8192 + (bBaseW ^ kx));
            bh[0][0] = t[0]; bh[0][1] = t[1]; bh[1][0] = t[2]; bh[1][1] = t[3];
            ldsm4(t, sb + OFF_WTLO + half * 8192 + (bBaseW ^ kx));
            bl[0][0] = t[0]; bl[0][1] = t[1]; bl[1][0] = t[2]; bl[1][1] = t[3];
#pragma unroll
            for (int f = 0; f < 2; ++f) {
                mma16816(acc[f], ah, bh[f][0], bh[f][1]);
                mma16816(acc[f], ah, bl[f][0], bl[f][1]);
                mma16816(acc[f], al, bh[f][0], bh[f][1]);
            }
        }
    };

    dumpW();
    loadKV(0);
    cp_wait<0>();
    __syncthreads();
    convK(0);
    __syncthreads();
    predOnly(0, P);

    for (int c = 0; c < NCH; ++c) {
        const int buf = c & 1;
        const bool hasNext = (c + 1 < NCH);
        if (hasNext) loadKV(c + 1);

        convKT(c);

        {
            const float* rv = (const float*)(sm + OFF_RAWV + buf * 4096);
#pragma unroll
            for (int f = 0; f < 2; ++f)
#pragma unroll
                for (int q = 0; q < 4; ++q) {
                    int e = 16 * wid + 8 * f + cc + (q & 1);
                    int m = cr + ((q >> 1) << 3);
                    float ep = (rv[m * 64 + e] - P[f][q]) * 0.0009765625f;
                    uint16_t hh, ll;
                    bsplit(ep, hh, ll);
                    *(uint16_t*)(sm + OFF_ETHI + e * 48 + m * 2) = hh;
                    *(uint16_t*)(sm + OFF_ETLO + e * 48 + m * 2) = ll;
                }
        }
        __syncthreads();

        {
            uint32_t aH[2][4], aL[2][4];
#pragma unroll
            for (int t2 = 0; t2 < 2; ++t2) {
                uint32_t ra = (uint32_t)((32 * wid + 16 * t2 + arow) * 48) + akb;
                ldsm4(aH[t2], sb + OFF_KTHI + ra);
                ldsm4(aL[t2], sb + OFF_KTLO + ra);
            }
#pragma unroll
            for (int p = 0; p < 4; ++p) {
                uint32_t rb = (uint32_t)((16 * p + brow) * 48) + bkb;
                uint32_t th[4], tl[4];
                ldsm4(th, sb + OFF_ETHI + rb);
                ldsm4(tl, sb + OFF_ETLO + rb);
#pragma unroll
                for (int t2 = 0; t2 < 2; ++t2) {
                    mma16816(W[t2][2 * p],     aH[t2], th[0], th[1]);
                    mma16816(W[t2][2 * p],     aH[t2], tl[0], tl[1]);
                    mma16816(W[t2][2 * p],     aL[t2], th[0], th[1]);
                    mma16816(W[t2][2 * p + 1], aH[t2], th[2], th[3]);
                    mma16816(W[t2][2 * p + 1], aH[t2], tl[2], tl[3]);
                    mma16816(W[t2][2 * p + 1], aL[t2], th[2], th[3]);
                }
            }
        }

        dumpW();

        if (hasNext) cp_wait<0>();
        __syncthreads();
        if (hasNext) convK(c + 1);
        __syncthreads();

        {
            float O[2][4];
#pragma unroll
            for (int f = 0; f < 2; ++f)
#pragma unroll
                for (int q = 0; q < 4; ++q) { O[f][q] = 0.f; P[f][q] = 0.f; }
            const int bufn = (c + 1) & 1;
#pragma unroll
            for (int kk = 0; kk < 8; ++kk) {
                uint32_t half = (uint32_t)(kk >> 2);
                uint32_t kx   = (uint32_t)((kk & 3) * 32);
                uint32_t t[4], bh[2][2], bl[2][2];
                ldsm4(t, sb + OFF_WTHI + half * 8192 + (bBaseW ^ kx));
                bh[0][0] = t[0]; bh[0][1] = t[1]; bh[1][0] = t[2]; bh[1][1] = t[3];
                ldsm4(t, sb + OFF_WTLO + half * 8192 + (bBaseW ^ kx));
                bl[0][0] = t[0]; bl[0][1] = t[1]; bl[1][0] = t[2]; bl[1][1] = t[3];

                uint32_t ah[4], al[4];
                ldsm4(ah, sb + OFF_KHI + buf * 4096 + half * 2048 + (aBaseK ^ kx));
                ldsm4(al, sb + OFF_KLO + buf * 4096 + half * 2048 + (aBaseK ^ kx));
#pragma unroll
                for (int f = 0; f < 2; ++f) {
                    mma16816(O[f], ah, bh[f][0], bh[f][1]);
                    mma16816(O[f], ah, bl[f][0], bl[f][1]);
                    mma16816(O[f], al, bh[f][0], bh[f][1]);
                }
                if (hasNext) {
                    uint32_t nh[4], nl[4];
                    ldsm4(nh, sb + OFF_KHI + bufn * 4096 + half * 2048 + (aBaseK ^ kx));
                    ldsm4(nl, sb + OFF_KLO + bufn * 4096 + half * 2048 + (aBaseK ^ kx));
#pragma unroll
                    for (int f = 0; f < 2; ++f) {
                        mma16816(P[f], nh, bh[f][0], bh[f][1]);
                        mma16816(P[f], nh, bl[f][0], bl[f][1]);
                        mma16816(P[f], nl, bh[f][0], bh[f][1]);
                    }
                }
            }
#pragma unroll
            for (int f = 0; f < 2; ++f) {
                int e = 16 * wid + 8 * f + cc;
                size_t r0 = (size_t)(c * 16 + cr) * HID + e;
                size_t r1 = (size_t)(c * 16 + cr + 8) * HID + e;
                *(float2*)(obase + r0) = make_float2(O[f][0], O[f][1]);
                *(float2*)(obase + r1) = make_float2(O[f][2], O[f][3]);
            }
        }
    }
}

// ---------------------------------------------------------------------------
// LayerNorm fused with bf16 hi/lo split (feeds the bf16 output GEMM)
// ---------------------------------------------------------------------------
__global__ __launch_bounds__(256)
void ln_cvt_kernel(const float* __restrict__ o,
                   const float* __restrict__ g,
                   const float* __restrict__ beta,
                   uint16_t* __restrict__ hi,
                   uint16_t* __restrict__ lo)
{
    __shared__ float s1[8], s2[8];
    const int row = blockIdx.x;
    const int t   = threadIdx.x;
    const float* p = o + (size_t)row * HID;

    float4 v0 = *(const float4*)(p + t * 8);
    float4 v1 = *(const float4*)(p + t * 8 + 4);
    float s  = v0.x + v0.y + v0.z + v0.w + v1.x + v1.y + v1.z + v1.w;
    float ss = v0.x*v0.x + v0.y*v0.y + v0.z*v0.z + v0.w*v0.w
             + v1.x*v1.x + v1.y*v1.y + v1.z*v1.z + v1.w*v1.w;
#pragma unroll
    for (int off = 16; off > 0; off >>= 1) {
        s  += __shfl_xor_sync(0xffffffffu, s,  off);
        ss += __shfl_xor_sync(0xffffffffu, ss, off);
    }
    const int w = t >> 5;
    if ((t & 31) == 0) { s1[w] = s; s2[w] = ss; }
    __syncthreads();
    float tot = 0.f, tot2 = 0.f;
#pragma unroll
    for (int i = 0; i < 8; ++i) { tot += s1[i]; tot2 += s2[i]; }
    const float mu  = tot * (1.0f / HID);
    const float var = tot2 * (1.0f / HID) - mu * mu;
    const float inv = rsqrtf(var + 1e-5f);

    float4 g0 = *(const float4*)(g + t * 8);
    float4 g1 = *(const float4*)(g + t * 8 + 4);
    float4 b0 = *(const float4*)(beta + t * 8);
    float4 b1 = *(const float4*)(beta + t * 8 + 4);
    float y[8];
    y[0] = (v0.x - mu) * inv * g0.x + b0.x;
    y[1] = (v0.y - mu) * inv * g0.y + b0.y;
    y[2] = (v0.z - mu) * inv * g0.z + b0.z;
    y[3] = (v0.w - mu) * inv * g0.w + b0.w;
    y[4] = (v1.x - mu) * inv * g1.x + b1.x;
    y[5] = (v1.y - mu) * inv * g1.y + b1.y;
    y[6] = (v1.z - mu) * inv * g1.z + b1.z;
    y[7] = (v1.w - mu) * inv * g1.w + b1.w;

    __align__(16) uint16_t hb[8], lb[8];
#pragma unroll
    for (int i = 0; i < 8; ++i) bsplit(y[i], hb[i], lb[i]);
    *(uint4*)(hi + (size_t)row * HID + t * 8) = *(uint4*)hb;
    *(uint4*)(lo + (size_t)row * HID + t * 8) = *(uint4*)lb;
}

// ---------------------------------------------------------------------------
// launch
// ---------------------------------------------------------------------------
extern "C" void kernel_launch(void* const* d_in, const int* in_sizes, int n_in,
                              void* d_out, int out_size)
{
    const float* x   = (const float*)d_in[0];
    const float* Wk  = (const float*)d_in[1];
    const float* Wv  = (const float*)d_in[2];
    const float* Wo  = (const float*)d_in[3];
    const float* lng = (const float*)d_in[4];
    const float* lnb = (const float*)d_in[5];
    const float* W0  = (const float*)d_in[6];
    float* out = (float*)d_out;

    float *gk, *gv, *go;
    uint16_t *ahi, *alo, *whi, *wlo;
    cudaGetSymbolAddress((void**)&gk, g_k);
    cudaGetSymbolAddress((void**)&gv, g_v);
    cudaGetSymbolAddress((void**)&go, g_o);
    cudaGetSymbolAddress((void**)&ahi, g_ahi);
    cudaGetSymbolAddress((void**)&alo, g_alo);
    cudaGetSymbolAddress((void**)&whi, g_whi);
    cudaGetSymbolAddress((void**)&wlo, g_wlo);

    cudaFuncSetAttribute(ttt_scan_mma,
                         cudaFuncAttributeMaxDynamicSharedMemorySize, SCAN2_SMEM);
    cudaFuncSetAttribute(gemm_mma_kernel,
                         cudaFuncAttributeMaxDynamicSharedMemorySize, GEMM_SMEM);
    cudaFuncSetAttribute(gemm_h2_kernel,
                         cudaFuncAttributeMaxDynamicSharedMemorySize, H2_SMEM);

    const int nx4 = (Mrows * HID) / 4;
    const int nw4 = (HID * HID) / 4;
    dim3 gg(Ndim / 128, Mrows / 128);    // (16, 64)

    // split x to fp16 hi/lo
    cvt_hilo_h<<<(nx4 + 255) / 256, 256>>>(x, ahi, alo, nx4);

    // k = x @ Wk^T   (fp16 2-product)
    cvt_hi_h<<<(nw4 + 255) / 256, 256>>>(Wk, whi, nw4);
    gemm_h2_kernel<<<gg, 256, H2_SMEM>>>(ahi, alo, whi, gk);

    // v = x @ Wv^T   (fp16 2-product)
    cvt_hi_h<<<(nw4 + 255) / 256, 256>>>(Wv, whi, nw4);
    gemm_h2_kernel<<<gg, 256, H2_SMEM>>>(ahi, alo, whi, gv);

    // RoPE on k
    {
        const int total = Bsz * Ssz * HEADS * (HDIM / 2);
        rope_kernel<<<(total + 255) / 256, 256>>>(gk);
    }

    // TTT scan -> o  (tensor-core, e-split)
    {
        dim3 sg(Bsz * HEADS, 2);
        ttt_scan_mma<<<sg, 128, SCAN2_SMEM>>>(gk, gv, W0, go);
    }

    // LayerNorm fused with bf16 hi/lo split
    ln_cvt_kernel<<<Mrows, 256>>>(go, lng, lnb, ahi, alo);

    // out = x + o_ln @ Wo^T  (bf16 3-product, proven accurate)
    cvt_hilo_bf<<<(nw4 + 255) / 256, 256>>>(Wo, whi, wlo, nw4);
    gemm_mma_kernel<<<gg, 256, GEMM_SMEM>>>(ahi, alo, whi, wlo, out, x);
}

// round 7
// speedup vs baseline: 1.4808x; 1.4808x over previous
#include <cuda_runtime.h>
#include <cuda_bf16.h>
#include <cuda_fp16.h>
#include <cstdint>

// Problem constants
#define Bsz   4
#define Ssz   2048
#define HID   2048
#define HEADS 16
#define HDIM  128
#define MBsz  16
#define NCH   128
#define Mrows (Bsz*Ssz)    // 8192
#define Kdim  2048
#define Ndim  2048

// Scratch (device globals: allocation-free rule). 16-bit payload is fp16 for
// the k/v GEMMs, bf16 for the output GEMM.
__device__ float g_k[(size_t)Mrows * HID];
__device__ float g_v[(size_t)Mrows * HID];
__device__ float g_o[(size_t)Mrows * HID];
__device__ uint16_t g_ahi[(size_t)Mrows * HID];
__device__ uint16_t g_alo[(size_t)Mrows * HID];
__device__ uint16_t g_whi[(size_t)HID * HID];
__device__ uint16_t g_wlo[(size_t)HID * HID];

// ---------------------------------------------------------------------------
// helpers (baseline PTX only: cp.async / ldmatrix / mma.sync — sm_80 features)
// ---------------------------------------------------------------------------
__device__ __forceinline__ uint32_t smem_u32(const void* p) {
    uint32_t a;
    asm("{ .reg .u64 t; cvta.to.shared.u64 t, %1; cvt.u32.u64 %0, t; }"
        : "=r"(a) : "l"(p));
    return a;
}

#define SWZ(x) ((x) ^ (((x) >> 3) & 0x70))

__device__ __forceinline__ void cp16(uint32_t dst, const void* src) {
    asm volatile("cp.async.cg.shared.global [%0], [%1], 16;\n"
                 :: "r"(dst), "l"(src) : "memory");
}
__device__ __forceinline__ void cp_commit() {
    asm volatile("cp.async.commit_group;\n" ::: "memory");
}
template <int N> __device__ __forceinline__ void cp_wait() {
    asm volatile("cp.async.wait_group %0;\n" :: "n"(N) : "memory");
}

__device__ __forceinline__ void ldsm4(uint32_t r[4], uint32_t a) {
    asm volatile("ldmatrix.sync.aligned.m8n8.x4.shared.b16 {%0,%1,%2,%3}, [%4];"
                 : "=r"(r[0]), "=r"(r[1]), "=r"(r[2]), "=r"(r[3]) : "r"(a));
}

// bf16 mma
__device__ __forceinline__ void mma16816(float c[4], const uint32_t a[4],
                                         const uint32_t b0, const uint32_t b1) {
    asm volatile(
        "mma.sync.aligned.m16n8k16.row.col.f32.bf16.bf16.f32 "
        "{%0,%1,%2,%3}, {%4,%5,%6,%7}, {%8,%9}, {%0,%1,%2,%3};"
        : "+f"(c[0]), "+f"(c[1]), "+f"(c[2]), "+f"(c[3])
        : "r"(a[0]), "r"(a[1]), "r"(a[2]), "r"(a[3]), "r"(b0), "r"(b1));
}
// fp16 mma
__device__ __forceinline__ void mma16816h(float c[4], const uint32_t a[4],
                                          const uint32_t b0, const uint32_t b1) {
    asm volatile(
        "mma.sync.aligned.m16n8k16.row.col.f32.f16.f16.f32 "
        "{%0,%1,%2,%3}, {%4,%5,%6,%7}, {%8,%9}, {%0,%1,%2,%3};"
        : "+f"(c[0]), "+f"(c[1]), "+f"(c[2]), "+f"(c[3])
        : "r"(a[0]), "r"(a[1]), "r"(a[2]), "r"(a[3]), "r"(b0), "r"(b1));
}

__device__ __forceinline__ void bsplit(float x, uint16_t& h, uint16_t& l) {
    __nv_bfloat16 hb = __float2bfloat16_rn(x);
    __nv_bfloat16 lb = __float2bfloat16_rn(x - __bfloat162float(hb));
    h = *(uint16_t*)&hb;
    l = *(uint16_t*)&lb;
}
__device__ __forceinline__ void hsplit(float x, uint16_t& h, uint16_t& l) {
    __half hb = __float2half_rn(x);
    __half lb = __float2half_rn(x - __half2float(hb));
    h = *(uint16_t*)&hb;
    l = *(uint16_t*)&lb;
}

// ---------------------------------------------------------------------------
// converters
// ---------------------------------------------------------------------------
__global__ __launch_bounds__(256)
void cvt_hilo_bf(const float* __restrict__ s,
                 uint16_t* __restrict__ hi,
                 uint16_t* __restrict__ lo, int n4)
{
    int i = blockIdx.x * blockDim.x + threadIdx.x;
    if (i >= n4) return;
    float4 v = ((const float4*)s)[i];
    uint16_t h[4], l[4];
    bsplit(v.x, h[0], l[0]); bsplit(v.y, h[1], l[1]);
    bsplit(v.z, h[2], l[2]); bsplit(v.w, h[3], l[3]);
    *(uint64_t*)(hi + 4 * (size_t)i) = *(uint64_t*)h;
    *(uint64_t*)(lo + 4 * (size_t)i) = *(uint64_t*)l;
}

__global__ __launch_bounds__(256)
void cvt_hilo_h(const float* __restrict__ s,
                uint16_t* __restrict__ hi,
                uint16_t* __restrict__ lo, int n4)
{
    int i = blockIdx.x * blockDim.x + threadIdx.x;
    if (i >= n4) return;
    float4 v = ((const float4*)s)[i];
    uint16_t h[4], l[4];
    hsplit(v.x, h[0], l[0]); hsplit(v.y, h[1], l[1]);
    hsplit(v.z, h[2], l[2]); hsplit(v.w, h[3], l[3]);
    *(uint64_t*)(hi + 4 * (size_t)i) = *(uint64_t*)h;
    *(uint64_t*)(lo + 4 * (size_t)i) = *(uint64_t*)l;
}

__global__ __launch_bounds__(256)
void cvt_hi_h(const float* __restrict__ s,
              uint16_t* __restrict__ hi, int n4)
{
    int i = blockIdx.x * blockDim.x + threadIdx.x;
    if (i >= n4) return;
    float4 v = ((const float4*)s)[i];
    uint16_t h[4];
    __half a = __float2half_rn(v.x), b = __float2half_rn(v.y);
    __half c = __float2half_rn(v.z), d = __float2half_rn(v.w);
    h[0] = *(uint16_t*)&a; h[1] = *(uint16_t*)&b;
    h[2] = *(uint16_t*)&c; h[3] = *(uint16_t*)&d;
    *(uint64_t*)(hi + 4 * (size_t)i) = *(uint64_t*)h;
}

// ---------------------------------------------------------------------------
// fp16 2-product GEMM in the R4-proven schedule:
// C = (Ah+Al) @ Bh^T. CTA 128x128, BK=64, GS=3 cp.async pipeline, occupancy 1,
// 8 warps, warp tile 64(m) x 32(n).
// ---------------------------------------------------------------------------
#define TILE_B   16384
#define H2_STAGE (3 * TILE_B)              // Ahi, Alo, Bh = 48KB
#define H2_SMEM  (1024 + 3 * H2_STAGE)     // 148480
#define KTILES   (Kdim / 64)               // 32

__global__ __launch_bounds__(256, 1)
void gemm_h2_kernel(const uint16_t* __restrict__ Ahi,
                    const uint16_t* __restrict__ Alo,
                    const uint16_t* __restrict__ Bh,
                    float* __restrict__ C)
{
    extern __shared__ uint8_t smraw[];
    const uint32_t s0 = (smem_u32(smraw) + 1023u) & ~1023u;

    const int tid  = threadIdx.x;
    const int wid  = tid >> 5;
    const int lane = tid & 31;
    const int wm   = wid & 1;        // 2 m-warps, 64 rows
    const int wn   = wid >> 1;       // 4 n-warps, 32 cols
    const int m0 = blockIdx.y * 128;
    const int n0 = blockIdx.x * 128;

    uint32_t aBase[4];
    {
        int amat = lane >> 3, al = lane & 7;
        int rofs = ((amat & 1) << 3) + al;
        uint32_t akb = (uint32_t)((amat >> 1) << 4);
#pragma unroll
        for (int mf = 0; mf < 4; ++mf) {
            uint32_t r = (uint32_t)(wm * 64 + mf * 16 + rofs) * 128u;
            aBase[mf] = SWZ(r) ^ akb;
        }
    }
    uint32_t bBase[2];
    {
        int bmat = lane >> 3, bl = lane & 7;
        int rofs = ((bmat >> 1) << 3) + bl;
        uint32_t bkb = (uint32_t)((bmat & 1) << 4);
#pragma unroll
        for (int nfp = 0; nfp < 2; ++nfp) {
            uint32_t r = (uint32_t)(wn * 32 + nfp * 16 + rofs) * 128u;
            bBase[nfp] = SWZ(r) ^ bkb;
        }
    }

    auto load_stage = [&](int kt) {
        uint32_t sb = s0 + (uint32_t)(kt % 3) * H2_STAGE;
        const size_t kof = (size_t)kt * 64;
#pragma unroll
        for (int j = 0; j < 4; ++j) {
            int q = j * 256 + tid;
            int row = q >> 3, ch = q & 7;
            uint32_t so = SWZ((uint32_t)(row * 128 + ch * 16));
            size_t ga = (size_t)(m0 + row) * Kdim + kof + (size_t)ch * 8;
            size_t gb = (size_t)(n0 + row) * Kdim + kof + (size_t)ch * 8;
            cp16(sb + so,          Ahi + ga);
            cp16(sb + TILE_B + so, Alo + ga);
            if (j < 2) {
                // B tile: 2048 chunks of 16B over 256 threads in 2 j-steps
                int q2 = j * 256 + tid;
                int row2 = q2 >> 1, ch2 = (q2 & 1) * 4;   // 8B granule? no: 16B
                (void)row2; (void)ch2;
            }
            cp16(sb + 2 * TILE_B + so, Bh + gb);
        }
        cp_commit();
    };

    float acc[4][4][4];
#pragma unroll
    for (int i = 0; i < 4; ++i)
#pragma unroll
        for (int j = 0; j < 4; ++j)
#pragma unroll
            for (int r = 0; r < 4; ++r) acc[i][j][r] = 0.f;

    load_stage(0);
    load_stage(1);

    for (int it = 0; it < KTILES; ++it) {
        cp_wait<1>();
        __syncthreads();
        if (it + 2 < KTILES) load_stage(it + 2);

        const uint32_t sb = s0 + (uint32_t)(it % 3) * H2_STAGE;
#pragma unroll
        for (int kk = 0; kk < 4; ++kk) {
            const uint32_t kx = (uint32_t)(kk * 32);
            uint32_t ah[4][4], al[4][4];
#pragma unroll
            for (int mf = 0; mf < 4; ++mf) {
                ldsm4(ah[mf], sb + (aBase[mf] ^ kx));
                ldsm4(al[mf], sb + TILE_B + (aBase[mf] ^ kx));
            }
            uint32_t bh[4][2];
#pragma unroll
            for (int nfp = 0; nfp < 2; ++nfp) {
                uint32_t t[4];
                ldsm4(t, sb + 2 * TILE_B + (bBase[nfp] ^ kx));
                bh[2 * nfp][0] = t[0]; bh[2 * nfp][1] = t[1];
                bh[2 * nfp + 1][0] = t[2]; bh[2 * nfp + 1][1] = t[3];
            }
#pragma unroll
            for (int mf = 0; mf < 4; ++mf)
#pragma unroll
                for (int nf = 0; nf < 4; ++nf) {
                    mma16816h(acc[mf][nf], ah[mf], bh[nf][0], bh[nf][1]);
                    mma16816h(acc[mf][nf], al[mf], bh[nf][0], bh[nf][1]);
                }
        }
    }

    const int cm = (lane >> 2);
    const int cn = (lane & 3) * 2;
#pragma unroll
    for (int mf = 0; mf < 4; ++mf) {
        const int row = m0 + wm * 64 + mf * 16 + cm;
#pragma unroll
        for (int nf = 0; nf < 4; ++nf) {
            const int col = n0 + wn * 32 + nf * 8 + cn;
            *(float2*)(C + (size_t)row * Ndim + col) =
                make_float2(acc[mf][nf][0], acc[mf][nf][1]);
            *(float2*)(C + (size_t)(row + 8) * Ndim + col) =
                make_float2(acc[mf][nf][2], acc[mf][nf][3]);
        }
    }
}

// ---------------------------------------------------------------------------
// bf16 3-product GEMM (R4-proven): C = A @ B^T + Res
// ---------------------------------------------------------------------------
#define GS      3
#define STAGE_B (4 * TILE_B)
#define GEMM_SMEM (1024 + GS * STAGE_B)

__global__ __launch_bounds__(256, 1)
void gemm_mma_kernel(const uint16_t* __restrict__ Ahi,
                     const uint16_t* __restrict__ Alo,
                     const uint16_t* __restrict__ Bhi,
                     const uint16_t* __restrict__ Blo,
                     float* __restrict__ C,
                     const float* __restrict__ Res)
{
    extern __shared__ uint8_t smraw[];
    const uint32_t s0 = (smem_u32(smraw) + 1023u) & ~1023u;

    const int tid  = threadIdx.x;
    const int wid  = tid >> 5;
    const int lane = tid & 31;
    const int wm   = wid & 1;
    const int wn   = wid >> 1;
    const int m0 = blockIdx.y * 128;
    const int n0 = blockIdx.x * 128;

    uint32_t aBase[4];
    {
        int amat = lane >> 3, al = lane & 7;
        int rofs = ((amat & 1) << 3) + al;
        uint32_t akb = (uint32_t)((amat >> 1) << 4);
#pragma unroll
        for (int mf = 0; mf < 4; ++mf) {
            uint32_t r = (uint32_t)(wm * 64 + mf * 16 + rofs) * 128u;
            aBase[mf] = SWZ(r) ^ akb;
        }
    }
    uint32_t bBase[2];
    {
        int bmat = lane >> 3, bl = lane & 7;
        int rofs = ((bmat >> 1) << 3) + bl;
        uint32_t bkb = (uint32_t)((bmat & 1) << 4);
#pragma unroll
        for (int nfp = 0; nfp < 2; ++nfp) {
            uint32_t r = (uint32_t)(wn * 32 + nfp * 16 + rofs) * 128u;
            bBase[nfp] = SWZ(r) ^ bkb;
        }
    }

    auto load_stage = [&](int kt) {
        uint32_t sb = s0 + (uint32_t)(kt % GS) * STAGE_B;
        const size_t kof = (size_t)kt * 64;
#pragma unroll
        for (int j = 0; j < 4; ++j) {
            int q = j * 256 + tid;
            int row = q >> 3, ch = q & 7;
            uint32_t so = SWZ((uint32_t)(row * 128 + ch * 16));
            size_t ga = (size_t)(m0 + row) * Kdim + kof + (size_t)ch * 8;
            size_t gb = (size_t)(n0 + row) * Kdim + kof + (size_t)ch * 8;
            cp16(sb + so,              Ahi + ga);
            cp16(sb + TILE_B + so,     Alo + ga);
            cp16(sb + 2 * TILE_B + so, Bhi + gb);
            cp16(sb + 3 * TILE_B + so, Blo + gb);
        }
        cp_commit();
    };

    float acc[4][4][4];
#pragma unroll
    for (int i = 0; i < 4; ++i)
#pragma unroll
        for (int j = 0; j < 4; ++j)
#pragma unroll
            for (int r = 0; r < 4; ++r) acc[i][j][r] = 0.f;

    load_stage(0);
    load_stage(1);

    for (int it = 0; it < KTILES; ++it) {
        cp_wait<1>();
        __syncthreads();
        if (it + 2 < KTILES) load_stage(it + 2);

        const uint32_t sb = s0 + (uint32_t)(it % GS) * STAGE_B;
#pragma unroll
        for (int kk = 0; kk < 4; ++kk) {
            const uint32_t kx = (uint32_t)(kk * 32);
            uint32_t ah[4][4], al[4][4];
#pragma unroll
            for (int mf = 0; mf < 4; ++mf) {
                ldsm4(ah[mf], sb + (aBase[mf] ^ kx));
                ldsm4(al[mf], sb + TILE_B + (aBase[mf] ^ kx));
            }
            uint32_t bh[4][2], bl[4][2];
#pragma unroll
            for (int nfp = 0; nfp < 2; ++nfp) {
                uint32_t t[4];
                ldsm4(t, sb + 2 * TILE_B + (bBase[nfp] ^ kx));
                bh[2 * nfp][0] = t[0]; bh[2 * nfp][1] = t[1];
                bh[2 * nfp + 1][0] = t[2]; bh[2 * nfp + 1][1] = t[3];
                ldsm4(t, sb + 3 * TILE_B + (bBase[nfp] ^ kx));
                bl[2 * nfp][0] = t[0]; bl[2 * nfp][1] = t[1];
                bl[2 * nfp + 1][0] = t[2]; bl[2 * nfp + 1][1] = t[3];
            }
#pragma unroll
            for (int mf = 0; mf < 4; ++mf)
#pragma unroll
                for (int nf = 0; nf < 4; ++nf) {
                    mma16816(acc[mf][nf], ah[mf], bh[nf][0], bh[nf][1]);
                    mma16816(acc[mf][nf], ah[mf], bl[nf][0], bl[nf][1]);
                    mma16816(acc[mf][nf], al[mf], bh[nf][0], bh[nf][1]);
                }
        }
    }

    const int cm = (lane >> 2);
    const int cn = (lane & 3) * 2;
#pragma unroll
    for (int mf = 0; mf < 4; ++mf) {
        const int row = m0 + wm * 64 + mf * 16 + cm;
#pragma unroll
        for (int nf = 0; nf < 4; ++nf) {
            const int col = n0 + wn * 32 + nf * 8 + cn;
            float2 v0 = make_float2(acc[mf][nf][0], acc[mf][nf][1]);
            float2 v1 = make_float2(acc[mf][nf][2], acc[mf][nf][3]);
            if (Res) {
                float2 r0 = *(const float2*)(Res + (size_t)row * Ndim + col);
                float2 r1 = *(const float2*)(Res + (size_t)(row + 8) * Ndim + col);
                v0.x += r0.x; v0.y += r0.y;
                v1.x += r1.x; v1.y += r1.y;
            }
            *(float2*)(C + (size_t)row * Ndim + col)       = v0;
            *(float2*)(C + (size_t)(row + 8) * Ndim + col) = v1;
        }
    }
}

// ---------------------------------------------------------------------------
// RoPE on g_k
// ---------------------------------------------------------------------------
__global__ void rope_kernel(float* __restrict__ k)
{
    const int gid = blockIdx.x * blockDim.x + threadIdx.x;
    const int total = Bsz * Ssz * HEADS * (HDIM / 2);
    if (gid >= total) return;
    const int i   = gid & 63;
    const int h   = (gid >> 6) & (HEADS - 1);
    const int row = gid >> 10;
    const int s   = row & (Ssz - 1);

    const float c = 0.20762050593046013f;   // log2(10000)/64
    const float inv = exp2f(-c * (float)i);
    const float ang = (float)s * inv;
    float sn = sinf(ang), cs = cosf(ang);

    float* p = k + (size_t)row * HID + h * HDIM;
    const float k1 = p[i];
    const float k2 = p[i + 64];
    p[i]      = k1 * cs - k2 * sn;
    p[i + 64] = k2 * cs + k1 * sn;
}

// ---------------------------------------------------------------------------
// Tensor-core TTT scan (R4-validated). Grid (64 bh, 2 e-halves), 128 threads.
// ---------------------------------------------------------------------------
#define OFF_RAWK   0
#define OFF_RAWV   16384
#define OFF_KHI    24576
#define OFF_KLO    32768
#define OFF_KTHI   40960
#define OFF_KTLO   47104
#define OFF_ETHI   53248
#define OFF_ETLO   56320
#define OFF_WTHI   59392
#define OFF_WTLO   75776
#define SCAN2_SMEM 92160

__global__ __launch_bounds__(128, 1)
void ttt_scan_mma(const float* __restrict__ gk,
                  const float* __restrict__ gv,
                  const float* __restrict__ W0,
                  float*       __restrict__ go)
{
    extern __shared__ __align__(16) char sm[];
    const uint32_t sb = smem_u32(sm);

    const int tid  = threadIdx.x;
    const int wid  = tid >> 5;
    const int lane = tid & 31;
    const int bh = blockIdx.x;
    const int eh = blockIdx.y;
    const int b  = bh >> 4, h = bh & 15;
    const int e0 = eh * 64;

    const int mat = lane >> 3, ml = lane & 7;
    const int arow = ((mat & 1) << 3) + ml;
    const uint32_t akb = (uint32_t)((mat >> 1) << 4);
    const int brow = ((mat >> 1) << 3) + ml;
    const uint32_t bkb = (uint32_t)((mat & 1) << 4);

    const uint32_t aBaseK = SWZ((uint32_t)(arow * 128)) ^ akb;
    const uint32_t bBaseW = SWZ((uint32_t)((16 * wid + brow) * 128)) ^ bkb;

    const int cr = lane >> 2;
    const int cc = (lane & 3) * 2;

    float W[2][8][4];
    {
        const float* W0p = W0 + (size_t)bh * (HDIM * HDIM);
#pragma unroll
        for (int t2 = 0; t2 < 2; ++t2) {
            int dt = 32 * wid + 16 * t2;
#pragma unroll
            for (int j = 0; j < 8; ++j) {
                int e = e0 + 8 * j + cc;
                W[t2][j][0] = W0p[(size_t)(dt + cr) * 128 + e];
                W[t2][j][1] = W0p[(size_t)(dt + cr) * 128 + e + 1];
                W[t2][j][2] = W0p[(size_t)(dt + cr + 8) * 128 + e];
                W[t2][j][3] = W0p[(size_t)(dt + cr + 8) * 128 + e + 1];
            }
        }
    }

    const float* kbase = gk + (size_t)b * Ssz * HID + h * HDIM;
    const float* vbase = gv + (size_t)b * Ssz * HID + h * HDIM + e0;
    float*       obase = go + (size_t)b * Ssz * HID + h * HDIM + e0;

    auto dumpW = [&]() {
#pragma unroll
        for (int t2 = 0; t2 < 2; ++t2) {
            int dt = 32 * wid + 16 * t2;
#pragma unroll
            for (int j = 0; j < 8; ++j) {
                int e = 8 * j + cc;
#pragma unroll
                for (int q = 0; q < 4; ++q) {
                    int d  = dt + cr + ((q >> 1) << 3);
                    int ee = e + (q & 1);
                    uint16_t hh, ll;
                    bsplit(W[t2][j][q], hh, ll);
                    uint32_t half = (uint32_t)(d >> 6);
                    uint32_t a = SWZ((uint32_t)(ee * 128 + (d & 63) * 2));
                    *(uint16_t*)(sm + OFF_WTHI + half * 8192 + a) = hh;
                    *(uint16_t*)(sm + OFF_WTLO + half * 8192 + a) = ll;
                }
            }
        }
    };

    auto loadKV = [&](int c) {
        int buf = c & 1;
        const float* ks = kbase + (size_t)(c * 16) * HID;
        const float* vs = vbase + (size_t)(c * 16) * HID;
#pragma unroll
        for (int j = 0; j < 4; ++j) {
            int q = j * 128 + tid;
            int row = q >> 5, ch = q & 31;
            cp16(sb + OFF_RAWK + buf * 8192 + (uint32_t)(row * 512 + ch * 16),
                 ks + (size_t)row * HID + ch * 4);
        }
#pragma unroll
        for (int j = 0; j < 2; ++j) {
            int q = j * 128 + tid;
            int row = q >> 4, ch = q & 15;
            cp16(sb + OFF_RAWV + buf * 4096 + (uint32_t)(row * 256 + ch * 16),
                 vs + (size_t)row * HID + ch * 4);
        }
        cp_commit();
    };

    auto convK = [&](int c) {
        int buf = c & 1;
        const float* rk = (const float*)(sm + OFF_RAWK + buf * 8192);
        int m = tid >> 3, c16 = (tid & 7) * 16;
        __align__(16) uint16_t hb[16], lb[16];
#pragma unroll
        for (int i = 0; i < 16; ++i) bsplit(rk[m * 128 + c16 + i], hb[i], lb[i]);
        uint32_t half = (uint32_t)(c16 >= 64);
        uint32_t ccl  = (uint32_t)((c16 & 63) * 2);
        uint32_t a0 = SWZ((uint32_t)(m * 128) + ccl);
        uint32_t a1 = SWZ((uint32_t)(m * 128) + ccl + 16);
        uint32_t kb = (uint32_t)(OFF_KHI + buf * 4096 + half * 2048);
        *(uint4*)(sm + kb + a0) = *(uint4*)&hb[0];
        *(uint4*)(sm + kb + a1) = *(uint4*)&hb[8];
        kb = (uint32_t)(OFF_KLO + buf * 4096 + half * 2048);
        *(uint4*)(sm + kb + a0) = *(uint4*)&lb[0];
        *(uint4*)(sm + kb + a1) = *(uint4*)&lb[8];
    };

    auto convKT = [&](int c) {
        int buf = c & 1;
        const float* rk = (const float*)(sm + OFF_RAWK + buf * 8192);
        int d = tid;
        __align__(16) uint16_t th[16], tl[16];
#pragma unroll
        for (int m = 0; m < 16; ++m) bsplit(rk[m * 128 + d], th[m], tl[m]);
        *(uint4*)(sm + OFF_KTHI + d * 48)      = *(uint4*)&th[0];
        *(uint4*)(sm + OFF_KTHI + d * 48 + 16) = *(uint4*)&th[8];
        *(uint4*)(sm + OFF_KTLO + d * 48)      = *(uint4*)&tl[0];
        *(uint4*)(sm + OFF_KTLO + d * 48 + 16) = *(uint4*)&tl[8];
    };

    float P[2][4];

    auto predOnly = [&](int buf, float acc[2][4]) {
#pragma unroll
        for (int f = 0; f < 2; ++f)
#pragma unroll
            for (int q = 0; q < 4; ++q) acc[f][q] = 0.f;
#pragma unroll
        for (int kk = 0; kk < 8; ++kk) {
            uint32_t half = (uint32_t)(kk >> 2);
            uint32_t kx   = (uint32_t)((kk & 3) * 32);
            uint32_t ah[4], al[4], t[4], bh[2][2], bl[2][2];
            ldsm4(ah, sb + OFF_KHI + buf * 4096 + half * 2048 + (aBaseK ^ kx));
            ldsm4(al, sb + OFF_KLO + buf * 4096 + half * 2048 + (aBaseK ^ kx));
            ldsm4(t, sb + OFF_WTHI + half * 8192 + (bBaseW ^ kx));
            bh[0][0] = t[0]; bh[0][1] = t[1]; bh[1][0] = t[2]; bh[1][1] = t[3];
            ldsm4(t, sb + OFF_WTLO + half * 8192 + (bBaseW ^ kx));
            bl[0][0] = t[0]; bl[0][1] = t[1]; bl[1][0] = t[2]; bl[1][1] = t[3];
#pragma unroll
            for (int f = 0; f < 2; ++f) {
                mma16816(acc[f], ah, bh[f][0], bh[f][1]);
                mma16816(acc[f], ah, bl[f][0], bl[f][1]);
                mma16816(acc[f], al, bh[f][0], bh[f][1]);
            }
        }
    };

    dumpW();
    loadKV(0);
    cp_wait<0>();
    __syncthreads();
    convK(0);
    __syncthreads();
    predOnly(0, P);

    for (int c = 0; c < NCH; ++c) {
        const int buf = c & 1;
        const bool hasNext = (c + 1 < NCH);
        if (hasNext) loadKV(c + 1);

        convKT(c);

        {
            const float* rv = (const float*)(sm + OFF_RAWV + buf * 4096);
#pragma unroll
            for (int f = 0; f < 2; ++f)
#pragma unroll
                for (int q = 0; q < 4; ++q) {
                    int e = 16 * wid + 8 * f + cc + (q & 1);
                    int m = cr + ((q >> 1) << 3);
                    float ep = (rv[m * 64 + e] - P[f][q]) * 0.0009765625f;
                    uint16_t hh, ll;
                    bsplit(ep, hh, ll);
                    *(uint16_t*)(sm + OFF_ETHI + e * 48 + m * 2) = hh;
                    *(uint16_t*)(sm + OFF_ETLO + e * 48 + m * 2) = ll;
                }
        }
        __syncthreads();

        {
            uint32_t aH[2][4], aL[2][4];
#pragma unroll
            for (int t2 = 0; t2 < 2; ++t2) {
                uint32_t ra = (uint32_t)((32 * wid + 16 * t2 + arow) * 48) + akb;
                ldsm4(aH[t2], sb + OFF_KTHI + ra);
                ldsm4(aL[t2], sb + OFF_KTLO + ra);
            }
#pragma unroll
            for (int p = 0; p < 4; ++p) {
                uint32_t rb = (uint32_t)((16 * p + brow) * 48) + bkb;
                uint32_t th[4], tl[4];
                ldsm4(th, sb + OFF_ETHI + rb);
                ldsm4(tl, sb + OFF_ETLO + rb);
#pragma unroll
                for (int t2 = 0; t2 < 2; ++t2) {
                    mma16816(W[t2][2 * p],     aH[t2], th[0], th[1]);
                    mma16816(W[t2][2 * p],     aH[t2], tl[0], tl[1]);
                    mma16816(W[t2][2 * p],     aL[t2], th[0], th[1]);
                    mma16816(W[t2][2 * p + 1], aH[t2], th[2], th[3]);
                    mma16816(W[t2][2 * p + 1], aH[t2], tl[2], tl[3]);
                    mma16816(W[t2][2 * p + 1], aL[t2], th[2], th[3]);
                }
            }
        }

        dumpW();

        if (hasNext) cp_wait<0>();
        __syncthreads();
        if (hasNext) convK(c + 1);
        __syncthreads();

        {
            float O[2][4];
#pragma unroll
            for (int f = 0; f < 2; ++f)
#pragma unroll
                for (int q = 0; q < 4; ++q) { O[f][q] = 0.f; P[f][q] = 0.f; }
            const int bufn = (c + 1) & 1;
#pragma unroll
            for (int kk = 0; kk < 8; ++kk) {
                uint32_t half = (uint32_t)(kk >> 2);
                uint32_t kx   = (uint32_t)((kk & 3) * 32);
                uint32_t t[4], bh[2][2], bl[2][2];
                ldsm4(t, sb + OFF_WTHI + half * 8192 + (bBaseW ^ kx));
                bh[0][0] = t[0]; bh[0][1] = t[1]; bh[1][0] = t[2]; bh[1][1] = t[3];
                ldsm4(t, sb + OFF_WTLO + half * 8192 + (bBaseW ^ kx));
                bl[0][0] = t[0]; bl[0][1] = t[1]; bl[1][0] = t[2]; bl[1][1] = t[3];

                uint32_t ah[4], al[4];
                ldsm4(ah, sb + OFF_KHI + buf * 4096 + half * 2048 + (aBaseK ^ kx));
                ldsm4(al, sb + OFF_KLO + buf * 4096 + half * 2048 + (aBaseK ^ kx));
#pragma unroll
                for (int f = 0; f < 2; ++f) {
                    mma16816(O[f], ah, bh[f][0], bh[f][1]);
                    mma16816(O[f], ah, bl[f][0], bl[f][1]);
                    mma16816(O[f], al, bh[f][0], bh[f][1]);
                }
                if (hasNext) {
                    uint32_t nh[4], nl[4];
                    ldsm4(nh, sb + OFF_KHI + bufn * 4096 + half * 2048 + (aBaseK ^ kx));
                    ldsm4(nl, sb + OFF_KLO + bufn * 4096 + half * 2048 + (aBaseK ^ kx));
#pragma unroll
                    for (int f = 0; f < 2; ++f) {
                        mma16816(P[f], nh, bh[f][0], bh[f][1]);
                        mma16816(P[f], nh, bl[f][0], bl[f][1]);
                        mma16816(P[f], nl, bh[f][0], bh[f][1]);
                    }
                }
            }
#pragma unroll
            for (int f = 0; f < 2; ++f) {
                int e = 16 * wid + 8 * f + cc;
                size_t r0 = (size_t)(c * 16 + cr) * HID + e;
                size_t r1 = (size_t)(c * 16 + cr + 8) * HID + e;
                *(float2*)(obase + r0) = make_float2(O[f][0], O[f][1]);
                *(float2*)(obase + r1) = make_float2(O[f][2], O[f][3]);
            }
        }
    }
}

// ---------------------------------------------------------------------------
// LayerNorm fused with bf16 hi/lo split (feeds the bf16 output GEMM)
// ---------------------------------------------------------------------------
__global__ __launch_bounds__(256)
void ln_cvt_kernel(const float* __restrict__ o,
                   const float* __restrict__ g,
                   const float* __restrict__ beta,
                   uint16_t* __restrict__ hi,
                   uint16_t* __restrict__ lo)
{
    __shared__ float s1[8], s2[8];
    const int row = blockIdx.x;
    const int t   = threadIdx.x;
    const float* p = o + (size_t)row * HID;

    float4 v0 = *(const float4*)(p + t * 8);
    float4 v1 = *(const float4*)(p + t * 8 + 4);
    float s  = v0.x + v0.y + v0.z + v0.w + v1.x + v1.y + v1.z + v1.w;
    float ss = v0.x*v0.x + v0.y*v0.y + v0.z*v0.z + v0.w*v0.w
             + v1.x*v1.x + v1.y*v1.y + v1.z*v1.z + v1.w*v1.w;
#pragma unroll
    for (int off = 16; off > 0; off >>= 1) {
        s  += __shfl_xor_sync(0xffffffffu, s,  off);
        ss += __shfl_xor_sync(0xffffffffu, ss, off);
    }
    const int w = t >> 5;
    if ((t & 31) == 0) { s1[w] = s; s2[w] = ss; }
    __syncthreads();
    float tot = 0.f, tot2 = 0.f;
#pragma unroll
    for (int i = 0; i < 8; ++i) { tot += s1[i]; tot2 += s2[i]; }
    const float mu  = tot * (1.0f / HID);
    const float var = tot2 * (1.0f / HID) - mu * mu;
    const float inv = rsqrtf(var + 1e-5f);

    float4 g0 = *(const float4*)(g + t * 8);
    float4 g1 = *(const float4*)(g + t * 8 + 4);
    float4 b0 = *(const float4*)(beta + t * 8);
    float4 b1 = *(const float4*)(beta + t * 8 + 4);
    float y[8];
    y[0] = (v0.x - mu) * inv * g0.x + b0.x;
    y[1] = (v0.y - mu) * inv * g0.y + b0.y;
    y[2] = (v0.z - mu) * inv * g0.z + b0.z;
    y[3] = (v0.w - mu) * inv * g0.w + b0.w;
    y[4] = (v1.x - mu) * inv * g1.x + b1.x;
    y[5] = (v1.y - mu) * inv * g1.y + b1.y;
    y[6] = (v1.z - mu) * inv * g1.z + b1.z;
    y[7] = (v1.w - mu) * inv * g1.w + b1.w;

    __align__(16) uint16_t hb[8], lb[8];
#pragma unroll
    for (int i = 0; i < 8; ++i) bsplit(y[i], hb[i], lb[i]);
    *(uint4*)(hi + (size_t)row * HID + t * 8) = *(uint4*)hb;
    *(uint4*)(lo + (size_t)row * HID + t * 8) = *(uint4*)lb;
}

// ---------------------------------------------------------------------------
// launch
// ---------------------------------------------------------------------------
extern "C" void kernel_launch(void* const* d_in, const int* in_sizes, int n_in,
                              void* d_out, int out_size)
{
    const float* x   = (const float*)d_in[0];
    const float* Wk  = (const float*)d_in[1];
    const float* Wv  = (const float*)d_in[2];
    const float* Wo  = (const float*)d_in[3];
    const float* lng = (const float*)d_in[4];
    const float* lnb = (const float*)d_in[5];
    const float* W0  = (const float*)d_in[6];
    float* out = (float*)d_out;

    float *gk, *gv, *go;
    uint16_t *ahi, *alo, *whi, *wlo;
    cudaGetSymbolAddress((void**)&gk, g_k);
    cudaGetSymbolAddress((void**)&gv, g_v);
    cudaGetSymbolAddress((void**)&go, g_o);
    cudaGetSymbolAddress((void**)&ahi, g_ahi);
    cudaGetSymbolAddress((void**)&alo, g_alo);
    cudaGetSymbolAddress((void**)&whi, g_whi);
    cudaGetSymbolAddress((void**)&wlo, g_wlo);

    cudaFuncSetAttribute(ttt_scan_mma,
                         cudaFuncAttributeMaxDynamicSharedMemorySize, SCAN2_SMEM);
    cudaFuncSetAttribute(gemm_mma_kernel,
                         cudaFuncAttributeMaxDynamicSharedMemorySize, GEMM_SMEM);
    cudaFuncSetAttribute(gemm_h2_kernel,
                         cudaFuncAttributeMaxDynamicSharedMemorySize, H2_SMEM);

    const int nx4 = (Mrows * HID) / 4;
    const int nw4 = (HID * HID) / 4;
    dim3 gg(Ndim / 128, Mrows / 128);    // (16, 64)

    // split x to fp16 hi/lo
    cvt_hilo_h<<<(nx4 + 255) / 256, 256>>>(x, ahi, alo, nx4);

    // k = x @ Wk^T   (fp16 2-product, R4 schedule)
    cvt_hi_h<<<(nw4 + 255) / 256, 256>>>(Wk, whi, nw4);
    gemm_h2_kernel<<<gg, 256, H2_SMEM>>>(ahi, alo, whi, gk);

    // v = x @ Wv^T   (fp16 2-product, R4 schedule)
    cvt_hi_h<<<(nw4 + 255) / 256, 256>>>(Wv, whi, nw4);
    gemm_h2_kernel<<<gg, 256, H2_SMEM>>>(ahi, alo, whi, gv);

    // RoPE on k
    {
        const int total = Bsz * Ssz * HEADS * (HDIM / 2);
        rope_kernel<<<(total + 255) / 256, 256>>>(gk);
    }

    // TTT scan -> o  (tensor-core, e-split)
    {
        dim3 sg(Bsz * HEADS, 2);
        ttt_scan_mma<<<sg, 128, SCAN2_SMEM>>>(gk, gv, W0, go);
    }

    // LayerNorm fused with bf16 hi/lo split
    ln_cvt_kernel<<<Mrows, 256>>>(go, lng, lnb, ahi, alo);

    // out = x + o_ln @ Wo^T  (bf16 3-product, proven accurate)
    cvt_hilo_bf<<<(nw4 + 255) / 256, 256>>>(Wo, whi, wlo, nw4);
    gemm_mma_kernel<<<gg, 256, GEMM_SMEM>>>(ahi, alo, whi, wlo, out, x);
}

// round 8
// speedup vs baseline: 1.6252x; 1.0975x over previous
#include <cuda_runtime.h>
#include <cuda_bf16.h>
#include <cuda_fp16.h>
#include <cstdint>

// Problem constants
#define Bsz   4
#define Ssz   2048
#define HID   2048
#define HEADS 16
#define HDIM  128
#define MBsz  16
#define NCH   128
#define Mrows (Bsz*Ssz)    // 8192
#define Kdim  2048
#define Ndim  2048

// Scratch (device globals: allocation-free rule). 16-bit payload is fp16.
__device__ float g_k[(size_t)Mrows * HID];
__device__ float g_v[(size_t)Mrows * HID];
__device__ float g_o[(size_t)Mrows * HID];
__device__ uint16_t g_ahi[(size_t)Mrows * HID];
__device__ uint16_t g_alo[(size_t)Mrows * HID];
__device__ uint16_t g_whi[(size_t)HID * HID];

// ---------------------------------------------------------------------------
// helpers (baseline PTX only: cp.async / ldmatrix / mma.sync — sm_80 features)
// ---------------------------------------------------------------------------
__device__ __forceinline__ uint32_t smem_u32(const void* p) {
    uint32_t a;
    asm("{ .reg .u64 t; cvta.to.shared.u64 t, %1; cvt.u32.u64 %0, t; }"
        : "=r"(a) : "l"(p));
    return a;
}

#define SWZ(x) ((x) ^ (((x) >> 3) & 0x70))

__device__ __forceinline__ void cp16(uint32_t dst, const void* src) {
    asm volatile("cp.async.cg.shared.global [%0], [%1], 16;\n"
                 :: "r"(dst), "l"(src) : "memory");
}
__device__ __forceinline__ void cp_commit() {
    asm volatile("cp.async.commit_group;\n" ::: "memory");
}
template <int N> __device__ __forceinline__ void cp_wait() {
    asm volatile("cp.async.wait_group %0;\n" :: "n"(N) : "memory");
}

__device__ __forceinline__ void ldsm4(uint32_t r[4], uint32_t a) {
    asm volatile("ldmatrix.sync.aligned.m8n8.x4.shared.b16 {%0,%1,%2,%3}, [%4];"
                 : "=r"(r[0]), "=r"(r[1]), "=r"(r[2]), "=r"(r[3]) : "r"(a));
}

// bf16 mma (used by the scan, where W stays fp32 in accumulators)
__device__ __forceinline__ void mma16816(float c[4], const uint32_t a[4],
                                         const uint32_t b0, const uint32_t b1) {
    asm volatile(
        "mma.sync.aligned.m16n8k16.row.col.f32.bf16.bf16.f32 "
        "{%0,%1,%2,%3}, {%4,%5,%6,%7}, {%8,%9}, {%0,%1,%2,%3};"
        : "+f"(c[0]), "+f"(c[1]), "+f"(c[2]), "+f"(c[3])
        : "r"(a[0]), "r"(a[1]), "r"(a[2]), "r"(a[3]), "r"(b0), "r"(b1));
}
// fp16 mma
__device__ __forceinline__ void mma16816h(float c[4], const uint32_t a[4],
                                          const uint32_t b0, const uint32_t b1) {
    asm volatile(
        "mma.sync.aligned.m16n8k16.row.col.f32.f16.f16.f32 "
        "{%0,%1,%2,%3}, {%4,%5,%6,%7}, {%8,%9}, {%0,%1,%2,%3};"
        : "+f"(c[0]), "+f"(c[1]), "+f"(c[2]), "+f"(c[3])
        : "r"(a[0]), "r"(a[1]), "r"(a[2]), "r"(a[3]), "r"(b0), "r"(b1));
}

__device__ __forceinline__ void bsplit(float x, uint16_t& h, uint16_t& l) {
    __nv_bfloat16 hb = __float2bfloat16_rn(x);
    __nv_bfloat16 lb = __float2bfloat16_rn(x - __bfloat162float(hb));
    h = *(uint16_t*)&hb;
    l = *(uint16_t*)&lb;
}
__device__ __forceinline__ void hsplit(float x, uint16_t& h, uint16_t& l) {
    __half hb = __float2half_rn(x);
    __half lb = __float2half_rn(x - __half2float(hb));
    h = *(uint16_t*)&hb;
    l = *(uint16_t*)&lb;
}

// ---------------------------------------------------------------------------
// converters
// ---------------------------------------------------------------------------
__global__ __launch_bounds__(256)
void cvt_hilo_h(const float* __restrict__ s,
                uint16_t* __restrict__ hi,
                uint16_t* __restrict__ lo, int n4)
{
    int i = blockIdx.x * blockDim.x + threadIdx.x;
    if (i >= n4) return;
    float4 v = ((const float4*)s)[i];
    uint16_t h[4], l[4];
    hsplit(v.x, h[0], l[0]); hsplit(v.y, h[1], l[1]);
    hsplit(v.z, h[2], l[2]); hsplit(v.w, h[3], l[3]);
    *(uint64_t*)(hi + 4 * (size_t)i) = *(uint64_t*)h;
    *(uint64_t*)(lo + 4 * (size_t)i) = *(uint64_t*)l;
}

__global__ __launch_bounds__(256)
void cvt_hi_h(const float* __restrict__ s,
              uint16_t* __restrict__ hi, int n4)
{
    int i = blockIdx.x * blockDim.x + threadIdx.x;
    if (i >= n4) return;
    float4 v = ((const float4*)s)[i];
    uint16_t h[4];
    __half a = __float2half_rn(v.x), b = __float2half_rn(v.y);
    __half c = __float2half_rn(v.z), d = __float2half_rn(v.w);
    h[0] = *(uint16_t*)&a; h[1] = *(uint16_t*)&b;
    h[2] = *(uint16_t*)&c; h[3] = *(uint16_t*)&d;
    *(uint64_t*)(hi + 4 * (size_t)i) = *(uint64_t*)h;
}

// ---------------------------------------------------------------------------
// fp16 2-product GEMM (R7-proven): C = (Ah+Al) @ Bh^T (+ optional residual)
// CTA 128x128, BK=64, GS=3 cp.async pipeline, occupancy 1, 8 warps,
// warp tile 64(m) x 32(n).
// ---------------------------------------------------------------------------
#define TILE_B   16384
#define H2_STAGE (3 * TILE_B)              // Ahi, Alo, Bh = 48KB
#define H2_SMEM  (1024 + 3 * H2_STAGE)     // 148480
#define KTILES   (Kdim / 64)               // 32

__global__ __launch_bounds__(256, 1)
void gemm_h2_kernel(const uint16_t* __restrict__ Ahi,
                    const uint16_t* __restrict__ Alo,
                    const uint16_t* __restrict__ Bh,
                    float* __restrict__ C,
                    const float* __restrict__ Res)
{
    extern __shared__ uint8_t smraw[];
    const uint32_t s0 = (smem_u32(smraw) + 1023u) & ~1023u;

    const int tid  = threadIdx.x;
    const int wid  = tid >> 5;
    const int lane = tid & 31;
    const int wm   = wid & 1;        // 2 m-warps, 64 rows
    const int wn   = wid >> 1;       // 4 n-warps, 32 cols
    const int m0 = blockIdx.y * 128;
    const int n0 = blockIdx.x * 128;

    uint32_t aBase[4];
    {
        int amat = lane >> 3, al = lane & 7;
        int rofs = ((amat & 1) << 3) + al;
        uint32_t akb = (uint32_t)((amat >> 1) << 4);
#pragma unroll
        for (int mf = 0; mf < 4; ++mf) {
            uint32_t r = (uint32_t)(wm * 64 + mf * 16 + rofs) * 128u;
            aBase[mf] = SWZ(r) ^ akb;
        }
    }
    uint32_t bBase[2];
    {
        int bmat = lane >> 3, bl = lane & 7;
        int rofs = ((bmat >> 1) << 3) + bl;
        uint32_t bkb = (uint32_t)((bmat & 1) << 4);
#pragma unroll
        for (int nfp = 0; nfp < 2; ++nfp) {
            uint32_t r = (uint32_t)(wn * 32 + nfp * 16 + rofs) * 128u;
            bBase[nfp] = SWZ(r) ^ bkb;
        }
    }

    auto load_stage = [&](int kt) {
        uint32_t sb = s0 + (uint32_t)(kt % 3) * H2_STAGE;
        const size_t kof = (size_t)kt * 64;
#pragma unroll
        for (int j = 0; j < 4; ++j) {
            int q = j * 256 + tid;
            int row = q >> 3, ch = q & 7;
            uint32_t so = SWZ((uint32_t)(row * 128 + ch * 16));
            size_t ga = (size_t)(m0 + row) * Kdim + kof + (size_t)ch * 8;
            size_t gb = (size_t)(n0 + row) * Kdim + kof + (size_t)ch * 8;
            cp16(sb + so,              Ahi + ga);
            cp16(sb + TILE_B + so,     Alo + ga);
            cp16(sb + 2 * TILE_B + so, Bh + gb);
        }
        cp_commit();
    };

    float acc[4][4][4];
#pragma unroll
    for (int i = 0; i < 4; ++i)
#pragma unroll
        for (int j = 0; j < 4; ++j)
#pragma unroll
            for (int r = 0; r < 4; ++r) acc[i][j][r] = 0.f;

    load_stage(0);
    load_stage(1);

    for (int it = 0; it < KTILES; ++it) {
        cp_wait<1>();
        __syncthreads();
        if (it + 2 < KTILES) load_stage(it + 2);

        const uint32_t sb = s0 + (uint32_t)(it % 3) * H2_STAGE;
#pragma unroll
        for (int kk = 0; kk < 4; ++kk) {
            const uint32_t kx = (uint32_t)(kk * 32);
            uint32_t ah[4][4], al[4][4];
#pragma unroll
            for (int mf = 0; mf < 4; ++mf) {
                ldsm4(ah[mf], sb + (aBase[mf] ^ kx));
                ldsm4(al[mf], sb + TILE_B + (aBase[mf] ^ kx));
            }
            uint32_t bh[4][2];
#pragma unroll
            for (int nfp = 0; nfp < 2; ++nfp) {
                uint32_t t[4];
                ldsm4(t, sb + 2 * TILE_B + (bBase[nfp] ^ kx));
                bh[2 * nfp][0] = t[0]; bh[2 * nfp][1] = t[1];
                bh[2 * nfp + 1][0] = t[2]; bh[2 * nfp + 1][1] = t[3];
            }
#pragma unroll
            for (int mf = 0; mf < 4; ++mf)
#pragma unroll
                for (int nf = 0; nf < 4; ++nf) {
                    mma16816h(acc[mf][nf], ah[mf], bh[nf][0], bh[nf][1]);
                    mma16816h(acc[mf][nf], al[mf], bh[nf][0], bh[nf][1]);
                }
        }
    }

    const int cm = (lane >> 2);
    const int cn = (lane & 3) * 2;
#pragma unroll
    for (int mf = 0; mf < 4; ++mf) {
        const int row = m0 + wm * 64 + mf * 16 + cm;
#pragma unroll
        for (int nf = 0; nf < 4; ++nf) {
            const int col = n0 + wn * 32 + nf * 8 + cn;
            float2 v0 = make_float2(acc[mf][nf][0], acc[mf][nf][1]);
            float2 v1 = make_float2(acc[mf][nf][2], acc[mf][nf][3]);
            if (Res) {
                float2 r0 = *(const float2*)(Res + (size_t)row * Ndim + col);
                float2 r1 = *(const float2*)(Res + (size_t)(row + 8) * Ndim + col);
                v0.x += r0.x; v0.y += r0.y;
                v1.x += r1.x; v1.y += r1.y;
            }
            *(float2*)(C + (size_t)row * Ndim + col)       = v0;
            *(float2*)(C + (size_t)(row + 8) * Ndim + col) = v1;
        }
    }
}

// ---------------------------------------------------------------------------
// RoPE on g_k
// ---------------------------------------------------------------------------
__global__ void rope_kernel(float* __restrict__ k)
{
    const int gid = blockIdx.x * blockDim.x + threadIdx.x;
    const int total = Bsz * Ssz * HEADS * (HDIM / 2);
    if (gid >= total) return;
    const int i   = gid & 63;
    const int h   = (gid >> 6) & (HEADS - 1);
    const int row = gid >> 10;
    const int s   = row & (Ssz - 1);

    const float c = 0.20762050593046013f;   // log2(10000)/64
    const float inv = exp2f(-c * (float)i);
    const float ang = (float)s * inv;
    float sn = sinf(ang), cs = cosf(ang);

    float* p = k + (size_t)row * HID + h * HDIM;
    const float k1 = p[i];
    const float k2 = p[i + 64];
    p[i]      = k1 * cs - k2 * sn;
    p[i + 64] = k2 * cs + k1 * sn;
}

// ---------------------------------------------------------------------------
// Tensor-core TTT scan (R4-validated). Grid (64 bh, 2 e-halves), 128 threads.
// ---------------------------------------------------------------------------
#define OFF_RAWK   0
#define OFF_RAWV   16384
#define OFF_KHI    24576
#define OFF_KLO    32768
#define OFF_KTHI   40960
#define OFF_KTLO   47104
#define OFF_ETHI   53248
#define OFF_ETLO   56320
#define OFF_WTHI   59392
#define OFF_WTLO   75776
#define SCAN2_SMEM 92160

__global__ __launch_bounds__(128, 1)
void ttt_scan_mma(const float* __restrict__ gk,
                  const float* __restrict__ gv,
                  const float* __restrict__ W0,
                  float*       __restrict__ go)
{
    extern __shared__ __align__(16) char sm[];
    const uint32_t sb = smem_u32(sm);

    const int tid  = threadIdx.x;
    const int wid  = tid >> 5;
    const int lane = tid & 31;
    const int bh = blockIdx.x;
    const int eh = blockIdx.y;
    const int b  = bh >> 4, h = bh & 15;
    const int e0 = eh * 64;

    const int mat = lane >> 3, ml = lane & 7;
    const int arow = ((mat & 1) << 3) + ml;
    const uint32_t akb = (uint32_t)((mat >> 1) << 4);
    const int brow = ((mat >> 1) << 3) + ml;
    const uint32_t bkb = (uint32_t)((mat & 1) << 4);

    const uint32_t aBaseK = SWZ((uint32_t)(arow * 128)) ^ akb;
    const uint32_t bBaseW = SWZ((uint32_t)((16 * wid + brow) * 128)) ^ bkb;

    const int cr = lane >> 2;
    const int cc = (lane & 3) * 2;

    float W[2][8][4];
    {
        const float* W0p = W0 + (size_t)bh * (HDIM * HDIM);
#pragma unroll
        for (int t2 = 0; t2 < 2; ++t2) {
            int dt = 32 * wid + 16 * t2;
#pragma unroll
            for (int j = 0; j < 8; ++j) {
                int e = e0 + 8 * j + cc;
                W[t2][j][0] = W0p[(size_t)(dt + cr) * 128 + e];
                W[t2][j][1] = W0p[(size_t)(dt + cr) * 128 + e + 1];
                W[t2][j][2] = W0p[(size_t)(dt + cr + 8) * 128 + e];
                W[t2][j][3] = W0p[(size_t)(dt + cr + 8) * 128 + e + 1];
            }
        }
    }

    const float* kbase = gk + (size_t)b * Ssz * HID + h * HDIM;
    const float* vbase = gv + (size_t)b * Ssz * HID + h * HDIM + e0;
    float*       obase = go + (size_t)b * Ssz * HID + h * HDIM + e0;

    auto dumpW = [&]() {
#pragma unroll
        for (int t2 = 0; t2 < 2; ++t2) {
            int dt = 32 * wid + 16 * t2;
#pragma unroll
            for (int j = 0; j < 8; ++j) {
                int e = 8 * j + cc;
#pragma unroll
                for (int q = 0; q < 4; ++q) {
                    int d  = dt + cr + ((q >> 1) << 3);
                    int ee = e + (q & 1);
                    uint16_t hh, ll;
                    bsplit(W[t2][j][q], hh, ll);
                    uint32_t half = (uint32_t)(d >> 6);
                    uint32_t a = SWZ((uint32_t)(ee * 128 + (d & 63) * 2));
                    *(uint16_t*)(sm + OFF_WTHI + half * 8192 + a) = hh;
                    *(uint16_t*)(sm + OFF_WTLO + half * 8192 + a) = ll;
                }
            }
        }
    };

    auto loadKV = [&](int c) {
        int buf = c & 1;
        const float* ks = kbase + (size_t)(c * 16) * HID;
        const float* vs = vbase + (size_t)(c * 16) * HID;
#pragma unroll
        for (int j = 0; j < 4; ++j) {
            int q = j * 128 + tid;
            int row = q >> 5, ch = q & 31;
            cp16(sb + OFF_RAWK + buf * 8192 + (uint32_t)(row * 512 + ch * 16),
                 ks + (size_t)row * HID + ch * 4);
        }
#pragma unroll
        for (int j = 0; j < 2; ++j) {
            int q = j * 128 + tid;
            int row = q >> 4, ch = q & 15;
            cp16(sb + OFF_RAWV + buf * 4096 + (uint32_t)(row * 256 + ch * 16),
                 vs + (size_t)row * HID + ch * 4);
        }
        cp_commit();
    };

    auto convK = [&](int c) {
        int buf = c & 1;
        const float* rk = (const float*)(sm + OFF_RAWK + buf * 8192);
        int m = tid >> 3, c16 = (tid & 7) * 16;
        __align__(16) uint16_t hb[16], lb[16];
#pragma unroll
        for (int i = 0; i < 16; ++i) bsplit(rk[m * 128 + c16 + i], hb[i], lb[i]);
        uint32_t half = (uint32_t)(c16 >= 64);
        uint32_t ccl  = (uint32_t)((c16 & 63) * 2);
        uint32_t a0 = SWZ((uint32_t)(m * 128) + ccl);
        uint32_t a1 = SWZ((uint32_t)(m * 128) + ccl + 16);
        uint32_t kb = (uint32_t)(OFF_KHI + buf * 4096 + half * 2048);
        *(uint4*)(sm + kb + a0) = *(uint4*)&hb[0];
        *(uint4*)(sm + kb + a1) = *(uint4*)&hb[8];
        kb = (uint32_t)(OFF_KLO + buf * 4096 + half * 2048);
        *(uint4*)(sm + kb + a0) = *(uint4*)&lb[0];
        *(uint4*)(sm + kb + a1) = *(uint4*)&lb[8];
    };

    auto convKT = [&](int c) {
        int buf = c & 1;
        const float* rk = (const float*)(sm + OFF_RAWK + buf * 8192);
        int d = tid;
        __align__(16) uint16_t th[16], tl[16];
#pragma unroll
        for (int m = 0; m < 16; ++m) bsplit(rk[m * 128 + d], th[m], tl[m]);
        *(uint4*)(sm + OFF_KTHI + d * 48)      = *(uint4*)&th[0];
        *(uint4*)(sm + OFF_KTHI + d * 48 + 16) = *(uint4*)&th[8];
        *(uint4*)(sm + OFF_KTLO + d * 48)      = *(uint4*)&tl[0];
        *(uint4*)(sm + OFF_KTLO + d * 48 + 16) = *(uint4*)&tl[8];
    };

    float P[2][4];

    auto predOnly = [&](int buf, float acc[2][4]) {
#pragma unroll
        for (int f = 0; f < 2; ++f)
#pragma unroll
            for (int q = 0; q < 4; ++q) acc[f][q] = 0.f;
#pragma unroll
        for (int kk = 0; kk < 8; ++kk) {
            uint32_t half = (uint32_t)(kk >> 2);
            uint32_t kx   = (uint32_t)((kk & 3) * 32);
            uint32_t ah[4], al[4], t[4], bh[2][2], bl[2][2];
            ldsm4(ah, sb + OFF_KHI + buf * 4096 + half * 2048 + (aBaseK ^ kx));
            ldsm4(al, sb + OFF_KLO + buf * 4096 + half * 2048 + (aBaseK ^ kx));
            ldsm4(t, sb + OFF_WTHI + half * 8192 + (bBaseW ^ kx));
            bh[0][0] = t[0]; bh[0][1] = t[1]; bh[1][0] = t[2]; bh[1][1] = t[3];
            ldsm4(t, sb + OFF_WTLO + half * 8192 + (bBaseW ^ kx));
            bl[0][0] = t[0]; bl[0][1] = t[1]; bl[1][0] = t[2]; bl[1][1] = t[3];
#pragma unroll
            for (int f = 0; f < 2; ++f) {
                mma16816(acc[f], ah, bh[f][0], bh[f][1]);
                mma16816(acc[f], ah, bl[f][0], bl[f][1]);
                mma16816(acc[f], al, bh[f][0], bh[f][1]);
            }
        }
    };

    dumpW();
    loadKV(0);
    cp_wait<0>();
    __syncthreads();
    convK(0);
    __syncthreads();
    predOnly(0, P);

    for (int c = 0; c < NCH; ++c) {
        const int buf = c & 1;
        const bool hasNext = (c + 1 < NCH);
        if (hasNext) loadKV(c + 1);

        convKT(c);

        {
            const float* rv = (const float*)(sm + OFF_RAWV + buf * 4096);
#pragma unroll
            for (int f = 0; f < 2; ++f)
#pragma unroll
                for (int q = 0; q < 4; ++q) {
                    int e = 16 * wid + 8 * f + cc + (q & 1);
                    int m = cr + ((q >> 1) << 3);
                    float ep = (rv[m * 64 + e] - P[f][q]) * 0.0009765625f;
                    uint16_t hh, ll;
                    bsplit(ep, hh, ll);
                    *(uint16_t*)(sm + OFF_ETHI + e * 48 + m * 2) = hh;
                    *(uint16_t*)(sm + OFF_ETLO + e * 48 + m * 2) = ll;
                }
        }
        __syncthreads();

        {
            uint32_t aH[2][4], aL[2][4];
#pragma unroll
            for (int t2 = 0; t2 < 2; ++t2) {
                uint32_t ra = (uint32_t)((32 * wid + 16 * t2 + arow) * 48) + akb;
                ldsm4(aH[t2], sb + OFF_KTHI + ra);
                ldsm4(aL[t2], sb + OFF_KTLO + ra);
            }
#pragma unroll
            for (int p = 0; p < 4; ++p) {
                uint32_t rb = (uint32_t)((16 * p + brow) * 48) + bkb;
                uint32_t th[4], tl[4];
                ldsm4(th, sb + OFF_ETHI + rb);
                ldsm4(tl, sb + OFF_ETLO + rb);
#pragma unroll
                for (int t2 = 0; t2 < 2; ++t2) {
                    mma16816(W[t2][2 * p],     aH[t2], th[0], th[1]);
                    mma16816(W[t2][2 * p],     aH[t2], tl[0], tl[1]);
                    mma16816(W[t2][2 * p],     aL[t2], th[0], th[1]);
                    mma16816(W[t2][2 * p + 1], aH[t2], th[2], th[3]);
                    mma16816(W[t2][2 * p + 1], aH[t2], tl[2], tl[3]);
                    mma16816(W[t2][2 * p + 1], aL[t2], th[2], th[3]);
                }
            }
        }

        dumpW();

        if (hasNext) cp_wait<0>();
        __syncthreads();
        if (hasNext) convK(c + 1);
        __syncthreads();

        {
            float O[2][4];
#pragma unroll
            for (int f = 0; f < 2; ++f)
#pragma unroll
                for (int q = 0; q < 4; ++q) { O[f][q] = 0.f; P[f][q] = 0.f; }
            const int bufn = (c + 1) & 1;
#pragma unroll
            for (int kk = 0; kk < 8; ++kk) {
                uint32_t half = (uint32_t)(kk >> 2);
                uint32_t kx   = (uint32_t)((kk & 3) * 32);
                uint32_t t[4], bh[2][2], bl[2][2];
                ldsm4(t, sb + OFF_WTHI + half * 8192 + (bBaseW ^ kx));
                bh[0][0] = t[0]; bh[0][1] = t[1]; bh[1][0] = t[2]; bh[1][1] = t[3];
                ldsm4(t, sb + OFF_WTLO + half * 8192 + (bBaseW ^ kx));
                bl[0][0] = t[0]; bl[0][1] = t[1]; bl[1][0] = t[2]; bl[1][1] = t[3];

                uint32_t ah[4], al[4];
                ldsm4(ah, sb + OFF_KHI + buf * 4096 + half * 2048 + (aBaseK ^ kx));
                ldsm4(al, sb + OFF_KLO + buf * 4096 + half * 2048 + (aBaseK ^ kx));
#pragma unroll
                for (int f = 0; f < 2; ++f) {
                    mma16816(O[f], ah, bh[f][0], bh[f][1]);
                    mma16816(O[f], ah, bl[f][0], bl[f][1]);
                    mma16816(O[f], al, bh[f][0], bh[f][1]);
                }
                if (hasNext) {
                    uint32_t nh[4], nl[4];
                    ldsm4(nh, sb + OFF_KHI + bufn * 4096 + half * 2048 + (aBaseK ^ kx));
                    ldsm4(nl, sb + OFF_KLO + bufn * 4096 + half * 2048 + (aBaseK ^ kx));
#pragma unroll
                    for (int f = 0; f < 2; ++f) {
                        mma16816(P[f], nh, bh[f][0], bh[f][1]);
                        mma16816(P[f], nh, bl[f][0], bl[f][1]);
                        mma16816(P[f], nl, bh[f][0], bh[f][1]);
                    }
                }
            }
#pragma unroll
            for (int f = 0; f < 2; ++f) {
                int e = 16 * wid + 8 * f + cc;
                size_t r0 = (size_t)(c * 16 + cr) * HID + e;
                size_t r1 = (size_t)(c * 16 + cr + 8) * HID + e;
                *(float2*)(obase + r0) = make_float2(O[f][0], O[f][1]);
                *(float2*)(obase + r1) = make_float2(O[f][2], O[f][3]);
            }
        }
    }
}

// ---------------------------------------------------------------------------
// LayerNorm fused with fp16 hi/lo split (feeds the fp16 output GEMM)
// ---------------------------------------------------------------------------
__global__ __launch_bounds__(256)
void ln_cvt_kernel(const float* __restrict__ o,
                   const float* __restrict__ g,
                   const float* __restrict__ beta,
                   uint16_t* __restrict__ hi,
                   uint16_t* __restrict__ lo)
{
    __shared__ float s1[8], s2[8];
    const int row = blockIdx.x;
    const int t   = threadIdx.x;
    const float* p = o + (size_t)row * HID;

    float4 v0 = *(const float4*)(p + t * 8);
    float4 v1 = *(const float4*)(p + t * 8 + 4);
    float s  = v0.x + v0.y + v0.z + v0.w + v1.x + v1.y + v1.z + v1.w;
    float ss = v0.x*v0.x + v0.y*v0.y + v0.z*v0.z + v0.w*v0.w
             + v1.x*v1.x + v1.y*v1.y + v1.z*v1.z + v1.w*v1.w;
#pragma unroll
    for (int off = 16; off > 0; off >>= 1) {
        s  += __shfl_xor_sync(0xffffffffu, s,  off);
        ss += __shfl_xor_sync(0xffffffffu, ss, off);
    }
    const int w = t >> 5;
    if ((t & 31) == 0) { s1[w] = s; s2[w] = ss; }
    __syncthreads();
    float tot = 0.f, tot2 = 0.f;
#pragma unroll
    for (int i = 0; i < 8; ++i) { tot += s1[i]; tot2 += s2[i]; }
    const float mu  = tot * (1.0f / HID);
    const float var = tot2 * (1.0f / HID) - mu * mu;
    const float inv = rsqrtf(var + 1e-5f);

    float4 g0 = *(const float4*)(g + t * 8);
    float4 g1 = *(const float4*)(g + t * 8 + 4);
    float4 b0 = *(const float4*)(beta + t * 8);
    float4 b1 = *(const float4*)(beta + t * 8 + 4);
    float y[8];
    y[0] = (v0.x - mu) * inv * g0.x + b0.x;
    y[1] = (v0.y - mu) * inv * g0.y + b0.y;
    y[2] = (v0.z - mu) * inv * g0.z + b0.z;
    y[3] = (v0.w - mu) * inv * g0.w + b0.w;
    y[4] = (v1.x - mu) * inv * g1.x + b1.x;
    y[5] = (v1.y - mu) * inv * g1.y + b1.y;
    y[6] = (v1.z - mu) * inv * g1.z + b1.z;
    y[7] = (v1.w - mu) * inv * g1.w + b1.w;

    __align__(16) uint16_t hb[8], lb[8];
#pragma unroll
    for (int i = 0; i < 8; ++i) hsplit(y[i], hb[i], lb[i]);
    *(uint4*)(hi + (size_t)row * HID + t * 8) = *(uint4*)hb;
    *(uint4*)(lo + (size_t)row * HID + t * 8) = *(uint4*)lb;
}

// ---------------------------------------------------------------------------
// launch
// ---------------------------------------------------------------------------
extern "C" void kernel_launch(void* const* d_in, const int* in_sizes, int n_in,
                              void* d_out, int out_size)
{
    const float* x   = (const float*)d_in[0];
    const float* Wk  = (const float*)d_in[1];
    const float* Wv  = (const float*)d_in[2];
    const float* Wo  = (const float*)d_in[3];
    const float* lng = (const float*)d_in[4];
    const float* lnb = (const float*)d_in[5];
    const float* W0  = (const float*)d_in[6];
    float* out = (float*)d_out;

    float *gk, *gv, *go;
    uint16_t *ahi, *alo, *whi;
    cudaGetSymbolAddress((void**)&gk, g_k);
    cudaGetSymbolAddress((void**)&gv, g_v);
    cudaGetSymbolAddress((void**)&go, g_o);
    cudaGetSymbolAddress((void**)&ahi, g_ahi);
    cudaGetSymbolAddress((void**)&alo, g_alo);
    cudaGetSymbolAddress((void**)&whi, g_whi);

    cudaFuncSetAttribute(ttt_scan_mma,
                         cudaFuncAttributeMaxDynamicSharedMemorySize, SCAN2_SMEM);
    cudaFuncSetAttribute(gemm_h2_kernel,
                         cudaFuncAttributeMaxDynamicSharedMemorySize, H2_SMEM);

    const int nx4 = (Mrows * HID) / 4;
    const int nw4 = (HID * HID) / 4;
    dim3 gg(Ndim / 128, Mrows / 128);    // (16, 64)

    // split x to fp16 hi/lo
    cvt_hilo_h<<<(nx4 + 255) / 256, 256>>>(x, ahi, alo, nx4);

    // k = x @ Wk^T   (fp16 2-product)
    cvt_hi_h<<<(nw4 + 255) / 256, 256>>>(Wk, whi, nw4);
    gemm_h2_kernel<<<gg, 256, H2_SMEM>>>(ahi, alo, whi, gk, nullptr);

    // v = x @ Wv^T   (fp16 2-product)
    cvt_hi_h<<<(nw4 + 255) / 256, 256>>>(Wv, whi, nw4);
    gemm_h2_kernel<<<gg, 256, H2_SMEM>>>(ahi, alo, whi, gv, nullptr);

    // RoPE on k
    {
        const int total = Bsz * Ssz * HEADS * (HDIM / 2);
        rope_kernel<<<(total + 255) / 256, 256>>>(gk);
    }

    // TTT scan -> o  (tensor-core, e-split)
    {
        dim3 sg(Bsz * HEADS, 2);
        ttt_scan_mma<<<sg, 128, SCAN2_SMEM>>>(gk, gv, W0, go);
    }

    // LayerNorm fused with fp16 hi/lo split
    ln_cvt_kernel<<<Mrows, 256>>>(go, lng, lnb, ahi, alo);

    // out = x + o_ln @ Wo^T  (fp16 2-product, residual fused)
    cvt_hi_h<<<(nw4 + 255) / 256, 256>>>(Wo, whi, nw4);
    gemm_h2_kernel<<<gg, 256, H2_SMEM>>>(ahi, alo, whi, out, x);
}

// round 9
// speedup vs baseline: 1.9016x; 1.1701x over previous
#include <cuda_runtime.h>
#include <cuda_bf16.h>
#include <cuda_fp16.h>
#include <cstdint>

// Problem constants
#define Bsz   4
#define Ssz   2048
#define HID   2048
#define HEADS 16
#define HDIM  128
#define MBsz  16
#define NCH   128
#define Mrows (Bsz*Ssz)    // 8192
#define Kdim  2048
#define Ndim  2048

// Scratch (device globals: allocation-free rule). 16-bit payload is fp16.
__device__ float g_k[(size_t)Mrows * HID];
__device__ float g_v[(size_t)Mrows * HID];
__device__ float g_o[(size_t)Mrows * HID];
__device__ uint16_t g_ahi[(size_t)Mrows * HID];
__device__ uint16_t g_alo[(size_t)Mrows * HID];
__device__ uint16_t g_whi[(size_t)HID * HID];

// ---------------------------------------------------------------------------
// helpers (baseline PTX only: cp.async / ldmatrix / mma.sync — sm_80 features)
// ---------------------------------------------------------------------------
__device__ __forceinline__ uint32_t smem_u32(const void* p) {
    uint32_t a;
    asm("{ .reg .u64 t; cvta.to.shared.u64 t, %1; cvt.u32.u64 %0, t; }"
        : "=r"(a) : "l"(p));
    return a;
}

#define SWZ(x) ((x) ^ (((x) >> 3) & 0x70))

__device__ __forceinline__ void cp16(uint32_t dst, const void* src) {
    asm volatile("cp.async.cg.shared.global [%0], [%1], 16;\n"
                 :: "r"(dst), "l"(src) : "memory");
}
__device__ __forceinline__ void cp_commit() {
    asm volatile("cp.async.commit_group;\n" ::: "memory");
}
template <int N> __device__ __forceinline__ void cp_wait() {
    asm volatile("cp.async.wait_group %0;\n" :: "n"(N) : "memory");
}

__device__ __forceinline__ void ldsm4(uint32_t r[4], uint32_t a) {
    asm volatile("ldmatrix.sync.aligned.m8n8.x4.shared.b16 {%0,%1,%2,%3}, [%4];"
                 : "=r"(r[0]), "=r"(r[1]), "=r"(r[2]), "=r"(r[3]) : "r"(a));
}

// fp16 mma
__device__ __forceinline__ void mma16816h(float c[4], const uint32_t a[4],
                                          const uint32_t b0, const uint32_t b1) {
    asm volatile(
        "mma.sync.aligned.m16n8k16.row.col.f32.f16.f16.f32 "
        "{%0,%1,%2,%3}, {%4,%5,%6,%7}, {%8,%9}, {%0,%1,%2,%3};"
        : "+f"(c[0]), "+f"(c[1]), "+f"(c[2]), "+f"(c[3])
        : "r"(a[0]), "r"(a[1]), "r"(a[2]), "r"(a[3]), "r"(b0), "r"(b1));
}

__device__ __forceinline__ void hsplit(float x, uint16_t& h, uint16_t& l) {
    __half hb = __float2half_rn(x);
    __half lb = __float2half_rn(x - __half2float(hb));
    h = *(uint16_t*)&hb;
    l = *(uint16_t*)&lb;
}
__device__ __forceinline__ uint16_t f2h(float x) {
    __half hb = __float2half_rn(x);
    return *(uint16_t*)&hb;
}

// ---------------------------------------------------------------------------
// converters
// ---------------------------------------------------------------------------
__global__ __launch_bounds__(256)
void cvt_hilo_h(const float* __restrict__ s,
                uint16_t* __restrict__ hi,
                uint16_t* __restrict__ lo, int n4)
{
    int i = blockIdx.x * blockDim.x + threadIdx.x;
    if (i >= n4) return;
    float4 v = ((const float4*)s)[i];
    uint16_t h[4], l[4];
    hsplit(v.x, h[0], l[0]); hsplit(v.y, h[1], l[1]);
    hsplit(v.z, h[2], l[2]); hsplit(v.w, h[3], l[3]);
    *(uint64_t*)(hi + 4 * (size_t)i) = *(uint64_t*)h;
    *(uint64_t*)(lo + 4 * (size_t)i) = *(uint64_t*)l;
}

__global__ __launch_bounds__(256)
void cvt_hi_h(const float* __restrict__ s,
              uint16_t* __restrict__ hi, int n4)
{
    int i = blockIdx.x * blockDim.x + threadIdx.x;
    if (i >= n4) return;
    float4 v = ((const float4*)s)[i];
    uint16_t h[4];
    h[0] = f2h(v.x); h[1] = f2h(v.y); h[2] = f2h(v.z); h[3] = f2h(v.w);
    *(uint64_t*)(hi + 4 * (size_t)i) = *(uint64_t*)h;
}

// ---------------------------------------------------------------------------
// fp16 GEMM (R7-proven schedule): C = (Ah [+ Al]) @ Bh^T (+ optional residual)
// USE_LO selects 2-product (hi+lo activations) vs single-product.
// CTA 128x128, BK=64, GS=3 cp.async pipeline, occupancy 1, 8 warps,
// warp tile 64(m) x 32(n).
// ---------------------------------------------------------------------------
#define TILE_B   16384
#define H2_STAGE (3 * TILE_B)              // Ahi, Alo, Bh = 48KB
#define H2_SMEM  (1024 + 3 * H2_STAGE)     // 148480
#define KTILES   (Kdim / 64)               // 32

template <bool USE_LO>
__global__ __launch_bounds__(256, 1)
void gemm_h2_kernel(const uint16_t* __restrict__ Ahi,
                    const uint16_t* __restrict__ Alo,
                    const uint16_t* __restrict__ Bh,
                    float* __restrict__ C,
                    const float* __restrict__ Res)
{
    extern __shared__ uint8_t smraw[];
    const uint32_t s0 = (smem_u32(smraw) + 1023u) & ~1023u;

    const int tid  = threadIdx.x;
    const int wid  = tid >> 5;
    const int lane = tid & 31;
    const int wm   = wid & 1;        // 2 m-warps, 64 rows
    const int wn   = wid >> 1;       // 4 n-warps, 32 cols
    const int m0 = blockIdx.y * 128;
    const int n0 = blockIdx.x * 128;

    uint32_t aBase[4];
    {
        int amat = lane >> 3, al = lane & 7;
        int rofs = ((amat & 1) << 3) + al;
        uint32_t akb = (uint32_t)((amat >> 1) << 4);
#pragma unroll
        for (int mf = 0; mf < 4; ++mf) {
            uint32_t r = (uint32_t)(wm * 64 + mf * 16 + rofs) * 128u;
            aBase[mf] = SWZ(r) ^ akb;
        }
    }
    uint32_t bBase[2];
    {
        int bmat = lane >> 3, bl = lane & 7;
        int rofs = ((bmat >> 1) << 3) + bl;
        uint32_t bkb = (uint32_t)((bmat & 1) << 4);
#pragma unroll
        for (int nfp = 0; nfp < 2; ++nfp) {
            uint32_t r = (uint32_t)(wn * 32 + nfp * 16 + rofs) * 128u;
            bBase[nfp] = SWZ(r) ^ bkb;
        }
    }

    auto load_stage = [&](int kt) {
        uint32_t sb = s0 + (uint32_t)(kt % 3) * H2_STAGE;
        const size_t kof = (size_t)kt * 64;
#pragma unroll
        for (int j = 0; j < 4; ++j) {
            int q = j * 256 + tid;
            int row = q >> 3, ch = q & 7;
            uint32_t so = SWZ((uint32_t)(row * 128 + ch * 16));
            size_t ga = (size_t)(m0 + row) * Kdim + kof + (size_t)ch * 8;
            size_t gb = (size_t)(n0 + row) * Kdim + kof + (size_t)ch * 8;
            cp16(sb + so, Ahi + ga);
            if (USE_LO) cp16(sb + TILE_B + so, Alo + ga);
            cp16(sb + 2 * TILE_B + so, Bh + gb);
        }
        cp_commit();
    };

    float acc[4][4][4];
#pragma unroll
    for (int i = 0; i < 4; ++i)
#pragma unroll
        for (int j = 0; j < 4; ++j)
#pragma unroll
            for (int r = 0; r < 4; ++r) acc[i][j][r] = 0.f;

    load_stage(0);
    load_stage(1);

    for (int it = 0; it < KTILES; ++it) {
        cp_wait<1>();
        __syncthreads();
        if (it + 2 < KTILES) load_stage(it + 2);

        const uint32_t sb = s0 + (uint32_t)(it % 3) * H2_STAGE;
#pragma unroll
        for (int kk = 0; kk < 4; ++kk) {
            const uint32_t kx = (uint32_t)(kk * 32);
            uint32_t ah[4][4], al[4][4];
#pragma unroll
            for (int mf = 0; mf < 4; ++mf) {
                ldsm4(ah[mf], sb + (aBase[mf] ^ kx));
                if (USE_LO) ldsm4(al[mf], sb + TILE_B + (aBase[mf] ^ kx));
            }
            uint32_t bh[4][2];
#pragma unroll
            for (int nfp = 0; nfp < 2; ++nfp) {
                uint32_t t[4];
                ldsm4(t, sb + 2 * TILE_B + (bBase[nfp] ^ kx));
                bh[2 * nfp][0] = t[0]; bh[2 * nfp][1] = t[1];
                bh[2 * nfp + 1][0] = t[2]; bh[2 * nfp + 1][1] = t[3];
            }
#pragma unroll
            for (int mf = 0; mf < 4; ++mf)
#pragma unroll
                for (int nf = 0; nf < 4; ++nf) {
                    mma16816h(acc[mf][nf], ah[mf], bh[nf][0], bh[nf][1]);
                    if (USE_LO)
                        mma16816h(acc[mf][nf], al[mf], bh[nf][0], bh[nf][1]);
                }
        }
    }

    const int cm = (lane >> 2);
    const int cn = (lane & 3) * 2;
#pragma unroll
    for (int mf = 0; mf < 4; ++mf) {
        const int row = m0 + wm * 64 + mf * 16 + cm;
#pragma unroll
        for (int nf = 0; nf < 4; ++nf) {
            const int col = n0 + wn * 32 + nf * 8 + cn;
            float2 v0 = make_float2(acc[mf][nf][0], acc[mf][nf][1]);
            float2 v1 = make_float2(acc[mf][nf][2], acc[mf][nf][3]);
            if (Res) {
                float2 r0 = *(const float2*)(Res + (size_t)row * Ndim + col);
                float2 r1 = *(const float2*)(Res + (size_t)(row + 8) * Ndim + col);
                v0.x += r0.x; v0.y += r0.y;
                v1.x += r1.x; v1.y += r1.y;
            }
            *(float2*)(C + (size_t)row * Ndim + col)       = v0;
            *(float2*)(C + (size_t)(row + 8) * Ndim + col) = v1;
        }
    }
}

// ---------------------------------------------------------------------------
// RoPE on g_k
// ---------------------------------------------------------------------------
__global__ void rope_kernel(float* __restrict__ k)
{
    const int gid = blockIdx.x * blockDim.x + threadIdx.x;
    const int total = Bsz * Ssz * HEADS * (HDIM / 2);
    if (gid >= total) return;
    const int i   = gid & 63;
    const int h   = (gid >> 6) & (HEADS - 1);
    const int row = gid >> 10;
    const int s   = row & (Ssz - 1);

    const float c = 0.20762050593046013f;   // log2(10000)/64
    const float inv = exp2f(-c * (float)i);
    const float ang = (float)s * inv;
    float sn = sinf(ang), cs = cosf(ang);

    float* p = k + (size_t)row * HID + h * HDIM;
    const float k1 = p[i];
    const float k2 = p[i + 64];
    p[i]      = k1 * cs - k2 * sn;
    p[i + 64] = k2 * cs + k1 * sn;
}

// ---------------------------------------------------------------------------
// Tensor-core TTT scan, fp16 2-product numerics.
// Grid (64 bh, 2 e-halves), 128 threads (4 warps).
// W [128d x 64e] in fp32 mma accumulators; K (A side) fp16 hi+lo;
// W / E' (B side) rounded once to fp16.
// ---------------------------------------------------------------------------
#define OFF_RAWK   0            // [2][16][128] f32 = 16384
#define OFF_RAWV   16384        // [2][16][64]  f32 = 8192
#define OFF_KHI    24576        // [2 buf][2 half][2048B] = 8192
#define OFF_KLO    32768        // 8192
#define OFF_KTHI   40960        // [128][48B] = 6144
#define OFF_KTLO   47104        // 6144
#define OFF_ETHI   53248        // [64][48B] = 3072
#define OFF_WTHI   56320        // [2 half][8192B] = 16384
#define SCAN2_SMEM 72704

__global__ __launch_bounds__(128, 1)
void ttt_scan_mma(const float* __restrict__ gk,
                  const float* __restrict__ gv,
                  const float* __restrict__ W0,
                  float*       __restrict__ go)
{
    extern __shared__ __align__(16) char sm[];
    const uint32_t sb = smem_u32(sm);

    const int tid  = threadIdx.x;
    const int wid  = tid >> 5;
    const int lane = tid & 31;
    const int bh = blockIdx.x;
    const int eh = blockIdx.y;
    const int b  = bh >> 4, h = bh & 15;
    const int e0 = eh * 64;

    const int mat = lane >> 3, ml = lane & 7;
    const int arow = ((mat & 1) << 3) + ml;
    const uint32_t akb = (uint32_t)((mat >> 1) << 4);
    const int brow = ((mat >> 1) << 3) + ml;
    const uint32_t bkb = (uint32_t)((mat & 1) << 4);

    const uint32_t aBaseK = SWZ((uint32_t)(arow * 128)) ^ akb;
    const uint32_t bBaseW = SWZ((uint32_t)((16 * wid + brow) * 128)) ^ bkb;

    const int cr = lane >> 2;
    const int cc = (lane & 3) * 2;

    float W[2][8][4];
    {
        const float* W0p = W0 + (size_t)bh * (HDIM * HDIM);
#pragma unroll
        for (int t2 = 0; t2 < 2; ++t2) {
            int dt = 32 * wid + 16 * t2;
#pragma unroll
            for (int j = 0; j < 8; ++j) {
                int e = e0 + 8 * j + cc;
                W[t2][j][0] = W0p[(size_t)(dt + cr) * 128 + e];
                W[t2][j][1] = W0p[(size_t)(dt + cr) * 128 + e + 1];
                W[t2][j][2] = W0p[(size_t)(dt + cr + 8) * 128 + e];
                W[t2][j][3] = W0p[(size_t)(dt + cr + 8) * 128 + e + 1];
            }
        }
    }

    const float* kbase = gk + (size_t)b * Ssz * HID + h * HDIM;
    const float* vbase = gv + (size_t)b * Ssz * HID + h * HDIM + e0;
    float*       obase = go + (size_t)b * Ssz * HID + h * HDIM + e0;

    auto dumpW = [&]() {
#pragma unroll
        for (int t2 = 0; t2 < 2; ++t2) {
            int dt = 32 * wid + 16 * t2;
#pragma unroll
            for (int j = 0; j < 8; ++j) {
                int e = 8 * j + cc;
#pragma unroll
                for (int q = 0; q < 4; ++q) {
                    int d  = dt + cr + ((q >> 1) << 3);
                    int ee = e + (q & 1);
                    uint32_t half = (uint32_t)(d >> 6);
                    uint32_t a = SWZ((uint32_t)(ee * 128 + (d & 63) * 2));
                    *(uint16_t*)(sm + OFF_WTHI + half * 8192 + a) = f2h(W[t2][j][q]);
                }
            }
        }
    };

    auto loadKV = [&](int c) {
        int buf = c & 1;
        const float* ks = kbase + (size_t)(c * 16) * HID;
        const float* vs = vbase + (size_t)(c * 16) * HID;
#pragma unroll
        for (int j = 0; j < 4; ++j) {
            int q = j * 128 + tid;
            int row = q >> 5, ch = q & 31;
            cp16(sb + OFF_RAWK + buf * 8192 + (uint32_t)(row * 512 + ch * 16),
                 ks + (size_t)row * HID + ch * 4);
        }
#pragma unroll
        for (int j = 0; j < 2; ++j) {
            int q = j * 128 + tid;
            int row = q >> 4, ch = q & 15;
            cp16(sb + OFF_RAWV + buf * 4096 + (uint32_t)(row * 256 + ch * 16),
                 vs + (size_t)row * HID + ch * 4);
        }
        cp_commit();
    };

    auto convK = [&](int c) {
        int buf = c & 1;
        const float* rk = (const float*)(sm + OFF_RAWK + buf * 8192);
        int m = tid >> 3, c16 = (tid & 7) * 16;
        __align__(16) uint16_t hb[16], lb[16];
#pragma unroll
        for (int i = 0; i < 16; ++i) hsplit(rk[m * 128 + c16 + i], hb[i], lb[i]);
        uint32_t half = (uint32_t)(c16 >= 64);
        uint32_t ccl  = (uint32_t)((c16 & 63) * 2);
        uint32_t a0 = SWZ((uint32_t)(m * 128) + ccl);
        uint32_t a1 = SWZ((uint32_t)(m * 128) + ccl + 16);
        uint32_t kb = (uint32_t)(OFF_KHI + buf * 4096 + half * 2048);
        *(uint4*)(sm + kb + a0) = *(uint4*)&hb[0];
        *(uint4*)(sm + kb + a1) = *(uint4*)&hb[8];
        kb = (uint32_t)(OFF_KLO + buf * 4096 + half * 2048);
        *(uint4*)(sm + kb + a0) = *(uint4*)&lb[0];
        *(uint4*)(sm + kb + a1) = *(uint4*)&lb[8];
    };

    auto convKT = [&](int c) {
        int buf = c & 1;
        const float* rk = (const float*)(sm + OFF_RAWK + buf * 8192);
        int d = tid;
        __align__(16) uint16_t th[16], tl[16];
#pragma unroll
        for (int m = 0; m < 16; ++m) hsplit(rk[m * 128 + d], th[m], tl[m]);
        *(uint4*)(sm + OFF_KTHI + d * 48)      = *(uint4*)&th[0];
        *(uint4*)(sm + OFF_KTHI + d * 48 + 16) = *(uint4*)&th[8];
        *(uint4*)(sm + OFF_KTLO + d * 48)      = *(uint4*)&tl[0];
        *(uint4*)(sm + OFF_KTLO + d * 48 + 16) = *(uint4*)&tl[8];
    };

    float P[2][4];

    auto predOnly = [&](int buf, float acc[2][4]) {
#pragma unroll
        for (int f = 0; f < 2; ++f)
#pragma unroll
            for (int q = 0; q < 4; ++q) acc[f][q] = 0.f;
#pragma unroll
        for (int kk = 0; kk < 8; ++kk) {
            uint32_t half = (uint32_t)(kk >> 2);
            uint32_t kx   = (uint32_t)((kk & 3) * 32);
            uint32_t ah[4], al[4], t[4], bh[2][2];
            ldsm4(ah, sb + OFF_KHI + buf * 4096 + half * 2048 + (aBaseK ^ kx));
            ldsm4(al, sb + OFF_KLO + buf * 4096 + half * 2048 + (aBaseK ^ kx));
            ldsm4(t, sb + OFF_WTHI + half * 8192 + (bBaseW ^ kx));
            bh[0][0] = t[0]; bh[0][1] = t[1]; bh[1][0] = t[2]; bh[1][1] = t[3];
#pragma unroll
            for (int f = 0; f < 2; ++f) {
                mma16816h(acc[f], ah, bh[f][0], bh[f][1]);
                mma16816h(acc[f], al, bh[f][0], bh[f][1]);
            }
        }
    };

    dumpW();
    loadKV(0);
    cp_wait<0>();
    __syncthreads();
    convK(0);
    __syncthreads();
    predOnly(0, P);

    for (int c = 0; c < NCH; ++c) {
        const int buf = c & 1;
        const bool hasNext = (c + 1 < NCH);
        if (hasNext) loadKV(c + 1);

        convKT(c);

        // E' = (V - pred) / 1024, fp16 (hi only — B side)
        {
            const float* rv = (const float*)(sm + OFF_RAWV + buf * 4096);
#pragma unroll
            for (int f = 0; f < 2; ++f)
#pragma unroll
                for (int q = 0; q < 4; ++q) {
                    int e = 16 * wid + 8 * f + cc + (q & 1);
                    int m = cr + ((q >> 1) << 3);
                    float ep = (rv[m * 64 + e] - P[f][q]) * 0.0009765625f;
                    *(uint16_t*)(sm + OFF_ETHI + e * 48 + m * 2) = f2h(ep);
                }
        }
        __syncthreads();

        // W += K^T @ E'   (A = K^T hi+lo fp16, B = E' fp16)
        {
            uint32_t aH[2][4], aL[2][4];
#pragma unroll
            for (int t2 = 0; t2 < 2; ++t2) {
                uint32_t ra = (uint32_t)((32 * wid + 16 * t2 + arow) * 48) + akb;
                ldsm4(aH[t2], sb + OFF_KTHI + ra);
                ldsm4(aL[t2], sb + OFF_KTLO + ra);
            }
#pragma unroll
            for (int p = 0; p < 4; ++p) {
                uint32_t rb = (uint32_t)((16 * p + brow) * 48) + bkb;
                uint32_t th[4];
                ldsm4(th, sb + OFF_ETHI + rb);
#pragma unroll
                for (int t2 = 0; t2 < 2; ++t2) {
                    mma16816h(W[t2][2 * p],     aH[t2], th[0], th[1]);
                    mma16816h(W[t2][2 * p],     aL[t2], th[0], th[1]);
                    mma16816h(W[t2][2 * p + 1], aH[t2], th[2], th[3]);
                    mma16816h(W[t2][2 * p + 1], aL[t2], th[2], th[3]);
                }
            }
        }

        dumpW();

        if (hasNext) cp_wait<0>();
        __syncthreads();
        if (hasNext) convK(c + 1);
        __syncthreads();

        // fused: out_c = K_c @ W_new (+ pred_{c+1} = K_{c+1} @ W_new)
        {
            float O[2][4];
#pragma unroll
            for (int f = 0; f < 2; ++f)
#pragma unroll
                for (int q = 0; q < 4; ++q) { O[f][q] = 0.f; P[f][q] = 0.f; }
            const int bufn = (c + 1) & 1;
#pragma unroll
            for (int kk = 0; kk < 8; ++kk) {
                uint32_t half = (uint32_t)(kk >> 2);
                uint32_t kx   = (uint32_t)((kk & 3) * 32);
                uint32_t t[4], bh[2][2];
                ldsm4(t, sb + OFF_WTHI + half * 8192 + (bBaseW ^ kx));
                bh[0][0] = t[0]; bh[0][1] = t[1]; bh[1][0] = t[2]; bh[1][1] = t[3];

                uint32_t ah[4], al[4];
                ldsm4(ah, sb + OFF_KHI + buf * 4096 + half * 2048 + (aBaseK ^ kx));
                ldsm4(al, sb + OFF_KLO + buf * 4096 + half * 2048 + (aBaseK ^ kx));
#pragma unroll
                for (int f = 0; f < 2; ++f) {
                    mma16816h(O[f], ah, bh[f][0], bh[f][1]);
                    mma16816h(O[f], al, bh[f][0], bh[f][1]);
                }
                if (hasNext) {
                    uint32_t nh[4], nl[4];
                    ldsm4(nh, sb + OFF_KHI + bufn * 4096 + half * 2048 + (aBaseK ^ kx));
                    ldsm4(nl, sb + OFF_KLO + bufn * 4096 + half * 2048 + (aBaseK ^ kx));
#pragma unroll
                    for (int f = 0; f < 2; ++f) {
                        mma16816h(P[f], nh, bh[f][0], bh[f][1]);
                        mma16816h(P[f], nl, bh[f][0], bh[f][1]);
                    }
                }
            }
#pragma unroll
            for (int f = 0; f < 2; ++f) {
                int e = 16 * wid + 8 * f + cc;
                size_t r0 = (size_t)(c * 16 + cr) * HID + e;
                size_t r1 = (size_t)(c * 16 + cr + 8) * HID + e;
                *(float2*)(obase + r0) = make_float2(O[f][0], O[f][1]);
                *(float2*)(obase + r1) = make_float2(O[f][2], O[f][3]);
            }
        }
    }
}

// ---------------------------------------------------------------------------
// LayerNorm fused with fp16 hi/lo split (feeds the fp16 output GEMM)
// ---------------------------------------------------------------------------
__global__ __launch_bounds__(256)
void ln_cvt_kernel(const float* __restrict__ o,
                   const float* __restrict__ g,
                   const float* __restrict__ beta,
                   uint16_t* __restrict__ hi,
                   uint16_t* __restrict__ lo)
{
    __shared__ float s1[8], s2[8];
    const int row = blockIdx.x;
    const int t   = threadIdx.x;
    const float* p = o + (size_t)row * HID;

    float4 v0 = *(const float4*)(p + t * 8);
    float4 v1 = *(const float4*)(p + t * 8 + 4);
    float s  = v0.x + v0.y + v0.z + v0.w + v1.x + v1.y + v1.z + v1.w;
    float ss = v0.x*v0.x + v0.y*v0.y + v0.z*v0.z + v0.w*v0.w
             + v1.x*v1.x + v1.y*v1.y + v1.z*v1.z + v1.w*v1.w;
#pragma unroll
    for (int off = 16; off > 0; off >>= 1) {
        s  += __shfl_xor_sync(0xffffffffu, s,  off);
        ss += __shfl_xor_sync(0xffffffffu, ss, off);
    }
    const int w = t >> 5;
    if ((t & 31) == 0) { s1[w] = s; s2[w] = ss; }
    __syncthreads();
    float tot = 0.f, tot2 = 0.f;
#pragma unroll
    for (int i = 0; i < 8; ++i) { tot += s1[i]; tot2 += s2[i]; }
    const float mu  = tot * (1.0f / HID);
    const float var = tot2 * (1.0f / HID) - mu * mu;
    const float inv = rsqrtf(var + 1e-5f);

    float4 g0 = *(const float4*)(g + t * 8);
    float4 g1 = *(const float4*)(g + t * 8 + 4);
    float4 b0 = *(const float4*)(beta + t * 8);
    float4 b1 = *(const float4*)(beta + t * 8 + 4);
    float y[8];
    y[0] = (v0.x - mu) * inv * g0.x + b0.x;
    y[1] = (v0.y - mu) * inv * g0.y + b0.y;
    y[2] = (v0.z - mu) * inv * g0.z + b0.z;
    y[3] = (v0.w - mu) * inv * g0.w + b0.w;
    y[4] = (v1.x - mu) * inv * g1.x + b1.x;
    y[5] = (v1.y - mu) * inv * g1.y + b1.y;
    y[6] = (v1.z - mu) * inv * g1.z + b1.z;
    y[7] = (v1.w - mu) * inv * g1.w + b1.w;

    __align__(16) uint16_t hb[8], lb[8];
#pragma unroll
    for (int i = 0; i < 8; ++i) hsplit(y[i], hb[i], lb[i]);
    *(uint4*)(hi + (size_t)row * HID + t * 8) = *(uint4*)hb;
    *(uint4*)(lo + (size_t)row * HID + t * 8) = *(uint4*)lb;
}

// ---------------------------------------------------------------------------
// launch
// ---------------------------------------------------------------------------
extern "C" void kernel_launch(void* const* d_in, const int* in_sizes, int n_in,
                              void* d_out, int out_size)
{
    const float* x   = (const float*)d_in[0];
    const float* Wk  = (const float*)d_in[1];
    const float* Wv  = (const float*)d_in[2];
    const float* Wo  = (const float*)d_in[3];
    const float* lng = (const float*)d_in[4];
    const float* lnb = (const float*)d_in[5];
    const float* W0  = (const float*)d_in[6];
    float* out = (float*)d_out;

    float *gk, *gv, *go;
    uint16_t *ahi, *alo, *whi;
    cudaGetSymbolAddress((void**)&gk, g_k);
    cudaGetSymbolAddress((void**)&gv, g_v);
    cudaGetSymbolAddress((void**)&go, g_o);
    cudaGetSymbolAddress((void**)&ahi, g_ahi);
    cudaGetSymbolAddress((void**)&alo, g_alo);
    cudaGetSymbolAddress((void**)&whi, g_whi);

    cudaFuncSetAttribute(ttt_scan_mma,
                         cudaFuncAttributeMaxDynamicSharedMemorySize, SCAN2_SMEM);
    cudaFuncSetAttribute(gemm_h2_kernel<true>,
                         cudaFuncAttributeMaxDynamicSharedMemorySize, H2_SMEM);
    cudaFuncSetAttribute(gemm_h2_kernel<false>,
                         cudaFuncAttributeMaxDynamicSharedMemorySize, H2_SMEM);

    const int nx4 = (Mrows * HID) / 4;
    const int nw4 = (HID * HID) / 4;
    dim3 gg(Ndim / 128, Mrows / 128);    // (16, 64)

    // split x to fp16 hi/lo
    cvt_hilo_h<<<(nx4 + 255) / 256, 256>>>(x, ahi, alo, nx4);

    // k = x @ Wk^T   (fp16 2-product)
    cvt_hi_h<<<(nw4 + 255) / 256, 256>>>(Wk, whi, nw4);
    gemm_h2_kernel<true><<<gg, 256, H2_SMEM>>>(ahi, alo, whi, gk, nullptr);

    // v = x @ Wv^T   (fp16 single-product; v is only the regression target)
    cvt_hi_h<<<(nw4 + 255) / 256, 256>>>(Wv, whi, nw4);
    gemm_h2_kernel<false><<<gg, 256, H2_SMEM>>>(ahi, alo, whi, gv, nullptr);

    // RoPE on k
    {
        const int total = Bsz * Ssz * HEADS * (HDIM / 2);
        rope_kernel<<<(total + 255) / 256, 256>>>(gk);
    }

    // TTT scan -> o  (tensor-core, e-split, fp16 2-product internals)
    {
        dim3 sg(Bsz * HEADS, 2);
        ttt_scan_mma<<<sg, 128, SCAN2_SMEM>>>(gk, gv, W0, go);
    }

    // LayerNorm fused with fp16 hi/lo split
    ln_cvt_kernel<<<Mrows, 256>>>(go, lng, lnb, ahi, alo);

    // out = x + o_ln @ Wo^T  (fp16 2-product, residual fused)
    cvt_hi_h<<<(nw4 + 255) / 256, 256>>>(Wo, whi, nw4);
    gemm_h2_kernel<true><<<gg, 256, H2_SMEM>>>(ahi, alo, whi, out, x);
}

// round 10
// speedup vs baseline: 2.1268x; 1.1184x over previous
#include <cuda_runtime.h>
#include <cuda_bf16.h>
#include <cuda_fp16.h>
#include <cstdint>

// Problem constants
#define Bsz   4
#define Ssz   2048
#define HID   2048
#define HEADS 16
#define HDIM  128
#define MBsz  16
#define NCH   128
#define Mrows (Bsz*Ssz)    // 8192
#define Kdim  2048
#define Ndim  2048

// Scratch (device globals: allocation-free rule). 16-bit payload is fp16.
__device__ float g_k[(size_t)Mrows * HID];
__device__ float g_v[(size_t)Mrows * HID];
__device__ float g_o[(size_t)Mrows * HID];
__device__ uint16_t g_ahi[(size_t)Mrows * HID];
__device__ uint16_t g_alo[(size_t)Mrows * HID];
__device__ uint16_t g_whi[(size_t)HID * HID];

// ---------------------------------------------------------------------------
// helpers (baseline PTX only: cp.async / ldmatrix / mma.sync — sm_80 features)
// ---------------------------------------------------------------------------
__device__ __forceinline__ uint32_t smem_u32(const void* p) {
    uint32_t a;
    asm("{ .reg .u64 t; cvta.to.shared.u64 t, %1; cvt.u32.u64 %0, t; }"
        : "=r"(a) : "l"(p));
    return a;
}

#define SWZ(x) ((x) ^ (((x) >> 3) & 0x70))

__device__ __forceinline__ void cp16(uint32_t dst, const void* src) {
    asm volatile("cp.async.cg.shared.global [%0], [%1], 16;\n"
                 :: "r"(dst), "l"(src) : "memory");
}
__device__ __forceinline__ void cp_commit() {
    asm volatile("cp.async.commit_group;\n" ::: "memory");
}
template <int N> __device__ __forceinline__ void cp_wait() {
    asm volatile("cp.async.wait_group %0;\n" :: "n"(N) : "memory");
}

__device__ __forceinline__ void ldsm4(uint32_t r[4], uint32_t a) {
    asm volatile("ldmatrix.sync.aligned.m8n8.x4.shared.b16 {%0,%1,%2,%3}, [%4];"
                 : "=r"(r[0]), "=r"(r[1]), "=r"(r[2]), "=r"(r[3]) : "r"(a));
}

// fp16 mma
__device__ __forceinline__ void mma16816h(float c[4], const uint32_t a[4],
                                          const uint32_t b0, const uint32_t b1) {
    asm volatile(
        "mma.sync.aligned.m16n8k16.row.col.f32.f16.f16.f32 "
        "{%0,%1,%2,%3}, {%4,%5,%6,%7}, {%8,%9}, {%0,%1,%2,%3};"
        : "+f"(c[0]), "+f"(c[1]), "+f"(c[2]), "+f"(c[3])
        : "r"(a[0]), "r"(a[1]), "r"(a[2]), "r"(a[3]), "r"(b0), "r"(b1));
}

__device__ __forceinline__ void hsplit(float x, uint16_t& h, uint16_t& l) {
    __half hb = __float2half_rn(x);
    __half lb = __float2half_rn(x - __half2float(hb));
    h = *(uint16_t*)&hb;
    l = *(uint16_t*)&lb;
}
__device__ __forceinline__ uint16_t f2h(float x) {
    __half hb = __float2half_rn(x);
    return *(uint16_t*)&hb;
}

// ---------------------------------------------------------------------------
// converters
// ---------------------------------------------------------------------------
__global__ __launch_bounds__(256)
void cvt_hilo_h(const float* __restrict__ s,
                uint16_t* __restrict__ hi,
                uint16_t* __restrict__ lo, int n4)
{
    int i = blockIdx.x * blockDim.x + threadIdx.x;
    if (i >= n4) return;
    float4 v = ((const float4*)s)[i];
    uint16_t h[4], l[4];
    hsplit(v.x, h[0], l[0]); hsplit(v.y, h[1], l[1]);
    hsplit(v.z, h[2], l[2]); hsplit(v.w, h[3], l[3]);
    *(uint64_t*)(hi + 4 * (size_t)i) = *(uint64_t*)h;
    *(uint64_t*)(lo + 4 * (size_t)i) = *(uint64_t*)l;
}

__global__ __launch_bounds__(256)
void cvt_hi_h(const float* __restrict__ s,
              uint16_t* __restrict__ hi, int n4)
{
    int i = blockIdx.x * blockDim.x + threadIdx.x;
    if (i >= n4) return;
    float4 v = ((const float4*)s)[i];
    uint16_t h[4];
    h[0] = f2h(v.x); h[1] = f2h(v.y); h[2] = f2h(v.z); h[3] = f2h(v.w);
    *(uint64_t*)(hi + 4 * (size_t)i) = *(uint64_t*)h;
}

// ---------------------------------------------------------------------------
// fp16 GEMM (R7-proven schedule): C = (Ah [+ Al]) @ Bh^T (+ optional residual)
// USE_LO selects 2-product (hi+lo activations) vs single-product.
// CTA 128x128, BK=64, GS=3 cp.async pipeline, occupancy 1, 8 warps,
// warp tile 64(m) x 32(n).
// ---------------------------------------------------------------------------
#define TILE_B   16384
#define H2_STAGE (3 * TILE_B)              // Ahi, Alo, Bh = 48KB
#define H2_SMEM  (1024 + 3 * H2_STAGE)     // 148480
#define KTILES   (Kdim / 64)               // 32

template <bool USE_LO>
__global__ __launch_bounds__(256, 1)
void gemm_h2_kernel(const uint16_t* __restrict__ Ahi,
                    const uint16_t* __restrict__ Alo,
                    const uint16_t* __restrict__ Bh,
                    float* __restrict__ C,
                    const float* __restrict__ Res)
{
    extern __shared__ uint8_t smraw[];
    const uint32_t s0 = (smem_u32(smraw) + 1023u) & ~1023u;

    const int tid  = threadIdx.x;
    const int wid  = tid >> 5;
    const int lane = tid & 31;
    const int wm   = wid & 1;        // 2 m-warps, 64 rows
    const int wn   = wid >> 1;       // 4 n-warps, 32 cols
    const int m0 = blockIdx.y * 128;
    const int n0 = blockIdx.x * 128;

    uint32_t aBase[4];
    {
        int amat = lane >> 3, al = lane & 7;
        int rofs = ((amat & 1) << 3) + al;
        uint32_t akb = (uint32_t)((amat >> 1) << 4);
#pragma unroll
        for (int mf = 0; mf < 4; ++mf) {
            uint32_t r = (uint32_t)(wm * 64 + mf * 16 + rofs) * 128u;
            aBase[mf] = SWZ(r) ^ akb;
        }
    }
    uint32_t bBase[2];
    {
        int bmat = lane >> 3, bl = lane & 7;
        int rofs = ((bmat >> 1) << 3) + bl;
        uint32_t bkb = (uint32_t)((bmat & 1) << 4);
#pragma unroll
        for (int nfp = 0; nfp < 2; ++nfp) {
            uint32_t r = (uint32_t)(wn * 32 + nfp * 16 + rofs) * 128u;
            bBase[nfp] = SWZ(r) ^ bkb;
        }
    }

    auto load_stage = [&](int kt) {
        uint32_t sb = s0 + (uint32_t)(kt % 3) * H2_STAGE;
        const size_t kof = (size_t)kt * 64;
#pragma unroll
        for (int j = 0; j < 4; ++j) {
            int q = j * 256 + tid;
            int row = q >> 3, ch = q & 7;
            uint32_t so = SWZ((uint32_t)(row * 128 + ch * 16));
            size_t ga = (size_t)(m0 + row) * Kdim + kof + (size_t)ch * 8;
            size_t gb = (size_t)(n0 + row) * Kdim + kof + (size_t)ch * 8;
            cp16(sb + so, Ahi + ga);
            if (USE_LO) cp16(sb + TILE_B + so, Alo + ga);
            cp16(sb + 2 * TILE_B + so, Bh + gb);
        }
        cp_commit();
    };

    float acc[4][4][4];
#pragma unroll
    for (int i = 0; i < 4; ++i)
#pragma unroll
        for (int j = 0; j < 4; ++j)
#pragma unroll
            for (int r = 0; r < 4; ++r) acc[i][j][r] = 0.f;

    load_stage(0);
    load_stage(1);

    for (int it = 0; it < KTILES; ++it) {
        cp_wait<1>();
        __syncthreads();
        if (it + 2 < KTILES) load_stage(it + 2);

        const uint32_t sb = s0 + (uint32_t)(it % 3) * H2_STAGE;
#pragma unroll
        for (int kk = 0; kk < 4; ++kk) {
            const uint32_t kx = (uint32_t)(kk * 32);
            uint32_t ah[4][4], al[4][4];
#pragma unroll
            for (int mf = 0; mf < 4; ++mf) {
                ldsm4(ah[mf], sb + (aBase[mf] ^ kx));
                if (USE_LO) ldsm4(al[mf], sb + TILE_B + (aBase[mf] ^ kx));
            }
            uint32_t bh[4][2];
#pragma unroll
            for (int nfp = 0; nfp < 2; ++nfp) {
                uint32_t t[4];
                ldsm4(t, sb + 2 * TILE_B + (bBase[nfp] ^ kx));
                bh[2 * nfp][0] = t[0]; bh[2 * nfp][1] = t[1];
                bh[2 * nfp + 1][0] = t[2]; bh[2 * nfp + 1][1] = t[3];
            }
#pragma unroll
            for (int mf = 0; mf < 4; ++mf)
#pragma unroll
                for (int nf = 0; nf < 4; ++nf) {
                    mma16816h(acc[mf][nf], ah[mf], bh[nf][0], bh[nf][1]);
                    if (USE_LO)
                        mma16816h(acc[mf][nf], al[mf], bh[nf][0], bh[nf][1]);
                }
        }
    }

    const int cm = (lane >> 2);
    const int cn = (lane & 3) * 2;
#pragma unroll
    for (int mf = 0; mf < 4; ++mf) {
        const int row = m0 + wm * 64 + mf * 16 + cm;
#pragma unroll
        for (int nf = 0; nf < 4; ++nf) {
            const int col = n0 + wn * 32 + nf * 8 + cn;
            float2 v0 = make_float2(acc[mf][nf][0], acc[mf][nf][1]);
            float2 v1 = make_float2(acc[mf][nf][2], acc[mf][nf][3]);
            if (Res) {
                float2 r0 = *(const float2*)(Res + (size_t)row * Ndim + col);
                float2 r1 = *(const float2*)(Res + (size_t)(row + 8) * Ndim + col);
                v0.x += r0.x; v0.y += r0.y;
                v1.x += r1.x; v1.y += r1.y;
            }
            *(float2*)(C + (size_t)row * Ndim + col)       = v0;
            *(float2*)(C + (size_t)(row + 8) * Ndim + col) = v1;
        }
    }
}

// ---------------------------------------------------------------------------
// RoPE on g_k
// ---------------------------------------------------------------------------
__global__ void rope_kernel(float* __restrict__ k)
{
    const int gid = blockIdx.x * blockDim.x + threadIdx.x;
    const int total = Bsz * Ssz * HEADS * (HDIM / 2);
    if (gid >= total) return;
    const int i   = gid & 63;
    const int h   = (gid >> 6) & (HEADS - 1);
    const int row = gid >> 10;
    const int s   = row & (Ssz - 1);

    const float c = 0.20762050593046013f;   // log2(10000)/64
    const float inv = exp2f(-c * (float)i);
    const float ang = (float)s * inv;
    float sn = sinf(ang), cs = cosf(ang);

    float* p = k + (size_t)row * HID + h * HDIM;
    const float k1 = p[i];
    const float k2 = p[i + 64];
    p[i]      = k1 * cs - k2 * sn;
    p[i + 64] = k2 * cs + k1 * sn;
}

// ---------------------------------------------------------------------------
// Tensor-core TTT scan, fp16 2-product numerics (R9-proven).
// Grid (64 bh, 2 e-halves), 128 threads (4 warps).
// ---------------------------------------------------------------------------
#define OFF_RAWK   0            // [2][16][128] f32 = 16384
#define OFF_RAWV   16384        // [2][16][64]  f32 = 8192
#define OFF_KHI    24576        // [2 buf][2 half][2048B] = 8192
#define OFF_KLO    32768        // 8192
#define OFF_KTHI   40960        // [128][48B] = 6144
#define OFF_KTLO   47104        // 6144
#define OFF_ETHI   53248        // [64][48B] = 3072
#define OFF_WTHI   56320        // [2 half][8192B] = 16384
#define SCAN2_SMEM 72704

__global__ __launch_bounds__(128, 1)
void ttt_scan_mma(const float* __restrict__ gk,
                  const float* __restrict__ gv,
                  const float* __restrict__ W0,
                  float*       __restrict__ go)
{
    extern __shared__ __align__(16) char sm[];
    const uint32_t sb = smem_u32(sm);

    const int tid  = threadIdx.x;
    const int wid  = tid >> 5;
    const int lane = tid & 31;
    const int bh = blockIdx.x;
    const int eh = blockIdx.y;
    const int b  = bh >> 4, h = bh & 15;
    const int e0 = eh * 64;

    const int mat = lane >> 3, ml = lane & 7;
    const int arow = ((mat & 1) << 3) + ml;
    const uint32_t akb = (uint32_t)((mat >> 1) << 4);
    const int brow = ((mat >> 1) << 3) + ml;
    const uint32_t bkb = (uint32_t)((mat & 1) << 4);

    const uint32_t aBaseK = SWZ((uint32_t)(arow * 128)) ^ akb;
    const uint32_t bBaseW = SWZ((uint32_t)((16 * wid + brow) * 128)) ^ bkb;

    const int cr = lane >> 2;
    const int cc = (lane & 3) * 2;

    float W[2][8][4];
    {
        const float* W0p = W0 + (size_t)bh * (HDIM * HDIM);
#pragma unroll
        for (int t2 = 0; t2 < 2; ++t2) {
            int dt = 32 * wid + 16 * t2;
#pragma unroll
            for (int j = 0; j < 8; ++j) {
                int e = e0 + 8 * j + cc;
                W[t2][j][0] = W0p[(size_t)(dt + cr) * 128 + e];
                W[t2][j][1] = W0p[(size_t)(dt + cr) * 128 + e + 1];
                W[t2][j][2] = W0p[(size_t)(dt + cr + 8) * 128 + e];
                W[t2][j][3] = W0p[(size_t)(dt + cr + 8) * 128 + e + 1];
            }
        }
    }

    const float* kbase = gk + (size_t)b * Ssz * HID + h * HDIM;
    const float* vbase = gv + (size_t)b * Ssz * HID + h * HDIM + e0;
    float*       obase = go + (size_t)b * Ssz * HID + h * HDIM + e0;

    auto dumpW = [&]() {
#pragma unroll
        for (int t2 = 0; t2 < 2; ++t2) {
            int dt = 32 * wid + 16 * t2;
#pragma unroll
            for (int j = 0; j < 8; ++j) {
                int e = 8 * j + cc;
#pragma unroll
                for (int q = 0; q < 4; ++q) {
                    int d  = dt + cr + ((q >> 1) << 3);
                    int ee = e + (q & 1);
                    uint32_t half = (uint32_t)(d >> 6);
                    uint32_t a = SWZ((uint32_t)(ee * 128 + (d & 63) * 2));
                    *(uint16_t*)(sm + OFF_WTHI + half * 8192 + a) = f2h(W[t2][j][q]);
                }
            }
        }
    };

    auto loadKV = [&](int c) {
        int buf = c & 1;
        const float* ks = kbase + (size_t)(c * 16) * HID;
        const float* vs = vbase + (size_t)(c * 16) * HID;
#pragma unroll
        for (int j = 0; j < 4; ++j) {
            int q = j * 128 + tid;
            int row = q >> 5, ch = q & 31;
            cp16(sb + OFF_RAWK + buf * 8192 + (uint32_t)(row * 512 + ch * 16),
                 ks + (size_t)row * HID + ch * 4);
        }
#pragma unroll
        for (int j = 0; j < 2; ++j) {
            int q = j * 128 + tid;
            int row = q >> 4, ch = q & 15;
            cp16(sb + OFF_RAWV + buf * 4096 + (uint32_t)(row * 256 + ch * 16),
                 vs + (size_t)row * HID + ch * 4);
        }
        cp_commit();
    };

    auto convK = [&](int c) {
        int buf = c & 1;
        const float* rk = (const float*)(sm + OFF_RAWK + buf * 8192);
        int m = tid >> 3, c16 = (tid & 7) * 16;
        __align__(16) uint16_t hb[16], lb[16];
#pragma unroll
        for (int i = 0; i < 16; ++i) hsplit(rk[m * 128 + c16 + i], hb[i], lb[i]);
        uint32_t half = (uint32_t)(c16 >= 64);
        uint32_t ccl  = (uint32_t)((c16 & 63) * 2);
        uint32_t a0 = SWZ((uint32_t)(m * 128) + ccl);
        uint32_t a1 = SWZ((uint32_t)(m * 128) + ccl + 16);
        uint32_t kb = (uint32_t)(OFF_KHI + buf * 4096 + half * 2048);
        *(uint4*)(sm + kb + a0) = *(uint4*)&hb[0];
        *(uint4*)(sm + kb + a1) = *(uint4*)&hb[8];
        kb = (uint32_t)(OFF_KLO + buf * 4096 + half * 2048);
        *(uint4*)(sm + kb + a0) = *(uint4*)&lb[0];
        *(uint4*)(sm + kb + a1) = *(uint4*)&lb[8];
    };

    auto convKT = [&](int c) {
        int buf = c & 1;
        const float* rk = (const float*)(sm + OFF_RAWK + buf * 8192);
        int d = tid;
        __align__(16) uint16_t th[16], tl[16];
#pragma unroll
        for (int m = 0; m < 16; ++m) hsplit(rk[m * 128 + d], th[m], tl[m]);
        *(uint4*)(sm + OFF_KTHI + d * 48)      = *(uint4*)&th[0];
        *(uint4*)(sm + OFF_KTHI + d * 48 + 16) = *(uint4*)&th[8];
        *(uint4*)(sm + OFF_KTLO + d * 48)      = *(uint4*)&tl[0];
        *(uint4*)(sm + OFF_KTLO + d * 48 + 16) = *(uint4*)&tl[8];
    };

    float P[2][4];

    auto predOnly = [&](int buf, float acc[2][4]) {
#pragma unroll
        for (int f = 0; f < 2; ++f)
#pragma unroll
            for (int q = 0; q < 4; ++q) acc[f][q] = 0.f;
#pragma unroll
        for (int kk = 0; kk < 8; ++kk) {
            uint32_t half = (uint32_t)(kk >> 2);
            uint32_t kx   = (uint32_t)((kk & 3) * 32);
            uint32_t ah[4], al[4], t[4], bh[2][2];
            ldsm4(ah, sb + OFF_KHI + buf * 4096 + half * 2048 + (aBaseK ^ kx));
            ldsm4(al, sb + OFF_KLO + buf * 4096 + half * 2048 + (aBaseK ^ kx));
            ldsm4(t, sb + OFF_WTHI + half * 8192 + (bBaseW ^ kx));
            bh[0][0] = t[0]; bh[0][1] = t[1]; bh[1][0] = t[2]; bh[1][1] = t[3];
#pragma unroll
            for (int f = 0; f < 2; ++f) {
                mma16816h(acc[f], ah, bh[f][0], bh[f][1]);
                mma16816h(acc[f], al, bh[f][0], bh[f][1]);
            }
        }
    };

    dumpW();
    loadKV(0);
    cp_wait<0>();
    __syncthreads();
    convK(0);
    __syncthreads();
    predOnly(0, P);

    for (int c = 0; c < NCH; ++c) {
        const int buf = c & 1;
        const bool hasNext = (c + 1 < NCH);
        if (hasNext) loadKV(c + 1);

        convKT(c);

        // E' = (V - pred) / 1024, fp16 (hi only — B side)
        {
            const float* rv = (const float*)(sm + OFF_RAWV + buf * 4096);
#pragma unroll
            for (int f = 0; f < 2; ++f)
#pragma unroll
                for (int q = 0; q < 4; ++q) {
                    int e = 16 * wid + 8 * f + cc + (q & 1);
                    int m = cr + ((q >> 1) << 3);
                    float ep = (rv[m * 64 + e] - P[f][q]) * 0.0009765625f;
                    *(uint16_t*)(sm + OFF_ETHI + e * 48 + m * 2) = f2h(ep);
                }
        }
        __syncthreads();

        // W += K^T @ E'   (A = K^T hi+lo fp16, B = E' fp16)
        {
            uint32_t aH[2][4], aL[2][4];
#pragma unroll
            for (int t2 = 0; t2 < 2; ++t2) {
                uint32_t ra = (uint32_t)((32 * wid + 16 * t2 + arow) * 48) + akb;
                ldsm4(aH[t2], sb + OFF_KTHI + ra);
                ldsm4(aL[t2], sb + OFF_KTLO + ra);
            }
#pragma unroll
            for (int p = 0; p < 4; ++p) {
                uint32_t rb = (uint32_t)((16 * p + brow) * 48) + bkb;
                uint32_t th[4];
                ldsm4(th, sb + OFF_ETHI + rb);
#pragma unroll
                for (int t2 = 0; t2 < 2; ++t2) {
                    mma16816h(W[t2][2 * p],     aH[t2], th[0], th[1]);
                    mma16816h(W[t2][2 * p],     aL[t2], th[0], th[1]);
                    mma16816h(W[t2][2 * p + 1], aH[t2], th[2], th[3]);
                    mma16816h(W[t2][2 * p + 1], aL[t2], th[2], th[3]);
                }
            }
        }

        dumpW();

        if (hasNext) cp_wait<0>();
        __syncthreads();
        if (hasNext) convK(c + 1);
        __syncthreads();

        // fused: out_c = K_c @ W_new (+ pred_{c+1} = K_{c+1} @ W_new)
        {
            float O[2][4];
#pragma unroll
            for (int f = 0; f < 2; ++f)
#pragma unroll
                for (int q = 0; q < 4; ++q) { O[f][q] = 0.f; P[f][q] = 0.f; }
            const int bufn = (c + 1) & 1;
#pragma unroll
            for (int kk = 0; kk < 8; ++kk) {
                uint32_t half = (uint32_t)(kk >> 2);
                uint32_t kx   = (uint32_t)((kk & 3) * 32);
                uint32_t t[4], bh[2][2];
                ldsm4(t, sb + OFF_WTHI + half * 8192 + (bBaseW ^ kx));
                bh[0][0] = t[0]; bh[0][1] = t[1]; bh[1][0] = t[2]; bh[1][1] = t[3];

                uint32_t ah[4], al[4];
                ldsm4(ah, sb + OFF_KHI + buf * 4096 + half * 2048 + (aBaseK ^ kx));
                ldsm4(al, sb + OFF_KLO + buf * 4096 + half * 2048 + (aBaseK ^ kx));
#pragma unroll
                for (int f = 0; f < 2; ++f) {
                    mma16816h(O[f], ah, bh[f][0], bh[f][1]);
                    mma16816h(O[f], al, bh[f][0], bh[f][1]);
                }
                if (hasNext) {
                    uint32_t nh[4], nl[4];
                    ldsm4(nh, sb + OFF_KHI + bufn * 4096 + half * 2048 + (aBaseK ^ kx));
                    ldsm4(nl, sb + OFF_KLO + bufn * 4096 + half * 2048 + (aBaseK ^ kx));
#pragma unroll
                    for (int f = 0; f < 2; ++f) {
                        mma16816h(P[f], nh, bh[f][0], bh[f][1]);
                        mma16816h(P[f], nl, bh[f][0], bh[f][1]);
                    }
                }
            }
#pragma unroll
            for (int f = 0; f < 2; ++f) {
                int e = 16 * wid + 8 * f + cc;
                size_t r0 = (size_t)(c * 16 + cr) * HID + e;
                size_t r1 = (size_t)(c * 16 + cr + 8) * HID + e;
                *(float2*)(obase + r0) = make_float2(O[f][0], O[f][1]);
                *(float2*)(obase + r1) = make_float2(O[f][2], O[f][3]);
            }
        }
    }
}

// ---------------------------------------------------------------------------
// LayerNorm fused with fp16 round (hi plane only — single-product out GEMM)
// ---------------------------------------------------------------------------
__global__ __launch_bounds__(256)
void ln_cvt_kernel(const float* __restrict__ o,
                   const float* __restrict__ g,
                   const float* __restrict__ beta,
                   uint16_t* __restrict__ hi)
{
    __shared__ float s1[8], s2[8];
    const int row = blockIdx.x;
    const int t   = threadIdx.x;
    const float* p = o + (size_t)row * HID;

    float4 v0 = *(const float4*)(p + t * 8);
    float4 v1 = *(const float4*)(p + t * 8 + 4);
    float s  = v0.x + v0.y + v0.z + v0.w + v1.x + v1.y + v1.z + v1.w;
    float ss = v0.x*v0.x + v0.y*v0.y + v0.z*v0.z + v0.w*v0.w
             + v1.x*v1.x + v1.y*v1.y + v1.z*v1.z + v1.w*v1.w;
#pragma unroll
    for (int off = 16; off > 0; off >>= 1) {
        s  += __shfl_xor_sync(0xffffffffu, s,  off);
        ss += __shfl_xor_sync(0xffffffffu, ss, off);
    }
    const int w = t >> 5;
    if ((t & 31) == 0) { s1[w] = s; s2[w] = ss; }
    __syncthreads();
    float tot = 0.f, tot2 = 0.f;
#pragma unroll
    for (int i = 0; i < 8; ++i) { tot += s1[i]; tot2 += s2[i]; }
    const float mu  = tot * (1.0f / HID);
    const float var = tot2 * (1.0f / HID) - mu * mu;
    const float inv = rsqrtf(var + 1e-5f);

    float4 g0 = *(const float4*)(g + t * 8);
    float4 g1 = *(const float4*)(g + t * 8 + 4);
    float4 b0 = *(const float4*)(beta + t * 8);
    float4 b1 = *(const float4*)(beta + t * 8 + 4);
    float y[8];
    y[0] = (v0.x - mu) * inv * g0.x + b0.x;
    y[1] = (v0.y - mu) * inv * g0.y + b0.y;
    y[2] = (v0.z - mu) * inv * g0.z + b0.z;
    y[3] = (v0.w - mu) * inv * g0.w + b0.w;
    y[4] = (v1.x - mu) * inv * g1.x + b1.x;
    y[5] = (v1.y - mu) * inv * g1.y + b1.y;
    y[6] = (v1.z - mu) * inv * g1.z + b1.z;
    y[7] = (v1.w - mu) * inv * g1.w + b1.w;

    __align__(16) uint16_t hb[8];
#pragma unroll
    for (int i = 0; i < 8; ++i) hb[i] = f2h(y[i]);
    *(uint4*)(hi + (size_t)row * HID + t * 8) = *(uint4*)hb;
}

// ---------------------------------------------------------------------------
// launch
// ---------------------------------------------------------------------------
extern "C" void kernel_launch(void* const* d_in, const int* in_sizes, int n_in,
                              void* d_out, int out_size)
{
    const float* x   = (const float*)d_in[0];
    const float* Wk  = (const float*)d_in[1];
    const float* Wv  = (const float*)d_in[2];
    const float* Wo  = (const float*)d_in[3];
    const float* lng = (const float*)d_in[4];
    const float* lnb = (const float*)d_in[5];
    const float* W0  = (const float*)d_in[6];
    float* out = (float*)d_out;

    float *gk, *gv, *go;
    uint16_t *ahi, *alo, *whi;
    cudaGetSymbolAddress((void**)&gk, g_k);
    cudaGetSymbolAddress((void**)&gv, g_v);
    cudaGetSymbolAddress((void**)&go, g_o);
    cudaGetSymbolAddress((void**)&ahi, g_ahi);
    cudaGetSymbolAddress((void**)&alo, g_alo);
    cudaGetSymbolAddress((void**)&whi, g_whi);

    cudaFuncSetAttribute(ttt_scan_mma,
                         cudaFuncAttributeMaxDynamicSharedMemorySize, SCAN2_SMEM);
    cudaFuncSetAttribute(gemm_h2_kernel<true>,
                         cudaFuncAttributeMaxDynamicSharedMemorySize, H2_SMEM);
    cudaFuncSetAttribute(gemm_h2_kernel<false>,
                         cudaFuncAttributeMaxDynamicSharedMemorySize, H2_SMEM);

    const int nx4 = (Mrows * HID) / 4;
    const int nw4 = (HID * HID) / 4;
    dim3 gg(Ndim / 128, Mrows / 128);    // (16, 64)

    // split x to fp16 hi/lo
    cvt_hilo_h<<<(nx4 + 255) / 256, 256>>>(x, ahi, alo, nx4);

    // k = x @ Wk^T   (fp16 2-product — k feeds the scan bilinearly, keep exact-ish)
    cvt_hi_h<<<(nw4 + 255) / 256, 256>>>(Wk, whi, nw4);
    gemm_h2_kernel<true><<<gg, 256, H2_SMEM>>>(ahi, alo, whi, gk, nullptr);

    // v = x @ Wv^T   (fp16 single-product; v is only the regression target)
    cvt_hi_h<<<(nw4 + 255) / 256, 256>>>(Wv, whi, nw4);
    gemm_h2_kernel<false><<<gg, 256, H2_SMEM>>>(ahi, alo, whi, gv, nullptr);

    // RoPE on k
    {
        const int total = Bsz * Ssz * HEADS * (HDIM / 2);
        rope_kernel<<<(total + 255) / 256, 256>>>(gk);
    }

    // TTT scan -> o  (tensor-core, e-split, fp16 2-product internals)
    {
        dim3 sg(Bsz * HEADS, 2);
        ttt_scan_mma<<<sg, 128, SCAN2_SMEM>>>(gk, gv, W0, go);
    }

    // LayerNorm fused with fp16 round (hi only)
    ln_cvt_kernel<<<Mrows, 256>>>(go, lng, lnb, ahi);

    // out = x + o_ln @ Wo^T  (fp16 single-product, residual fused;
    // residual x is exact fp32 and dilutes the rounding error)
    cvt_hi_h<<<(nw4 + 255) / 256, 256>>>(Wo, whi, nw4);
    gemm_h2_kernel<false><<<gg, 256, H2_SMEM>>>(ahi, alo, whi, out, x);
}

// round 11
// speedup vs baseline: 2.4283x; 1.1418x over previous
#include <cuda_runtime.h>
#include <cuda_bf16.h>
#include <cuda_fp16.h>
#include <cstdint>

// Problem constants
#define Bsz   4
#define Ssz   2048
#define HID   2048
#define HEADS 16
#define HDIM  128
#define MBsz  16
#define NCH   128
#define Mrows (Bsz*Ssz)    // 8192
#define Kdim  2048
#define Ndim  2048

// Scratch (device globals: allocation-free rule). 16-bit payload is fp16.
__device__ float g_k[(size_t)Mrows * HID];
__device__ float g_v[(size_t)Mrows * HID];
__device__ float g_o[(size_t)Mrows * HID];
__device__ uint16_t g_ahi[(size_t)Mrows * HID];
__device__ uint16_t g_whi[(size_t)HID * HID];

// ---------------------------------------------------------------------------
// helpers (baseline PTX only: cp.async / ldmatrix / mma.sync — sm_80 features)
// ---------------------------------------------------------------------------
__device__ __forceinline__ uint32_t smem_u32(const void* p) {
    uint32_t a;
    asm("{ .reg .u64 t; cvta.to.shared.u64 t, %1; cvt.u32.u64 %0, t; }"
        : "=r"(a) : "l"(p));
    return a;
}

#define SWZ(x) ((x) ^ (((x) >> 3) & 0x70))

__device__ __forceinline__ void cp16(uint32_t dst, const void* src) {
    asm volatile("cp.async.cg.shared.global [%0], [%1], 16;\n"
                 :: "r"(dst), "l"(src) : "memory");
}
__device__ __forceinline__ void cp_commit() {
    asm volatile("cp.async.commit_group;\n" ::: "memory");
}
template <int N> __device__ __forceinline__ void cp_wait() {
    asm volatile("cp.async.wait_group %0;\n" :: "n"(N) : "memory");
}

__device__ __forceinline__ void ldsm4(uint32_t r[4], uint32_t a) {
    asm volatile("ldmatrix.sync.aligned.m8n8.x4.shared.b16 {%0,%1,%2,%3}, [%4];"
                 : "=r"(r[0]), "=r"(r[1]), "=r"(r[2]), "=r"(r[3]) : "r"(a));
}

// fp16 mma
__device__ __forceinline__ void mma16816h(float c[4], const uint32_t a[4],
                                          const uint32_t b0, const uint32_t b1) {
    asm volatile(
        "mma.sync.aligned.m16n8k16.row.col.f32.f16.f16.f32 "
        "{%0,%1,%2,%3}, {%4,%5,%6,%7}, {%8,%9}, {%0,%1,%2,%3};"
        : "+f"(c[0]), "+f"(c[1]), "+f"(c[2]), "+f"(c[3])
        : "r"(a[0]), "r"(a[1]), "r"(a[2]), "r"(a[3]), "r"(b0), "r"(b1));
}

__device__ __forceinline__ void hsplit(float x, uint16_t& h, uint16_t& l) {
    __half hb = __float2half_rn(x);
    __half lb = __float2half_rn(x - __half2float(hb));
    h = *(uint16_t*)&hb;
    l = *(uint16_t*)&lb;
}
__device__ __forceinline__ uint16_t f2h(float x) {
    __half hb = __float2half_rn(x);
    return *(uint16_t*)&hb;
}

// ---------------------------------------------------------------------------
// converter: fp32 -> fp16 (single round)
// ---------------------------------------------------------------------------
__global__ __launch_bounds__(256)
void cvt_hi_h(const float* __restrict__ s,
              uint16_t* __restrict__ hi, int n4)
{
    int i = blockIdx.x * blockDim.x + threadIdx.x;
    if (i >= n4) return;
    float4 v = ((const float4*)s)[i];
    uint16_t h[4];
    h[0] = f2h(v.x); h[1] = f2h(v.y); h[2] = f2h(v.z); h[3] = f2h(v.w);
    *(uint64_t*)(hi + 4 * (size_t)i) = *(uint64_t*)h;
}

// ---------------------------------------------------------------------------
// fp16 single-product GEMM (R9/R10-proven): C = Ah @ Bh^T (+ optional residual)
// CTA 128x128, BK=64, GS=3 cp.async pipeline, occupancy 1, 8 warps,
// warp tile 64(m) x 32(n).
// ---------------------------------------------------------------------------
#define TILE_B   16384
#define H2_STAGE (2 * TILE_B)              // Ahi, Bh = 32KB
#define H2_SMEM  (1024 + 3 * H2_STAGE)
#define KTILES   (Kdim / 64)               // 32

__global__ __launch_bounds__(256, 1)
void gemm_h1_kernel(const uint16_t* __restrict__ Ahi,
                    const uint16_t* __restrict__ Bh,
                    float* __restrict__ C,
                    const float* __restrict__ Res)
{
    extern __shared__ uint8_t smraw[];
    const uint32_t s0 = (smem_u32(smraw) + 1023u) & ~1023u;

    const int tid  = threadIdx.x;
    const int wid  = tid >> 5;
    const int lane = tid & 31;
    const int wm   = wid & 1;        // 2 m-warps, 64 rows
    const int wn   = wid >> 1;       // 4 n-warps, 32 cols
    const int m0 = blockIdx.y * 128;
    const int n0 = blockIdx.x * 128;

    uint32_t aBase[4];
    {
        int amat = lane >> 3, al = lane & 7;
        int rofs = ((amat & 1) << 3) + al;
        uint32_t akb = (uint32_t)((amat >> 1) << 4);
#pragma unroll
        for (int mf = 0; mf < 4; ++mf) {
            uint32_t r = (uint32_t)(wm * 64 + mf * 16 + rofs) * 128u;
            aBase[mf] = SWZ(r) ^ akb;
        }
    }
    uint32_t bBase[2];
    {
        int bmat = lane >> 3, bl = lane & 7;
        int rofs = ((bmat >> 1) << 3) + bl;
        uint32_t bkb = (uint32_t)((bmat & 1) << 4);
#pragma unroll
        for (int nfp = 0; nfp < 2; ++nfp) {
            uint32_t r = (uint32_t)(wn * 32 + nfp * 16 + rofs) * 128u;
            bBase[nfp] = SWZ(r) ^ bkb;
        }
    }

    auto load_stage = [&](int kt) {
        uint32_t sb = s0 + (uint32_t)(kt % 3) * H2_STAGE;
        const size_t kof = (size_t)kt * 64;
#pragma unroll
        for (int j = 0; j < 4; ++j) {
            int q = j * 256 + tid;
            int row = q >> 3, ch = q & 7;
            uint32_t so = SWZ((uint32_t)(row * 128 + ch * 16));
            size_t ga = (size_t)(m0 + row) * Kdim + kof + (size_t)ch * 8;
            size_t gb = (size_t)(n0 + row) * Kdim + kof + (size_t)ch * 8;
            cp16(sb + so,          Ahi + ga);
            cp16(sb + TILE_B + so, Bh + gb);
        }
        cp_commit();
    };

    float acc[4][4][4];
#pragma unroll
    for (int i = 0; i < 4; ++i)
#pragma unroll
        for (int j = 0; j < 4; ++j)
#pragma unroll
            for (int r = 0; r < 4; ++r) acc[i][j][r] = 0.f;

    load_stage(0);
    load_stage(1);

    for (int it = 0; it < KTILES; ++it) {
        cp_wait<1>();
        __syncthreads();
        if (it + 2 < KTILES) load_stage(it + 2);

        const uint32_t sb = s0 + (uint32_t)(it % 3) * H2_STAGE;
#pragma unroll
        for (int kk = 0; kk < 4; ++kk) {
            const uint32_t kx = (uint32_t)(kk * 32);
            uint32_t ah[4][4];
#pragma unroll
            for (int mf = 0; mf < 4; ++mf)
                ldsm4(ah[mf], sb + (aBase[mf] ^ kx));
            uint32_t bh[4][2];
#pragma unroll
            for (int nfp = 0; nfp < 2; ++nfp) {
                uint32_t t[4];
                ldsm4(t, sb + TILE_B + (bBase[nfp] ^ kx));
                bh[2 * nfp][0] = t[0]; bh[2 * nfp][1] = t[1];
                bh[2 * nfp + 1][0] = t[2]; bh[2 * nfp + 1][1] = t[3];
            }
#pragma unroll
            for (int mf = 0; mf < 4; ++mf)
#pragma unroll
                for (int nf = 0; nf < 4; ++nf)
                    mma16816h(acc[mf][nf], ah[mf], bh[nf][0], bh[nf][1]);
        }
    }

    const int cm = (lane >> 2);
    const int cn = (lane & 3) * 2;
#pragma unroll
    for (int mf = 0; mf < 4; ++mf) {
        const int row = m0 + wm * 64 + mf * 16 + cm;
#pragma unroll
        for (int nf = 0; nf < 4; ++nf) {
            const int col = n0 + wn * 32 + nf * 8 + cn;
            float2 v0 = make_float2(acc[mf][nf][0], acc[mf][nf][1]);
            float2 v1 = make_float2(acc[mf][nf][2], acc[mf][nf][3]);
            if (Res) {
                float2 r0 = *(const float2*)(Res + (size_t)row * Ndim + col);
                float2 r1 = *(const float2*)(Res + (size_t)(row + 8) * Ndim + col);
                v0.x += r0.x; v0.y += r0.y;
                v1.x += r1.x; v1.y += r1.y;
            }
            *(float2*)(C + (size_t)row * Ndim + col)       = v0;
            *(float2*)(C + (size_t)(row + 8) * Ndim + col) = v1;
        }
    }
}

// ---------------------------------------------------------------------------
// RoPE on g_k
// ---------------------------------------------------------------------------
__global__ void rope_kernel(float* __restrict__ k)
{
    const int gid = blockIdx.x * blockDim.x + threadIdx.x;
    const int total = Bsz * Ssz * HEADS * (HDIM / 2);
    if (gid >= total) return;
    const int i   = gid & 63;
    const int h   = (gid >> 6) & (HEADS - 1);
    const int row = gid >> 10;
    const int s   = row & (Ssz - 1);

    const float c = 0.20762050593046013f;   // log2(10000)/64
    const float inv = exp2f(-c * (float)i);
    const float ang = (float)s * inv;
    float sn = sinf(ang), cs = cosf(ang);

    float* p = k + (size_t)row * HID + h * HDIM;
    const float k1 = p[i];
    const float k2 = p[i + 64];
    p[i]      = k1 * cs - k2 * sn;
    p[i + 64] = k2 * cs + k1 * sn;
}

// ---------------------------------------------------------------------------
// Tensor-core TTT scan, fp16 2-product numerics (R9-proven).
// Grid (64 bh, 2 e-halves), 128 threads (4 warps).
// K is re-split hi/lo fp16 from the fp32 k buffer — scan precision
// independent of the k-GEMM's single-product rounding.
// ---------------------------------------------------------------------------
#define OFF_RAWK   0            // [2][16][128] f32 = 16384
#define OFF_RAWV   16384        // [2][16][64]  f32 = 8192
#define OFF_KHI    24576        // [2 buf][2 half][2048B] = 8192
#define OFF_KLO    32768        // 8192
#define OFF_KTHI   40960        // [128][48B] = 6144
#define OFF_KTLO   47104        // 6144
#define OFF_ETHI   53248        // [64][48B] = 3072
#define OFF_WTHI   56320        // [2 half][8192B] = 16384
#define SCAN2_SMEM 72704

__global__ __launch_bounds__(128, 1)
void ttt_scan_mma(const float* __restrict__ gk,
                  const float* __restrict__ gv,
                  const float* __restrict__ W0,
                  float*       __restrict__ go)
{
    extern __shared__ __align__(16) char sm[];
    const uint32_t sb = smem_u32(sm);

    const int tid  = threadIdx.x;
    const int wid  = tid >> 5;
    const int lane = tid & 31;
    const int bh = blockIdx.x;
    const int eh = blockIdx.y;
    const int b  = bh >> 4, h = bh & 15;
    const int e0 = eh * 64;

    const int mat = lane >> 3, ml = lane & 7;
    const int arow = ((mat & 1) << 3) + ml;
    const uint32_t akb = (uint32_t)((mat >> 1) << 4);
    const int brow = ((mat >> 1) << 3) + ml;
    const uint32_t bkb = (uint32_t)((mat & 1) << 4);

    const uint32_t aBaseK = SWZ((uint32_t)(arow * 128)) ^ akb;
    const uint32_t bBaseW = SWZ((uint32_t)((16 * wid + brow) * 128)) ^ bkb;

    const int cr = lane >> 2;
    const int cc = (lane & 3) * 2;

    float W[2][8][4];
    {
        const float* W0p = W0 + (size_t)bh * (HDIM * HDIM);
#pragma unroll
        for (int t2 = 0; t2 < 2; ++t2) {
            int dt = 32 * wid + 16 * t2;
#pragma unroll
            for (int j = 0; j < 8; ++j) {
                int e = e0 + 8 * j + cc;
                W[t2][j][0] = W0p[(size_t)(dt + cr) * 128 + e];
                W[t2][j][1] = W0p[(size_t)(dt + cr) * 128 + e + 1];
                W[t2][j][2] = W0p[(size_t)(dt + cr + 8) * 128 + e];
                W[t2][j][3] = W0p[(size_t)(dt + cr + 8) * 128 + e + 1];
            }
        }
    }

    const float* kbase = gk + (size_t)b * Ssz * HID + h * HDIM;
    const float* vbase = gv + (size_t)b * Ssz * HID + h * HDIM + e0;
    float*       obase = go + (size_t)b * Ssz * HID + h * HDIM + e0;

    auto dumpW = [&]() {
#pragma unroll
        for (int t2 = 0; t2 < 2; ++t2) {
            int dt = 32 * wid + 16 * t2;
#pragma unroll
            for (int j = 0; j < 8; ++j) {
                int e = 8 * j + cc;
#pragma unroll
                for (int q = 0; q < 4; ++q) {
                    int d  = dt + cr + ((q >> 1) << 3);
                    int ee = e + (q & 1);
                    uint32_t half = (uint32_t)(d >> 6);
                    uint32_t a = SWZ((uint32_t)(ee * 128 + (d & 63) * 2));
                    *(uint16_t*)(sm + OFF_WTHI + half * 8192 + a) = f2h(W[t2][j][q]);
                }
            }
        }
    };

    auto loadKV = [&](int c) {
        int buf = c & 1;
        const float* ks = kbase + (size_t)(c * 16) * HID;
        const float* vs = vbase + (size_t)(c * 16) * HID;
#pragma unroll
        for (int j = 0; j < 4; ++j) {
            int q = j * 128 + tid;
            int row = q >> 5, ch = q & 31;
            cp16(sb + OFF_RAWK + buf * 8192 + (uint32_t)(row * 512 + ch * 16),
                 ks + (size_t)row * HID + ch * 4);
        }
#pragma unroll
        for (int j = 0; j < 2; ++j) {
            int q = j * 128 + tid;
            int row = q >> 4, ch = q & 15;
            cp16(sb + OFF_RAWV + buf * 4096 + (uint32_t)(row * 256 + ch * 16),
                 vs + (size_t)row * HID + ch * 4);
        }
        cp_commit();
    };

    auto convK = [&](int c) {
        int buf = c & 1;
        const float* rk = (const float*)(sm + OFF_RAWK + buf * 8192);
        int m = tid >> 3, c16 = (tid & 7) * 16;
        __align__(16) uint16_t hb[16], lb[16];
#pragma unroll
        for (int i = 0; i < 16; ++i) hsplit(rk[m * 128 + c16 + i], hb[i], lb[i]);
        uint32_t half = (uint32_t)(c16 >= 64);
        uint32_t ccl  = (uint32_t)((c16 & 63) * 2);
        uint32_t a0 = SWZ((uint32_t)(m * 128) + ccl);
        uint32_t a1 = SWZ((uint32_t)(m * 128) + ccl + 16);
        uint32_t kb = (uint32_t)(OFF_KHI + buf * 4096 + half * 2048);
        *(uint4*)(sm + kb + a0) = *(uint4*)&hb[0];
        *(uint4*)(sm + kb + a1) = *(uint4*)&hb[8];
        kb = (uint32_t)(OFF_KLO + buf * 4096 + half * 2048);
        *(uint4*)(sm + kb + a0) = *(uint4*)&lb[0];
        *(uint4*)(sm + kb + a1) = *(uint4*)&lb[8];
    };

    auto convKT = [&](int c) {
        int buf = c & 1;
        const float* rk = (const float*)(sm + OFF_RAWK + buf * 8192);
        int d = tid;
        __align__(16) uint16_t th[16], tl[16];
#pragma unroll
        for (int m = 0; m < 16; ++m) hsplit(rk[m * 128 + d], th[m], tl[m]);
        *(uint4*)(sm + OFF_KTHI + d * 48)      = *(uint4*)&th[0];
        *(uint4*)(sm + OFF_KTHI + d * 48 + 16) = *(uint4*)&th[8];
        *(uint4*)(sm + OFF_KTLO + d * 48)      = *(uint4*)&tl[0];
        *(uint4*)(sm + OFF_KTLO + d * 48 + 16) = *(uint4*)&tl[8];
    };

    float P[2][4];

    auto predOnly = [&](int buf, float acc[2][4]) {
#pragma unroll
        for (int f = 0; f < 2; ++f)
#pragma unroll
            for (int q = 0; q < 4; ++q) acc[f][q] = 0.f;
#pragma unroll
        for (int kk = 0; kk < 8; ++kk) {
            uint32_t half = (uint32_t)(kk >> 2);
            uint32_t kx   = (uint32_t)((kk & 3) * 32);
            uint32_t ah[4], al[4], t[4], bh[2][2];
            ldsm4(ah, sb + OFF_KHI + buf * 4096 + half * 2048 + (aBaseK ^ kx));
            ldsm4(al, sb + OFF_KLO + buf * 4096 + half * 2048 + (aBaseK ^ kx));
            ldsm4(t, sb + OFF_WTHI + half * 8192 + (bBaseW ^ kx));
            bh[0][0] = t[0]; bh[0][1] = t[1]; bh[1][0] = t[2]; bh[1][1] = t[3];
#pragma unroll
            for (int f = 0; f < 2; ++f) {
                mma16816h(acc[f], ah, bh[f][0], bh[f][1]);
                mma16816h(acc[f], al, bh[f][0], bh[f][1]);
            }
        }
    };

    dumpW();
    loadKV(0);
    cp_wait<0>();
    __syncthreads();
    convK(0);
    __syncthreads();
    predOnly(0, P);

    for (int c = 0; c < NCH; ++c) {
        const int buf = c & 1;
        const bool hasNext = (c + 1 < NCH);
        if (hasNext) loadKV(c + 1);

        convKT(c);

        // E' = (V - pred) / 1024, fp16 (hi only — B side)
        {
            const float* rv = (const float*)(sm + OFF_RAWV + buf * 4096);
#pragma unroll
            for (int f = 0; f < 2; ++f)
#pragma unroll
                for (int q = 0; q < 4; ++q) {
                    int e = 16 * wid + 8 * f + cc + (q & 1);
                    int m = cr + ((q >> 1) << 3);
                    float ep = (rv[m * 64 + e] - P[f][q]) * 0.0009765625f;
                    *(uint16_t*)(sm + OFF_ETHI + e * 48 + m * 2) = f2h(ep);
                }
        }
        __syncthreads();

        // W += K^T @ E'   (A = K^T hi+lo fp16, B = E' fp16)
        {
            uint32_t aH[2][4], aL[2][4];
#pragma unroll
            for (int t2 = 0; t2 < 2; ++t2) {
                uint32_t ra = (uint32_t)((32 * wid + 16 * t2 + arow) * 48) + akb;
                ldsm4(aH[t2], sb + OFF_KTHI + ra);
                ldsm4(aL[t2], sb + OFF_KTLO + ra);
            }
#pragma unroll
            for (int p = 0; p < 4; ++p) {
                uint32_t rb = (uint32_t)((16 * p + brow) * 48) + bkb;
                uint32_t th[4];
                ldsm4(th, sb + OFF_ETHI + rb);
#pragma unroll
                for (int t2 = 0; t2 < 2; ++t2) {
                    mma16816h(W[t2][2 * p],     aH[t2], th[0], th[1]);
                    mma16816h(W[t2][2 * p],     aL[t2], th[0], th[1]);
                    mma16816h(W[t2][2 * p + 1], aH[t2], th[2], th[3]);
                    mma16816h(W[t2][2 * p + 1], aL[t2], th[2], th[3]);
                }
            }
        }

        dumpW();

        if (hasNext) cp_wait<0>();
        __syncthreads();
        if (hasNext) convK(c + 1);
        __syncthreads();

        // fused: out_c = K_c @ W_new (+ pred_{c+1} = K_{c+1} @ W_new)
        {
            float O[2][4];
#pragma unroll
            for (int f = 0; f < 2; ++f)
#pragma unroll
                for (int q = 0; q < 4; ++q) { O[f][q] = 0.f; P[f][q] = 0.f; }
            const int bufn = (c + 1) & 1;
#pragma unroll
            for (int kk = 0; kk < 8; ++kk) {
                uint32_t half = (uint32_t)(kk >> 2);
                uint32_t kx   = (uint32_t)((kk & 3) * 32);
                uint32_t t[4], bh[2][2];
                ldsm4(t, sb + OFF_WTHI + half * 8192 + (bBaseW ^ kx));
                bh[0][0] = t[0]; bh[0][1] = t[1]; bh[1][0] = t[2]; bh[1][1] = t[3];

                uint32_t ah[4], al[4];
                ldsm4(ah, sb + OFF_KHI + buf * 4096 + half * 2048 + (aBaseK ^ kx));
                ldsm4(al, sb + OFF_KLO + buf * 4096 + half * 2048 + (aBaseK ^ kx));
#pragma unroll
                for (int f = 0; f < 2; ++f) {
                    mma16816h(O[f], ah, bh[f][0], bh[f][1]);
                    mma16816h(O[f], al, bh[f][0], bh[f][1]);
                }
                if (hasNext) {
                    uint32_t nh[4], nl[4];
                    ldsm4(nh, sb + OFF_KHI + bufn * 4096 + half * 2048 + (aBaseK ^ kx));
                    ldsm4(nl, sb + OFF_KLO + bufn * 4096 + half * 2048 + (aBaseK ^ kx));
#pragma unroll
                    for (int f = 0; f < 2; ++f) {
                        mma16816h(P[f], nh, bh[f][0], bh[f][1]);
                        mma16816h(P[f], nl, bh[f][0], bh[f][1]);
                    }
                }
            }
#pragma unroll
            for (int f = 0; f < 2; ++f) {
                int e = 16 * wid + 8 * f + cc;
                size_t r0 = (size_t)(c * 16 + cr) * HID + e;
                size_t r1 = (size_t)(c * 16 + cr + 8) * HID + e;
                *(float2*)(obase + r0) = make_float2(O[f][0], O[f][1]);
                *(float2*)(obase + r1) = make_float2(O[f][2], O[f][3]);
            }
        }
    }
}

// ---------------------------------------------------------------------------
// LayerNorm fused with fp16 round (hi plane only — single-product out GEMM)
// ---------------------------------------------------------------------------
__global__ __launch_bounds__(256)
void ln_cvt_kernel(const float* __restrict__ o,
                   const float* __restrict__ g,
                   const float* __restrict__ beta,
                   uint16_t* __restrict__ hi)
{
    __shared__ float s1[8], s2[8];
    const int row = blockIdx.x;
    const int t   = threadIdx.x;
    const float* p = o + (size_t)row * HID;

    float4 v0 = *(const float4*)(p + t * 8);
    float4 v1 = *(const float4*)(p + t * 8 + 4);
    float s  = v0.x + v0.y + v0.z + v0.w + v1.x + v1.y + v1.z + v1.w;
    float ss = v0.x*v0.x + v0.y*v0.y + v0.z*v0.z + v0.w*v0.w
             + v1.x*v1.x + v1.y*v1.y + v1.z*v1.z + v1.w*v1.w;
#pragma unroll
    for (int off = 16; off > 0; off >>= 1) {
        s  += __shfl_xor_sync(0xffffffffu, s,  off);
        ss += __shfl_xor_sync(0xffffffffu, ss, off);
    }
    const int w = t >> 5;
    if ((t & 31) == 0) { s1[w] = s; s2[w] = ss; }
    __syncthreads();
    float tot = 0.f, tot2 = 0.f;
#pragma unroll
    for (int i = 0; i < 8; ++i) { tot += s1[i]; tot2 += s2[i]; }
    const float mu  = tot * (1.0f / HID);
    const float var = tot2 * (1.0f / HID) - mu * mu;
    const float inv = rsqrtf(var + 1e-5f);

    float4 g0 = *(const float4*)(g + t * 8);
    float4 g1 = *(const float4*)(g + t * 8 + 4);
    float4 b0 = *(const float4*)(beta + t * 8);
    float4 b1 = *(const float4*)(beta + t * 8 + 4);
    float y[8];
    y[0] = (v0.x - mu) * inv * g0.x + b0.x;
    y[1] = (v0.y - mu) * inv * g0.y + b0.y;
    y[2] = (v0.z - mu) * inv * g0.z + b0.z;
    y[3] = (v0.w - mu) * inv * g0.w + b0.w;
    y[4] = (v1.x - mu) * inv * g1.x + b1.x;
    y[5] = (v1.y - mu) * inv * g1.y + b1.y;
    y[6] = (v1.z - mu) * inv * g1.z + b1.z;
    y[7] = (v1.w - mu) * inv * g1.w + b1.w;

    __align__(16) uint16_t hb[8];
#pragma unroll
    for (int i = 0; i < 8; ++i) hb[i] = f2h(y[i]);
    *(uint4*)(hi + (size_t)row * HID + t * 8) = *(uint4*)hb;
}

// ---------------------------------------------------------------------------
// launch
// ---------------------------------------------------------------------------
extern "C" void kernel_launch(void* const* d_in, const int* in_sizes, int n_in,
                              void* d_out, int out_size)
{
    const float* x   = (const float*)d_in[0];
    const float* Wk  = (const float*)d_in[1];
    const float* Wv  = (const float*)d_in[2];
    const float* Wo  = (const float*)d_in[3];
    const float* lng = (const float*)d_in[4];
    const float* lnb = (const float*)d_in[5];
    const float* W0  = (const float*)d_in[6];
    float* out = (float*)d_out;

    float *gk, *gv, *go;
    uint16_t *ahi, *whi;
    cudaGetSymbolAddress((void**)&gk, g_k);
    cudaGetSymbolAddress((void**)&gv, g_v);
    cudaGetSymbolAddress((void**)&go, g_o);
    cudaGetSymbolAddress((void**)&ahi, g_ahi);
    cudaGetSymbolAddress((void**)&whi, g_whi);

    cudaFuncSetAttribute(ttt_scan_mma,
                         cudaFuncAttributeMaxDynamicSharedMemorySize, SCAN2_SMEM);
    cudaFuncSetAttribute(gemm_h1_kernel,
                         cudaFuncAttributeMaxDynamicSharedMemorySize, H2_SMEM);

    const int nx4 = (Mrows * HID) / 4;
    const int nw4 = (HID * HID) / 4;
    dim3 gg(Ndim / 128, Mrows / 128);    // (16, 64)

    // x -> fp16 (single round; the scan re-splits k in fp32->hi/lo internally)
    cvt_hi_h<<<(nx4 + 255) / 256, 256>>>(x, ahi, nx4);

    // k = x @ Wk^T   (fp16 single-product)
    cvt_hi_h<<<(nw4 + 255) / 256, 256>>>(Wk, whi, nw4);
    gemm_h1_kernel<<<gg, 256, H2_SMEM>>>(ahi, whi, gk, nullptr);

    // v = x @ Wv^T   (fp16 single-product)
    cvt_hi_h<<<(nw4 + 255) / 256, 256>>>(Wv, whi, nw4);
    gemm_h1_kernel<<<gg, 256, H2_SMEM>>>(ahi, whi, gv, nullptr);

    // RoPE on k
    {
        const int total = Bsz * Ssz * HEADS * (HDIM / 2);
        rope_kernel<<<(total + 255) / 256, 256>>>(gk);
    }

    // TTT scan -> o  (tensor-core, e-split, fp16 2-product internals)
    {
        dim3 sg(Bsz * HEADS, 2);
        ttt_scan_mma<<<sg, 128, SCAN2_SMEM>>>(gk, gv, W0, go);
    }

    // LayerNorm fused with fp16 round (hi only)
    ln_cvt_kernel<<<Mrows, 256>>>(go, lng, lnb, ahi);

    // out = x + o_ln @ Wo^T  (fp16 single-product, residual fused)
    cvt_hi_h<<<(nw4 + 255) / 256, 256>>>(Wo, whi, nw4);
    gemm_h1_kernel<<<gg, 256, H2_SMEM>>>(ahi, whi, out, x);
}

// round 12
// speedup vs baseline: 2.7389x; 1.1279x over previous
#include <cuda_runtime.h>
#include <cuda_bf16.h>
#include <cuda_fp16.h>
#include <cstdint>

// Problem constants
#define Bsz   4
#define Ssz   2048
#define HID   2048
#define HEADS 16
#define HDIM  128
#define MBsz  16
#define NCH   128
#define Mrows (Bsz*Ssz)    // 8192
#define Kdim  2048
#define Ndim  2048

// Scratch (device globals: allocation-free rule). 16-bit payload is fp16.
__device__ float g_k[(size_t)Mrows * HID];
__device__ float g_v[(size_t)Mrows * HID];
__device__ float g_o[(size_t)Mrows * HID];
__device__ uint16_t g_ahi[(size_t)Mrows * HID];
__device__ uint16_t g_whi[(size_t)HID * HID];

// ---------------------------------------------------------------------------
// helpers (baseline PTX only: cp.async / ldmatrix / mma.sync — sm_80 features)
// ---------------------------------------------------------------------------
__device__ __forceinline__ uint32_t smem_u32(const void* p) {
    uint32_t a;
    asm("{ .reg .u64 t; cvta.to.shared.u64 t, %1; cvt.u32.u64 %0, t; }"
        : "=r"(a) : "l"(p));
    return a;
}

#define SWZ(x) ((x) ^ (((x) >> 3) & 0x70))

__device__ __forceinline__ void cp16(uint32_t dst, const void* src) {
    asm volatile("cp.async.cg.shared.global [%0], [%1], 16;\n"
                 :: "r"(dst), "l"(src) : "memory");
}
__device__ __forceinline__ void cp_commit() {
    asm volatile("cp.async.commit_group;\n" ::: "memory");
}
template <int N> __device__ __forceinline__ void cp_wait() {
    asm volatile("cp.async.wait_group %0;\n" :: "n"(N) : "memory");
}

__device__ __forceinline__ void ldsm4(uint32_t r[4], uint32_t a) {
    asm volatile("ldmatrix.sync.aligned.m8n8.x4.shared.b16 {%0,%1,%2,%3}, [%4];"
                 : "=r"(r[0]), "=r"(r[1]), "=r"(r[2]), "=r"(r[3]) : "r"(a));
}

// fp16 mma
__device__ __forceinline__ void mma16816h(float c[4], const uint32_t a[4],
                                          const uint32_t b0, const uint32_t b1) {
    asm volatile(
        "mma.sync.aligned.m16n8k16.row.col.f32.f16.f16.f32 "
        "{%0,%1,%2,%3}, {%4,%5,%6,%7}, {%8,%9}, {%0,%1,%2,%3};"
        : "+f"(c[0]), "+f"(c[1]), "+f"(c[2]), "+f"(c[3])
        : "r"(a[0]), "r"(a[1]), "r"(a[2]), "r"(a[3]), "r"(b0), "r"(b1));
}

__device__ __forceinline__ void hsplit(float x, uint16_t& h, uint16_t& l) {
    __half hb = __float2half_rn(x);
    __half lb = __float2half_rn(x - __half2float(hb));
    h = *(uint16_t*)&hb;
    l = *(uint16_t*)&lb;
}
__device__ __forceinline__ uint16_t f2h(float x) {
    __half hb = __float2half_rn(x);
    return *(uint16_t*)&hb;
}

// ---------------------------------------------------------------------------
// converter: fp32 -> fp16 (single round)
// ---------------------------------------------------------------------------
__global__ __launch_bounds__(256)
void cvt_hi_h(const float* __restrict__ s,
              uint16_t* __restrict__ hi, int n4)
{
    int i = blockIdx.x * blockDim.x + threadIdx.x;
    if (i >= n4) return;
    float4 v = ((const float4*)s)[i];
    uint16_t h[4];
    h[0] = f2h(v.x); h[1] = f2h(v.y); h[2] = f2h(v.z); h[3] = f2h(v.w);
    *(uint64_t*)(hi + 4 * (size_t)i) = *(uint64_t*)h;
}

// ---------------------------------------------------------------------------
// fp16 single-product GEMM: C = Ah @ Bh^T (+ optional residual)
// CTA 128x128, BK=64, GS=3 cp.async pipeline, 8 warps, warp tile 64x32.
// OCCUPANCY 2: single-product register footprint (~110) fits the 128-reg cap,
// two CTAs/SM give 4 warps/SMSP to hide HMMA latency + pipeline bubbles.
// ---------------------------------------------------------------------------
#define TILE_B   16384
#define H2_STAGE (2 * TILE_B)              // Ahi, Bh = 32KB
#define H2_SMEM  (1024 + 3 * H2_STAGE)     // 99328 (x2 CTAs = 194KB < 228KB)
#define KTILES   (Kdim / 64)               // 32

__global__ __launch_bounds__(256, 2)
void gemm_h1_kernel(const uint16_t* __restrict__ Ahi,
                    const uint16_t* __restrict__ Bh,
                    float* __restrict__ C,
                    const float* __restrict__ Res)
{
    extern __shared__ uint8_t smraw[];
    const uint32_t s0 = (smem_u32(smraw) + 1023u) & ~1023u;

    const int tid  = threadIdx.x;
    const int wid  = tid >> 5;
    const int lane = tid & 31;
    const int wm   = wid & 1;        // 2 m-warps, 64 rows
    const int wn   = wid >> 1;       // 4 n-warps, 32 cols
    const int m0 = blockIdx.y * 128;
    const int n0 = blockIdx.x * 128;

    uint32_t aBase[4];
    {
        int amat = lane >> 3, al = lane & 7;
        int rofs = ((amat & 1) << 3) + al;
        uint32_t akb = (uint32_t)((amat >> 1) << 4);
#pragma unroll
        for (int mf = 0; mf < 4; ++mf) {
            uint32_t r = (uint32_t)(wm * 64 + mf * 16 + rofs) * 128u;
            aBase[mf] = SWZ(r) ^ akb;
        }
    }
    uint32_t bBase[2];
    {
        int bmat = lane >> 3, bl = lane & 7;
        int rofs = ((bmat >> 1) << 3) + bl;
        uint32_t bkb = (uint32_t)((bmat & 1) << 4);
#pragma unroll
        for (int nfp = 0; nfp < 2; ++nfp) {
            uint32_t r = (uint32_t)(wn * 32 + nfp * 16 + rofs) * 128u;
            bBase[nfp] = SWZ(r) ^ bkb;
        }
    }

    auto load_stage = [&](int kt) {
        uint32_t sb = s0 + (uint32_t)(kt % 3) * H2_STAGE;
        const size_t kof = (size_t)kt * 64;
#pragma unroll
        for (int j = 0; j < 4; ++j) {
            int q = j * 256 + tid;
            int row = q >> 3, ch = q & 7;
            uint32_t so = SWZ((uint32_t)(row * 128 + ch * 16));
            size_t ga = (size_t)(m0 + row) * Kdim + kof + (size_t)ch * 8;
            size_t gb = (size_t)(n0 + row) * Kdim + kof + (size_t)ch * 8;
            cp16(sb + so,          Ahi + ga);
            cp16(sb + TILE_B + so, Bh + gb);
        }
        cp_commit();
    };

    float acc[4][4][4];
#pragma unroll
    for (int i = 0; i < 4; ++i)
#pragma unroll
        for (int j = 0; j < 4; ++j)
#pragma unroll
            for (int r = 0; r < 4; ++r) acc[i][j][r] = 0.f;

    load_stage(0);
    load_stage(1);

    for (int it = 0; it < KTILES; ++it) {
        cp_wait<1>();
        __syncthreads();
        if (it + 2 < KTILES) load_stage(it + 2);

        const uint32_t sb = s0 + (uint32_t)(it % 3) * H2_STAGE;
#pragma unroll
        for (int kk = 0; kk < 4; ++kk) {
            const uint32_t kx = (uint32_t)(kk * 32);
            uint32_t ah[4][4];
#pragma unroll
            for (int mf = 0; mf < 4; ++mf)
                ldsm4(ah[mf], sb + (aBase[mf] ^ kx));
            uint32_t bh[4][2];
#pragma unroll
            for (int nfp = 0; nfp < 2; ++nfp) {
                uint32_t t[4];
                ldsm4(t, sb + TILE_B + (bBase[nfp] ^ kx));
                bh[2 * nfp][0] = t[0]; bh[2 * nfp][1] = t[1];
                bh[2 * nfp + 1][0] = t[2]; bh[2 * nfp + 1][1] = t[3];
            }
#pragma unroll
            for (int mf = 0; mf < 4; ++mf)
#pragma unroll
                for (int nf = 0; nf < 4; ++nf)
                    mma16816h(acc[mf][nf], ah[mf], bh[nf][0], bh[nf][1]);
        }
    }

    const int cm = (lane >> 2);
    const int cn = (lane & 3) * 2;
#pragma unroll
    for (int mf = 0; mf < 4; ++mf) {
        const int row = m0 + wm * 64 + mf * 16 + cm;
#pragma unroll
        for (int nf = 0; nf < 4; ++nf) {
            const int col = n0 + wn * 32 + nf * 8 + cn;
            float2 v0 = make_float2(acc[mf][nf][0], acc[mf][nf][1]);
            float2 v1 = make_float2(acc[mf][nf][2], acc[mf][nf][3]);
            if (Res) {
                float2 r0 = *(const float2*)(Res + (size_t)row * Ndim + col);
                float2 r1 = *(const float2*)(Res + (size_t)(row + 8) * Ndim + col);
                v0.x += r0.x; v0.y += r0.y;
                v1.x += r1.x; v1.y += r1.y;
            }
            *(float2*)(C + (size_t)row * Ndim + col)       = v0;
            *(float2*)(C + (size_t)(row + 8) * Ndim + col) = v1;
        }
    }
}

// ---------------------------------------------------------------------------
// RoPE on g_k
// ---------------------------------------------------------------------------
__global__ void rope_kernel(float* __restrict__ k)
{
    const int gid = blockIdx.x * blockDim.x + threadIdx.x;
    const int total = Bsz * Ssz * HEADS * (HDIM / 2);
    if (gid >= total) return;
    const int i   = gid & 63;
    const int h   = (gid >> 6) & (HEADS - 1);
    const int row = gid >> 10;
    const int s   = row & (Ssz - 1);

    const float c = 0.20762050593046013f;   // log2(10000)/64
    const float inv = exp2f(-c * (float)i);
    const float ang = (float)s * inv;
    float sn = sinf(ang), cs = cosf(ang);

    float* p = k + (size_t)row * HID + h * HDIM;
    const float k1 = p[i];
    const float k2 = p[i + 64];
    p[i]      = k1 * cs - k2 * sn;
    p[i + 64] = k2 * cs + k1 * sn;
}

// ---------------------------------------------------------------------------
// Tensor-core TTT scan, fp16 2-product numerics (R9-proven).
// Grid (64 bh, 2 e-halves), 128 threads (4 warps).
// ---------------------------------------------------------------------------
#define OFF_RAWK   0            // [2][16][128] f32 = 16384
#define OFF_RAWV   16384        // [2][16][64]  f32 = 8192
#define OFF_KHI    24576        // [2 buf][2 half][2048B] = 8192
#define OFF_KLO    32768        // 8192
#define OFF_KTHI   40960        // [128][48B] = 6144
#define OFF_KTLO   47104        // 6144
#define OFF_ETHI   53248        // [64][48B] = 3072
#define OFF_WTHI   56320        // [2 half][8192B] = 16384
#define SCAN2_SMEM 72704

__global__ __launch_bounds__(128, 1)
void ttt_scan_mma(const float* __restrict__ gk,
                  const float* __restrict__ gv,
                  const float* __restrict__ W0,
                  float*       __restrict__ go)
{
    extern __shared__ __align__(16) char sm[];
    const uint32_t sb = smem_u32(sm);

    const int tid  = threadIdx.x;
    const int wid  = tid >> 5;
    const int lane = tid & 31;
    const int bh = blockIdx.x;
    const int eh = blockIdx.y;
    const int b  = bh >> 4, h = bh & 15;
    const int e0 = eh * 64;

    const int mat = lane >> 3, ml = lane & 7;
    const int arow = ((mat & 1) << 3) + ml;
    const uint32_t akb = (uint32_t)((mat >> 1) << 4);
    const int brow = ((mat >> 1) << 3) + ml;
    const uint32_t bkb = (uint32_t)((mat & 1) << 4);

    const uint32_t aBaseK = SWZ((uint32_t)(arow * 128)) ^ akb;
    const uint32_t bBaseW = SWZ((uint32_t)((16 * wid + brow) * 128)) ^ bkb;

    const int cr = lane >> 2;
    const int cc = (lane & 3) * 2;

    float W[2][8][4];
    {
        const float* W0p = W0 + (size_t)bh * (HDIM * HDIM);
#pragma unroll
        for (int t2 = 0; t2 < 2; ++t2) {
            int dt = 32 * wid + 16 * t2;
#pragma unroll
            for (int j = 0; j < 8; ++j) {
                int e = e0 + 8 * j + cc;
                W[t2][j][0] = W0p[(size_t)(dt + cr) * 128 + e];
                W[t2][j][1] = W0p[(size_t)(dt + cr) * 128 + e + 1];
                W[t2][j][2] = W0p[(size_t)(dt + cr + 8) * 128 + e];
                W[t2][j][3] = W0p[(size_t)(dt + cr + 8) * 128 + e + 1];
            }
        }
    }

    const float* kbase = gk + (size_t)b * Ssz * HID + h * HDIM;
    const float* vbase = gv + (size_t)b * Ssz * HID + h * HDIM + e0;
    float*       obase = go + (size_t)b * Ssz * HID + h * HDIM + e0;

    auto dumpW = [&]() {
#pragma unroll
        for (int t2 = 0; t2 < 2; ++t2) {
            int dt = 32 * wid + 16 * t2;
#pragma unroll
            for (int j = 0; j < 8; ++j) {
                int e = 8 * j + cc;
#pragma unroll
                for (int q = 0; q < 4; ++q) {
                    int d  = dt + cr + ((q >> 1) << 3);
                    int ee = e + (q & 1);
                    uint32_t half = (uint32_t)(d >> 6);
                    uint32_t a = SWZ((uint32_t)(ee * 128 + (d & 63) * 2));
                    *(uint16_t*)(sm + OFF_WTHI + half * 8192 + a) = f2h(W[t2][j][q]);
                }
            }
        }
    };

    auto loadKV = [&](int c) {
        int buf = c & 1;
        const float* ks = kbase + (size_t)(c * 16) * HID;
        const float* vs = vbase + (size_t)(c * 16) * HID;
#pragma unroll
        for (int j = 0; j < 4; ++j) {
            int q = j * 128 + tid;
            int row = q >> 5, ch = q & 31;
            cp16(sb + OFF_RAWK + buf * 8192 + (uint32_t)(row * 512 + ch * 16),
                 ks + (size_t)row * HID + ch * 4);
        }
#pragma unroll
        for (int j = 0; j < 2; ++j) {
            int q = j * 128 + tid;
            int row = q >> 4, ch = q & 15;
            cp16(sb + OFF_RAWV + buf * 4096 + (uint32_t)(row * 256 + ch * 16),
                 vs + (size_t)row * HID + ch * 4);
        }
        cp_commit();
    };

    auto convK = [&](int c) {
        int buf = c & 1;
        const float* rk = (const float*)(sm + OFF_RAWK + buf * 8192);
        int m = tid >> 3, c16 = (tid & 7) * 16;
        __align__(16) uint16_t hb[16], lb[16];
#pragma unroll
        for (int i = 0; i < 16; ++i) hsplit(rk[m * 128 + c16 + i], hb[i], lb[i]);
        uint32_t half = (uint32_t)(c16 >= 64);
        uint32_t ccl  = (uint32_t)((c16 & 63) * 2);
        uint32_t a0 = SWZ((uint32_t)(m * 128) + ccl);
        uint32_t a1 = SWZ((uint32_t)(m * 128) + ccl + 16);
        uint32_t kb = (uint32_t)(OFF_KHI + buf * 4096 + half * 2048);
        *(uint4*)(sm + kb + a0) = *(uint4*)&hb[0];
        *(uint4*)(sm + kb + a1) = *(uint4*)&hb[8];
        kb = (uint32_t)(OFF_KLO + buf * 4096 + half * 2048);
        *(uint4*)(sm + kb + a0) = *(uint4*)&lb[0];
        *(uint4*)(sm + kb + a1) = *(uint4*)&lb[8];
    };

    auto convKT = [&](int c) {
        int buf = c & 1;
        const float* rk = (const float*)(sm + OFF_RAWK + buf * 8192);
        int d = tid;
        __align__(16) uint16_t th[16], tl[16];
#pragma unroll
        for (int m = 0; m < 16; ++m) hsplit(rk[m * 128 + d], th[m], tl[m]);
        *(uint4*)(sm + OFF_KTHI + d * 48)      = *(uint4*)&th[0];
        *(uint4*)(sm + OFF_KTHI + d * 48 + 16) = *(uint4*)&th[8];
        *(uint4*)(sm + OFF_KTLO + d * 48)      = *(uint4*)&tl[0];
        *(uint4*)(sm + OFF_KTLO + d * 48 + 16) = *(uint4*)&tl[8];
    };

    float P[2][4];

    auto predOnly = [&](int buf, float acc[2][4]) {
#pragma unroll
        for (int f = 0; f < 2; ++f)
#pragma unroll
            for (int q = 0; q < 4; ++q) acc[f][q] = 0.f;
#pragma unroll
        for (int kk = 0; kk < 8; ++kk) {
            uint32_t half = (uint32_t)(kk >> 2);
            uint32_t kx   = (uint32_t)((kk & 3) * 32);
            uint32_t ah[4], al[4], t[4], bh[2][2];
            ldsm4(ah, sb + OFF_KHI + buf * 4096 + half * 2048 + (aBaseK ^ kx));
            ldsm4(al, sb + OFF_KLO + buf * 4096 + half * 2048 + (aBaseK ^ kx));
            ldsm4(t, sb + OFF_WTHI + half * 8192 + (bBaseW ^ kx));
            bh[0][0] = t[0]; bh[0][1] = t[1]; bh[1][0] = t[2]; bh[1][1] = t[3];
#pragma unroll
            for (int f = 0; f < 2; ++f) {
                mma16816h(acc[f], ah, bh[f][0], bh[f][1]);
                mma16816h(acc[f], al, bh[f][0], bh[f][1]);
            }
        }
    };

    dumpW();
    loadKV(0);
    cp_wait<0>();
    __syncthreads();
    convK(0);
    __syncthreads();
    predOnly(0, P);

    for (int c = 0; c < NCH; ++c) {
        const int buf = c & 1;
        const bool hasNext = (c + 1 < NCH);
        if (hasNext) loadKV(c + 1);

        convKT(c);

        // E' = (V - pred) / 1024, fp16 (hi only — B side)
        {
            const float* rv = (const float*)(sm + OFF_RAWV + buf * 4096);
#pragma unroll
            for (int f = 0; f < 2; ++f)
#pragma unroll
                for (int q = 0; q < 4; ++q) {
                    int e = 16 * wid + 8 * f + cc + (q & 1);
                    int m = cr + ((q >> 1) << 3);
                    float ep = (rv[m * 64 + e] - P[f][q]) * 0.0009765625f;
                    *(uint16_t*)(sm + OFF_ETHI + e * 48 + m * 2) = f2h(ep);
                }
        }
        __syncthreads();

        // W += K^T @ E'   (A = K^T hi+lo fp16, B = E' fp16)
        {
            uint32_t aH[2][4], aL[2][4];
#pragma unroll
            for (int t2 = 0; t2 < 2; ++t2) {
                uint32_t ra = (uint32_t)((32 * wid + 16 * t2 + arow) * 48) + akb;
                ldsm4(aH[t2], sb + OFF_KTHI + ra);
                ldsm4(aL[t2], sb + OFF_KTLO + ra);
            }
#pragma unroll
            for (int p = 0; p < 4; ++p) {
                uint32_t rb = (uint32_t)((16 * p + brow) * 48) + bkb;
                uint32_t th[4];
                ldsm4(th, sb + OFF_ETHI + rb);
#pragma unroll
                for (int t2 = 0; t2 < 2; ++t2) {
                    mma16816h(W[t2][2 * p],     aH[t2], th[0], th[1]);
                    mma16816h(W[t2][2 * p],     aL[t2], th[0], th[1]);
                    mma16816h(W[t2][2 * p + 1], aH[t2], th[2], th[3]);
                    mma16816h(W[t2][2 * p + 1], aL[t2], th[2], th[3]);
                }
            }
        }

        dumpW();

        if (hasNext) cp_wait<0>();
        __syncthreads();
        if (hasNext) convK(c + 1);
        __syncthreads();

        // fused: out_c = K_c @ W_new (+ pred_{c+1} = K_{c+1} @ W_new)
        {
            float O[2][4];
#pragma unroll
            for (int f = 0; f < 2; ++f)
#pragma unroll
                for (int q = 0; q < 4; ++q) { O[f][q] = 0.f; P[f][q] = 0.f; }
            const int bufn = (c + 1) & 1;
#pragma unroll
            for (int kk = 0; kk < 8; ++kk) {
                uint32_t half = (uint32_t)(kk >> 2);
                uint32_t kx   = (uint32_t)((kk & 3) * 32);
                uint32_t t[4], bh[2][2];
                ldsm4(t, sb + OFF_WTHI + half * 8192 + (bBaseW ^ kx));
                bh[0][0] = t[0]; bh[0][1] = t[1]; bh[1][0] = t[2]; bh[1][1] = t[3];

                uint32_t ah[4], al[4];
                ldsm4(ah, sb + OFF_KHI + buf * 4096 + half * 2048 + (aBaseK ^ kx));
                ldsm4(al, sb + OFF_KLO + buf * 4096 + half * 2048 + (aBaseK ^ kx));
#pragma unroll
                for (int f = 0; f < 2; ++f) {
                    mma16816h(O[f], ah, bh[f][0], bh[f][1]);
                    mma16816h(O[f], al, bh[f][0], bh[f][1]);
                }
                if (hasNext) {
                    uint32_t nh[4], nl[4];
                    ldsm4(nh, sb + OFF_KHI + bufn * 4096 + half * 2048 + (aBaseK ^ kx));
                    ldsm4(nl, sb + OFF_KLO + bufn * 4096 + half * 2048 + (aBaseK ^ kx));
#pragma unroll
                    for (int f = 0; f < 2; ++f) {
                        mma16816h(P[f], nh, bh[f][0], bh[f][1]);
                        mma16816h(P[f], nl, bh[f][0], bh[f][1]);
                    }
                }
            }
#pragma unroll
            for (int f = 0; f < 2; ++f) {
                int e = 16 * wid + 8 * f + cc;
                size_t r0 = (size_t)(c * 16 + cr) * HID + e;
                size_t r1 = (size_t)(c * 16 + cr + 8) * HID + e;
                *(float2*)(obase + r0) = make_float2(O[f][0], O[f][1]);
                *(float2*)(obase + r1) = make_float2(O[f][2], O[f][3]);
            }
        }
    }
}

// ---------------------------------------------------------------------------
// LayerNorm fused with fp16 round (hi plane only — single-product out GEMM)
// ---------------------------------------------------------------------------
__global__ __launch_bounds__(256)
void ln_cvt_kernel(const float* __restrict__ o,
                   const float* __restrict__ g,
                   const float* __restrict__ beta,
                   uint16_t* __restrict__ hi)
{
    __shared__ float s1[8], s2[8];
    const int row = blockIdx.x;
    const int t   = threadIdx.x;
    const float* p = o + (size_t)row * HID;

    float4 v0 = *(const float4*)(p + t * 8);
    float4 v1 = *(const float4*)(p + t * 8 + 4);
    float s  = v0.x + v0.y + v0.z + v0.w + v1.x + v1.y + v1.z + v1.w;
    float ss = v0.x*v0.x + v0.y*v0.y + v0.z*v0.z + v0.w*v0.w
             + v1.x*v1.x + v1.y*v1.y + v1.z*v1.z + v1.w*v1.w;
#pragma unroll
    for (int off = 16; off > 0; off >>= 1) {
        s  += __shfl_xor_sync(0xffffffffu, s,  off);
        ss += __shfl_xor_sync(0xffffffffu, ss, off);
    }
    const int w = t >> 5;
    if ((t & 31) == 0) { s1[w] = s; s2[w] = ss; }
    __syncthreads();
    float tot = 0.f, tot2 = 0.f;
#pragma unroll
    for (int i = 0; i < 8; ++i) { tot += s1[i]; tot2 += s2[i]; }
    const float mu  = tot * (1.0f / HID);
    const float var = tot2 * (1.0f / HID) - mu * mu;
    const float inv = rsqrtf(var + 1e-5f);

    float4 g0 = *(const float4*)(g + t * 8);
    float4 g1 = *(const float4*)(g + t * 8 + 4);
    float4 b0 = *(const float4*)(beta + t * 8);
    float4 b1 = *(const float4*)(beta + t * 8 + 4);
    float y[8];
    y[0] = (v0.x - mu) * inv * g0.x + b0.x;
    y[1] = (v0.y - mu) * inv * g0.y + b0.y;
    y[2] = (v0.z - mu) * inv * g0.z + b0.z;
    y[3] = (v0.w - mu) * inv * g0.w + b0.w;
    y[4] = (v1.x - mu) * inv * g1.x + b1.x;
    y[5] = (v1.y - mu) * inv * g1.y + b1.y;
    y[6] = (v1.z - mu) * inv * g1.z + b1.z;
    y[7] = (v1.w - mu) * inv * g1.w + b1.w;

    __align__(16) uint16_t hb[8];
#pragma unroll
    for (int i = 0; i < 8; ++i) hb[i] = f2h(y[i]);
    *(uint4*)(hi + (size_t)row * HID + t * 8) = *(uint4*)hb;
}

// ---------------------------------------------------------------------------
// launch
// ---------------------------------------------------------------------------
extern "C" void kernel_launch(void* const* d_in, const int* in_sizes, int n_in,
                              void* d_out, int out_size)
{
    const float* x   = (const float*)d_in[0];
    const float* Wk  = (const float*)d_in[1];
    const float* Wv  = (const float*)d_in[2];
    const float* Wo  = (const float*)d_in[3];
    const float* lng = (const float*)d_in[4];
    const float* lnb = (const float*)d_in[5];
    const float* W0  = (const float*)d_in[6];
    float* out = (float*)d_out;

    float *gk, *gv, *go;
    uint16_t *ahi, *whi;
    cudaGetSymbolAddress((void**)&gk, g_k);
    cudaGetSymbolAddress((void**)&gv, g_v);
    cudaGetSymbolAddress((void**)&go, g_o);
    cudaGetSymbolAddress((void**)&ahi, g_ahi);
    cudaGetSymbolAddress((void**)&whi, g_whi);

    cudaFuncSetAttribute(ttt_scan_mma,
                         cudaFuncAttributeMaxDynamicSharedMemorySize, SCAN2_SMEM);
    cudaFuncSetAttribute(gemm_h1_kernel,
                         cudaFuncAttributeMaxDynamicSharedMemorySize, H2_SMEM);

    const int nx4 = (Mrows * HID) / 4;
    const int nw4 = (HID * HID) / 4;
    dim3 gg(Ndim / 128, Mrows / 128);    // (16, 64)

    // x -> fp16 (single round; the scan re-splits k in fp32->hi/lo internally)
    cvt_hi_h<<<(nx4 + 255) / 256, 256>>>(x, ahi, nx4);

    // k = x @ Wk^T   (fp16 single-product)
    cvt_hi_h<<<(nw4 + 255) / 256, 256>>>(Wk, whi, nw4);
    gemm_h1_kernel<<<gg, 256, H2_SMEM>>>(ahi, whi, gk, nullptr);

    // v = x @ Wv^T   (fp16 single-product)
    cvt_hi_h<<<(nw4 + 255) / 256, 256>>>(Wv, whi, nw4);
    gemm_h1_kernel<<<gg, 256, H2_SMEM>>>(ahi, whi, gv, nullptr);

    // RoPE on k
    {
        const int total = Bsz * Ssz * HEADS * (HDIM / 2);
        rope_kernel<<<(total + 255) / 256, 256>>>(gk);
    }

    // TTT scan -> o  (tensor-core, e-split, fp16 2-product internals)
    {
        dim3 sg(Bsz * HEADS, 2);
        ttt_scan_mma<<<sg, 128, SCAN2_SMEM>>>(gk, gv, W0, go);
    }

    // LayerNorm fused with fp16 round (hi only)
    ln_cvt_kernel<<<Mrows, 256>>>(go, lng, lnb, ahi);

    // out = x + o_ln @ Wo^T  (fp16 single-product, residual fused)
    cvt_hi_h<<<(nw4 + 255) / 256, 256>>>(Wo, whi, nw4);
    gemm_h1_kernel<<<gg, 256, H2_SMEM>>>(ahi, whi, out, x);
}

// round 13
// speedup vs baseline: 2.7815x; 1.0156x over previous
#include <cuda_runtime.h>
#include <cuda_bf16.h>
#include <cuda_fp16.h>
#include <cstdint>

// Problem constants
#define Bsz   4
#define Ssz   2048
#define HID   2048
#define HEADS 16
#define HDIM  128
#define MBsz  16
#define NCH   128
#define Mrows (Bsz*Ssz)    // 8192
#define Kdim  2048
#define Ndim  2048

// Scratch (device globals: allocation-free rule). 16-bit payload is fp16.
__device__ float g_k[(size_t)Mrows * HID];
__device__ float g_v[(size_t)Mrows * HID];
__device__ float g_o[(size_t)Mrows * HID];
__device__ uint16_t g_ahi[(size_t)Mrows * HID];
__device__ uint16_t g_wk16[(size_t)HID * HID];
__device__ uint16_t g_wv16[(size_t)HID * HID];
__device__ uint16_t g_wo16[(size_t)HID * HID];

// ---------------------------------------------------------------------------
// helpers (baseline PTX only: cp.async / ldmatrix / mma.sync — sm_80 features)
// ---------------------------------------------------------------------------
__device__ __forceinline__ uint32_t smem_u32(const void* p) {
    uint32_t a;
    asm("{ .reg .u64 t; cvta.to.shared.u64 t, %1; cvt.u32.u64 %0, t; }"
        : "=r"(a) : "l"(p));
    return a;
}

#define SWZ(x) ((x) ^ (((x) >> 3) & 0x70))

__device__ __forceinline__ void cp16(uint32_t dst, const void* src) {
    asm volatile("cp.async.cg.shared.global [%0], [%1], 16;\n"
                 :: "r"(dst), "l"(src) : "memory");
}
__device__ __forceinline__ void cp_commit() {
    asm volatile("cp.async.commit_group;\n" ::: "memory");
}
template <int N> __device__ __forceinline__ void cp_wait() {
    asm volatile("cp.async.wait_group %0;\n" :: "n"(N) : "memory");
}

__device__ __forceinline__ void ldsm4(uint32_t r[4], uint32_t a) {
    asm volatile("ldmatrix.sync.aligned.m8n8.x4.shared.b16 {%0,%1,%2,%3}, [%4];"
                 : "=r"(r[0]), "=r"(r[1]), "=r"(r[2]), "=r"(r[3]) : "r"(a));
}

// fp16 mma
__device__ __forceinline__ void mma16816h(float c[4], const uint32_t a[4],
                                          const uint32_t b0, const uint32_t b1) {
    asm volatile(
        "mma.sync.aligned.m16n8k16.row.col.f32.f16.f16.f32 "
        "{%0,%1,%2,%3}, {%4,%5,%6,%7}, {%8,%9}, {%0,%1,%2,%3};"
        : "+f"(c[0]), "+f"(c[1]), "+f"(c[2]), "+f"(c[3])
        : "r"(a[0]), "r"(a[1]), "r"(a[2]), "r"(a[3]), "r"(b0), "r"(b1));
}

__device__ __forceinline__ void hsplit(float x, uint16_t& h, uint16_t& l) {
    __half hb = __float2half_rn(x);
    __half lb = __float2half_rn(x - __half2float(hb));
    h = *(uint16_t*)&hb;
    l = *(uint16_t*)&lb;
}
__device__ __forceinline__ uint16_t f2h(float x) {
    __half hb = __float2half_rn(x);
    return *(uint16_t*)&hb;
}

// ---------------------------------------------------------------------------
// single consolidated converter: x, Wk, Wv, Wo -> fp16 in one launch
// block ranges: [0,16384) x | [16384,20480) Wk | [20480,24576) Wv | [24576,28672) Wo
// ---------------------------------------------------------------------------
#define CVT_XBLK 16384
#define CVT_WBLK 4096
#define CVT_BLKS (CVT_XBLK + 3 * CVT_WBLK)

__global__ __launch_bounds__(256)
void cvt_all_kernel(const float* __restrict__ x,
                    const float* __restrict__ Wk,
                    const float* __restrict__ Wv,
                    const float* __restrict__ Wo,
                    uint16_t* __restrict__ ax,
                    uint16_t* __restrict__ wk,
                    uint16_t* __restrict__ wv,
                    uint16_t* __restrict__ wo)
{
    int bid = blockIdx.x;
    const float* s;
    uint16_t* d;
    if (bid < CVT_XBLK)                      { s = x;  d = ax; }
    else if (bid < CVT_XBLK + CVT_WBLK)      { s = Wk; d = wk; bid -= CVT_XBLK; }
    else if (bid < CVT_XBLK + 2 * CVT_WBLK)  { s = Wv; d = wv; bid -= CVT_XBLK + CVT_WBLK; }
    else                                     { s = Wo; d = wo; bid -= CVT_XBLK + 2 * CVT_WBLK; }

    size_t i = (size_t)bid * 256 + threadIdx.x;
    float4 v = ((const float4*)s)[i];
    uint16_t h[4];
    h[0] = f2h(v.x); h[1] = f2h(v.y); h[2] = f2h(v.z); h[3] = f2h(v.w);
    *(uint64_t*)(d + 4 * i) = *(uint64_t*)h;
}

// ---------------------------------------------------------------------------
// fp16 single-product GEMM core (R12-proven, occ 2):
// C = Ah @ Bh^T (+ optional residual). CTA 128x128, BK=64, GS=3, 8 warps.
// ---------------------------------------------------------------------------
#define TILE_B   16384
#define H2_STAGE (2 * TILE_B)              // Ahi, Bh = 32KB
#define H2_SMEM  (1024 + 3 * H2_STAGE)     // 99328 (x2 CTAs = 194KB < 228KB)
#define KTILES   (Kdim / 64)               // 32

__device__ __forceinline__ void gemm_h1_body(
    const uint16_t* __restrict__ Ahi,
    const uint16_t* __restrict__ Bh,
    float* __restrict__ C,
    const float* __restrict__ Res,
    uint8_t* smraw)
{
    const uint32_t s0 = (smem_u32(smraw) + 1023u) & ~1023u;

    const int tid  = threadIdx.x;
    const int wid  = tid >> 5;
    const int lane = tid & 31;
    const int wm   = wid & 1;        // 2 m-warps, 64 rows
    const int wn   = wid >> 1;       // 4 n-warps, 32 cols
    const int m0 = blockIdx.y * 128;
    const int n0 = blockIdx.x * 128;

    uint32_t aBase[4];
    {
        int amat = lane >> 3, al = lane & 7;
        int rofs = ((amat & 1) << 3) + al;
        uint32_t akb = (uint32_t)((amat >> 1) << 4);
#pragma unroll
        for (int mf = 0; mf < 4; ++mf) {
            uint32_t r = (uint32_t)(wm * 64 + mf * 16 + rofs) * 128u;
            aBase[mf] = SWZ(r) ^ akb;
        }
    }
    uint32_t bBase[2];
    {
        int bmat = lane >> 3, bl = lane & 7;
        int rofs = ((bmat >> 1) << 3) + bl;
        uint32_t bkb = (uint32_t)((bmat & 1) << 4);
#pragma unroll
        for (int nfp = 0; nfp < 2; ++nfp) {
            uint32_t r = (uint32_t)(wn * 32 + nfp * 16 + rofs) * 128u;
            bBase[nfp] = SWZ(r) ^ bkb;
        }
    }

    auto load_stage = [&](int kt) {
        uint32_t sb = s0 + (uint32_t)(kt % 3) * H2_STAGE;
        const size_t kof = (size_t)kt * 64;
#pragma unroll
        for (int j = 0; j < 4; ++j) {
            int q = j * 256 + tid;
            int row = q >> 3, ch = q & 7;
            uint32_t so = SWZ((uint32_t)(row * 128 + ch * 16));
            size_t ga = (size_t)(m0 + row) * Kdim + kof + (size_t)ch * 8;
            size_t gb = (size_t)(n0 + row) * Kdim + kof + (size_t)ch * 8;
            cp16(sb + so,          Ahi + ga);
            cp16(sb + TILE_B + so, Bh + gb);
        }
        cp_commit();
    };

    float acc[4][4][4];
#pragma unroll
    for (int i = 0; i < 4; ++i)
#pragma unroll
        for (int j = 0; j < 4; ++j)
#pragma unroll
            for (int r = 0; r < 4; ++r) acc[i][j][r] = 0.f;

    load_stage(0);
    load_stage(1);

    for (int it = 0; it < KTILES; ++it) {
        cp_wait<1>();
        __syncthreads();
        if (it + 2 < KTILES) load_stage(it + 2);

        const uint32_t sb = s0 + (uint32_t)(it % 3) * H2_STAGE;
#pragma unroll
        for (int kk = 0; kk < 4; ++kk) {
            const uint32_t kx = (uint32_t)(kk * 32);
            uint32_t ah[4][4];
#pragma unroll
            for (int mf = 0; mf < 4; ++mf)
                ldsm4(ah[mf], sb + (aBase[mf] ^ kx));
            uint32_t bh[4][2];
#pragma unroll
            for (int nfp = 0; nfp < 2; ++nfp) {
                uint32_t t[4];
                ldsm4(t, sb + TILE_B + (bBase[nfp] ^ kx));
                bh[2 * nfp][0] = t[0]; bh[2 * nfp][1] = t[1];
                bh[2 * nfp + 1][0] = t[2]; bh[2 * nfp + 1][1] = t[3];
            }
#pragma unroll
            for (int mf = 0; mf < 4; ++mf)
#pragma unroll
                for (int nf = 0; nf < 4; ++nf)
                    mma16816h(acc[mf][nf], ah[mf], bh[nf][0], bh[nf][1]);
        }
    }

    const int cm = (lane >> 2);
    const int cn = (lane & 3) * 2;
#pragma unroll
    for (int mf = 0; mf < 4; ++mf) {
        const int row = m0 + wm * 64 + mf * 16 + cm;
#pragma unroll
        for (int nf = 0; nf < 4; ++nf) {
            const int col = n0 + wn * 32 + nf * 8 + cn;
            float2 v0 = make_float2(acc[mf][nf][0], acc[mf][nf][1]);
            float2 v1 = make_float2(acc[mf][nf][2], acc[mf][nf][3]);
            if (Res) {
                float2 r0 = *(const float2*)(Res + (size_t)row * Ndim + col);
                float2 r1 = *(const float2*)(Res + (size_t)(row + 8) * Ndim + col);
                v0.x += r0.x; v0.y += r0.y;
                v1.x += r1.x; v1.y += r1.y;
            }
            *(float2*)(C + (size_t)row * Ndim + col)       = v0;
            *(float2*)(C + (size_t)(row + 8) * Ndim + col) = v1;
        }
    }
}

// merged k+v GEMM: grid (16, 64, 2); z selects (Wk->k) or (Wv->v)
__global__ __launch_bounds__(256, 2)
void gemm_kv_kernel(const uint16_t* __restrict__ Ahi,
                    const uint16_t* __restrict__ Bk,
                    const uint16_t* __restrict__ Bv,
                    float* __restrict__ Ck,
                    float* __restrict__ Cv)
{
    extern __shared__ uint8_t smraw[];
    if (blockIdx.z == 0) gemm_h1_body(Ahi, Bk, Ck, nullptr, smraw);
    else                 gemm_h1_body(Ahi, Bv, Cv, nullptr, smraw);
}

// single GEMM (output projection): C = Ah @ Bh^T + Res
__global__ __launch_bounds__(256, 2)
void gemm_h1_kernel(const uint16_t* __restrict__ Ahi,
                    const uint16_t* __restrict__ Bh,
                    float* __restrict__ C,
                    const float* __restrict__ Res)
{
    extern __shared__ uint8_t smraw[];
    gemm_h1_body(Ahi, Bh, C, Res, smraw);
}

// ---------------------------------------------------------------------------
// RoPE on g_k
// ---------------------------------------------------------------------------
__global__ void rope_kernel(float* __restrict__ k)
{
    const int gid = blockIdx.x * blockDim.x + threadIdx.x;
    const int total = Bsz * Ssz * HEADS * (HDIM / 2);
    if (gid >= total) return;
    const int i   = gid & 63;
    const int h   = (gid >> 6) & (HEADS - 1);
    const int row = gid >> 10;
    const int s   = row & (Ssz - 1);

    const float c = 0.20762050593046013f;   // log2(10000)/64
    const float inv = exp2f(-c * (float)i);
    const float ang = (float)s * inv;
    float sn = sinf(ang), cs = cosf(ang);

    float* p = k + (size_t)row * HID + h * HDIM;
    const float k1 = p[i];
    const float k2 = p[i + 64];
    p[i]      = k1 * cs - k2 * sn;
    p[i + 64] = k2 * cs + k1 * sn;
}

// ---------------------------------------------------------------------------
// Tensor-core TTT scan, fp16 2-product numerics (R9-proven).
// Grid (64 bh, 2 e-halves), 128 threads (4 warps).
// ---------------------------------------------------------------------------
#define OFF_RAWK   0            // [2][16][128] f32 = 16384
#define OFF_RAWV   16384        // [2][16][64]  f32 = 8192
#define OFF_KHI    24576        // [2 buf][2 half][2048B] = 8192
#define OFF_KLO    32768        // 8192
#define OFF_KTHI   40960        // [128][48B] = 6144
#define OFF_KTLO   47104        // 6144
#define OFF_ETHI   53248        // [64][48B] = 3072
#define OFF_WTHI   56320        // [2 half][8192B] = 16384
#define SCAN2_SMEM 72704

__global__ __launch_bounds__(128, 1)
void ttt_scan_mma(const float* __restrict__ gk,
                  const float* __restrict__ gv,
                  const float* __restrict__ W0,
                  float*       __restrict__ go)
{
    extern __shared__ __align__(16) char sm[];
    const uint32_t sb = smem_u32(sm);

    const int tid  = threadIdx.x;
    const int wid  = tid >> 5;
    const int lane = tid & 31;
    const int bh = blockIdx.x;
    const int eh = blockIdx.y;
    const int b  = bh >> 4, h = bh & 15;
    const int e0 = eh * 64;

    const int mat = lane >> 3, ml = lane & 7;
    const int arow = ((mat & 1) << 3) + ml;
    const uint32_t akb = (uint32_t)((mat >> 1) << 4);
    const int brow = ((mat >> 1) << 3) + ml;
    const uint32_t bkb = (uint32_t)((mat & 1) << 4);

    const uint32_t aBaseK = SWZ((uint32_t)(arow * 128)) ^ akb;
    const uint32_t bBaseW = SWZ((uint32_t)((16 * wid + brow) * 128)) ^ bkb;

    const int cr = lane >> 2;
    const int cc = (lane & 3) * 2;

    float W[2][8][4];
    {
        const float* W0p = W0 + (size_t)bh * (HDIM * HDIM);
#pragma unroll
        for (int t2 = 0; t2 < 2; ++t2) {
            int dt = 32 * wid + 16 * t2;
#pragma unroll
            for (int j = 0; j < 8; ++j) {
                int e = e0 + 8 * j + cc;
                W[t2][j][0] = W0p[(size_t)(dt + cr) * 128 + e];
                W[t2][j][1] = W0p[(size_t)(dt + cr) * 128 + e + 1];
                W[t2][j][2] = W0p[(size_t)(dt + cr + 8) * 128 + e];
                W[t2][j][3] = W0p[(size_t)(dt + cr + 8) * 128 + e + 1];
            }
        }
    }

    const float* kbase = gk + (size_t)b * Ssz * HID + h * HDIM;
    const float* vbase = gv + (size_t)b * Ssz * HID + h * HDIM + e0;
    float*       obase = go + (size_t)b * Ssz * HID + h * HDIM + e0;

    auto dumpW = [&]() {
#pragma unroll
        for (int t2 = 0; t2 < 2; ++t2) {
            int dt = 32 * wid + 16 * t2;
#pragma unroll
            for (int j = 0; j < 8; ++j) {
                int e = 8 * j + cc;
#pragma unroll
                for (int q = 0; q < 4; ++q) {
                    int d  = dt + cr + ((q >> 1) << 3);
                    int ee = e + (q & 1);
                    uint32_t half = (uint32_t)(d >> 6);
                    uint32_t a = SWZ((uint32_t)(ee * 128 + (d & 63) * 2));
                    *(uint16_t*)(sm + OFF_WTHI + half * 8192 + a) = f2h(W[t2][j][q]);
                }
            }
        }
    };

    auto loadKV = [&](int c) {
        int buf = c & 1;
        const float* ks = kbase + (size_t)(c * 16) * HID;
        const float* vs = vbase + (size_t)(c * 16) * HID;
#pragma unroll
        for (int j = 0; j < 4; ++j) {
            int q = j * 128 + tid;
            int row = q >> 5, ch = q & 31;
            cp16(sb + OFF_RAWK + buf * 8192 + (uint32_t)(row * 512 + ch * 16),
                 ks + (size_t)row * HID + ch * 4);
        }
#pragma unroll
        for (int j = 0; j < 2; ++j) {
            int q = j * 128 + tid;
            int row = q >> 4, ch = q & 15;
            cp16(sb + OFF_RAWV + buf * 4096 + (uint32_t)(row * 256 + ch * 16),
                 vs + (size_t)row * HID + ch * 4);
        }
        cp_commit();
    };

    auto convK = [&](int c) {
        int buf = c & 1;
        const float* rk = (const float*)(sm + OFF_RAWK + buf * 8192);
        int m = tid >> 3, c16 = (tid & 7) * 16;
        __align__(16) uint16_t hb[16], lb[16];
#pragma unroll
        for (int i = 0; i < 16; ++i) hsplit(rk[m * 128 + c16 + i], hb[i], lb[i]);
        uint32_t half = (uint32_t)(c16 >= 64);
        uint32_t ccl  = (uint32_t)((c16 & 63) * 2);
        uint32_t a0 = SWZ((uint32_t)(m * 128) + ccl);
        uint32_t a1 = SWZ((uint32_t)(m * 128) + ccl + 16);
        uint32_t kb = (uint32_t)(OFF_KHI + buf * 4096 + half * 2048);
        *(uint4*)(sm + kb + a0) = *(uint4*)&hb[0];
        *(uint4*)(sm + kb + a1) = *(uint4*)&hb[8];
        kb = (uint32_t)(OFF_KLO + buf * 4096 + half * 2048);
        *(uint4*)(sm + kb + a0) = *(uint4*)&lb[0];
        *(uint4*)(sm + kb + a1) = *(uint4*)&lb[8];
    };

    auto convKT = [&](int c) {
        int buf = c & 1;
        const float* rk = (const float*)(sm + OFF_RAWK + buf * 8192);
        int d = tid;
        __align__(16) uint16_t th[16], tl[16];
#pragma unroll
        for (int m = 0; m < 16; ++m) hsplit(rk[m * 128 + d], th[m], tl[m]);
        *(uint4*)(sm + OFF_KTHI + d * 48)      = *(uint4*)&th[0];
        *(uint4*)(sm + OFF_KTHI + d * 48 + 16) = *(uint4*)&th[8];
        *(uint4*)(sm + OFF_KTLO + d * 48)      = *(uint4*)&tl[0];
        *(uint4*)(sm + OFF_KTLO + d * 48 + 16) = *(uint4*)&tl[8];
    };

    float P[2][4];

    auto predOnly = [&](int buf, float acc[2][4]) {
#pragma unroll
        for (int f = 0; f < 2; ++f)
#pragma unroll
            for (int q = 0; q < 4; ++q) acc[f][q] = 0.f;
#pragma unroll
        for (int kk = 0; kk < 8; ++kk) {
            uint32_t half = (uint32_t)(kk >> 2);
            uint32_t kx   = (uint32_t)((kk & 3) * 32);
            uint32_t ah[4], al[4], t[4], bh[2][2];
            ldsm4(ah, sb + OFF_KHI + buf * 4096 + half * 2048 + (aBaseK ^ kx));
            ldsm4(al, sb + OFF_KLO + buf * 4096 + half * 2048 + (aBaseK ^ kx));
            ldsm4(t, sb + OFF_WTHI + half * 8192 + (bBaseW ^ kx));
            bh[0][0] = t[0]; bh[0][1] = t[1]; bh[1][0] = t[2]; bh[1][1] = t[3];
#pragma unroll
            for (int f = 0; f < 2; ++f) {
                mma16816h(acc[f], ah, bh[f][0], bh[f][1]);
                mma16816h(acc[f], al, bh[f][0], bh[f][1]);
            }
        }
    };

    dumpW();
    loadKV(0);
    cp_wait<0>();
    __syncthreads();
    convK(0);
    __syncthreads();
    predOnly(0, P);

    for (int c = 0; c < NCH; ++c) {
        const int buf = c & 1;
        const bool hasNext = (c + 1 < NCH);
        if (hasNext) loadKV(c + 1);

        convKT(c);

        // E' = (V - pred) / 1024, fp16 (hi only — B side)
        {
            const float* rv = (const float*)(sm + OFF_RAWV + buf * 4096);
#pragma unroll
            for (int f = 0; f < 2; ++f)
#pragma unroll
                for (int q = 0; q < 4; ++q) {
                    int e = 16 * wid + 8 * f + cc + (q & 1);
                    int m = cr + ((q >> 1) << 3);
                    float ep = (rv[m * 64 + e] - P[f][q]) * 0.0009765625f;
                    *(uint16_t*)(sm + OFF_ETHI + e * 48 + m * 2) = f2h(ep);
                }
        }
        __syncthreads();

        // W += K^T @ E'
        {
            uint32_t aH[2][4], aL[2][4];
#pragma unroll
            for (int t2 = 0; t2 < 2; ++t2) {
                uint32_t ra = (uint32_t)((32 * wid + 16 * t2 + arow) * 48) + akb;
                ldsm4(aH[t2], sb + OFF_KTHI + ra);
                ldsm4(aL[t2], sb + OFF_KTLO + ra);
            }
#pragma unroll
            for (int p = 0; p < 4; ++p) {
                uint32_t rb = (uint32_t)((16 * p + brow) * 48) + bkb;
                uint32_t th[4];
                ldsm4(th, sb + OFF_ETHI + rb);
#pragma unroll
                for (int t2 = 0; t2 < 2; ++t2) {
                    mma16816h(W[t2][2 * p],     aH[t2], th[0], th[1]);
                    mma16816h(W[t2][2 * p],     aL[t2], th[0], th[1]);
                    mma16816h(W[t2][2 * p + 1], aH[t2], th[2], th[3]);
                    mma16816h(W[t2][2 * p + 1], aL[t2], th[2], th[3]);
                }
            }
        }

        dumpW();

        if (hasNext) cp_wait<0>();
        __syncthreads();
        if (hasNext) convK(c + 1);
        __syncthreads();

        // fused: out_c = K_c @ W_new (+ pred_{c+1} = K_{c+1} @ W_new)
        {
            float O[2][4];
#pragma unroll
            for (int f = 0; f < 2; ++f)
#pragma unroll
                for (int q = 0; q < 4; ++q) { O[f][q] = 0.f; P[f][q] = 0.f; }
            const int bufn = (c + 1) & 1;
#pragma unroll
            for (int kk = 0; kk < 8; ++kk) {
                uint32_t half = (uint32_t)(kk >> 2);
                uint32_t kx   = (uint32_t)((kk & 3) * 32);
                uint32_t t[4], bh[2][2];
                ldsm4(t, sb + OFF_WTHI + half * 8192 + (bBaseW ^ kx));
                bh[0][0] = t[0]; bh[0][1] = t[1]; bh[1][0] = t[2]; bh[1][1] = t[3];

                uint32_t ah[4], al[4];
                ldsm4(ah, sb + OFF_KHI + buf * 4096 + half * 2048 + (aBaseK ^ kx));
                ldsm4(al, sb + OFF_KLO + buf * 4096 + half * 2048 + (aBaseK ^ kx));
#pragma unroll
                for (int f = 0; f < 2; ++f) {
                    mma16816h(O[f], ah, bh[f][0], bh[f][1]);
                    mma16816h(O[f], al, bh[f][0], bh[f][1]);
                }
                if (hasNext) {
                    uint32_t nh[4], nl[4];
                    ldsm4(nh, sb + OFF_KHI + bufn * 4096 + half * 2048 + (aBaseK ^ kx));
                    ldsm4(nl, sb + OFF_KLO + bufn * 4096 + half * 2048 + (aBaseK ^ kx));
#pragma unroll
                    for (int f = 0; f < 2; ++f) {
                        mma16816h(P[f], nh, bh[f][0], bh[f][1]);
                        mma16816h(P[f], nl, bh[f][0], bh[f][1]);
                    }
                }
            }
#pragma unroll
            for (int f = 0; f < 2; ++f) {
                int e = 16 * wid + 8 * f + cc;
                size_t r0 = (size_t)(c * 16 + cr) * HID + e;
                size_t r1 = (size_t)(c * 16 + cr + 8) * HID + e;
                *(float2*)(obase + r0) = make_float2(O[f][0], O[f][1]);
                *(float2*)(obase + r1) = make_float2(O[f][2], O[f][3]);
            }
        }
    }
}

// ---------------------------------------------------------------------------
// LayerNorm fused with fp16 round (hi plane only — single-product out GEMM)
// ---------------------------------------------------------------------------
__global__ __launch_bounds__(256)
void ln_cvt_kernel(const float* __restrict__ o,
                   const float* __restrict__ g,
                   const float* __restrict__ beta,
                   uint16_t* __restrict__ hi)
{
    __shared__ float s1[8], s2[8];
    const int row = blockIdx.x;
    const int t   = threadIdx.x;
    const float* p = o + (size_t)row * HID;

    float4 v0 = *(const float4*)(p + t * 8);
    float4 v1 = *(const float4*)(p + t * 8 + 4);
    float s  = v0.x + v0.y + v0.z + v0.w + v1.x + v1.y + v1.z + v1.w;
    float ss = v0.x*v0.x + v0.y*v0.y + v0.z*v0.z + v0.w*v0.w
             + v1.x*v1.x + v1.y*v1.y + v1.z*v1.z + v1.w*v1.w;
#pragma unroll
    for (int off = 16; off > 0; off >>= 1) {
        s  += __shfl_xor_sync(0xffffffffu, s,  off);
        ss += __shfl_xor_sync(0xffffffffu, ss, off);
    }
    const int w = t >> 5;
    if ((t & 31) == 0) { s1[w] = s; s2[w] = ss; }
    __syncthreads();
    float tot = 0.f, tot2 = 0.f;
#pragma unroll
    for (int i = 0; i < 8; ++i) { tot += s1[i]; tot2 += s2[i]; }
    const float mu  = tot * (1.0f / HID);
    const float var = tot2 * (1.0f / HID) - mu * mu;
    const float inv = rsqrtf(var + 1e-5f);

    float4 g0 = *(const float4*)(g + t * 8);
    float4 g1 = *(const float4*)(g + t * 8 + 4);
    float4 b0 = *(const float4*)(beta + t * 8);
    float4 b1 = *(const float4*)(beta + t * 8 + 4);
    float y[8];
    y[0] = (v0.x - mu) * inv * g0.x + b0.x;
    y[1] = (v0.y - mu) * inv * g0.y + b0.y;
    y[2] = (v0.z - mu) * inv * g0.z + b0.z;
    y[3] = (v0.w - mu) * inv * g0.w + b0.w;
    y[4] = (v1.x - mu) * inv * g1.x + b1.x;
    y[5] = (v1.y - mu) * inv * g1.y + b1.y;
    y[6] = (v1.z - mu) * inv * g1.z + b1.z;
    y[7] = (v1.w - mu) * inv * g1.w + b1.w;

    __align__(16) uint16_t hb[8];
#pragma unroll
    for (int i = 0; i < 8; ++i) hb[i] = f2h(y[i]);
    *(uint4*)(hi + (size_t)row * HID + t * 8) = *(uint4*)hb;
}

// ---------------------------------------------------------------------------
// launch
// ---------------------------------------------------------------------------
extern "C" void kernel_launch(void* const* d_in, const int* in_sizes, int n_in,
                              void* d_out, int out_size)
{
    const float* x   = (const float*)d_in[0];
    const float* Wk  = (const float*)d_in[1];
    const float* Wv  = (const float*)d_in[2];
    const float* Wo  = (const float*)d_in[3];
    const float* lng = (const float*)d_in[4];
    const float* lnb = (const float*)d_in[5];
    const float* W0  = (const float*)d_in[6];
    float* out = (float*)d_out;

    float *gk, *gv, *go;
    uint16_t *ahi, *wk16, *wv16, *wo16;
    cudaGetSymbolAddress((void**)&gk, g_k);
    cudaGetSymbolAddress((void**)&gv, g_v);
    cudaGetSymbolAddress((void**)&go, g_o);
    cudaGetSymbolAddress((void**)&ahi, g_ahi);
    cudaGetSymbolAddress((void**)&wk16, g_wk16);
    cudaGetSymbolAddress((void**)&wv16, g_wv16);
    cudaGetSymbolAddress((void**)&wo16, g_wo16);

    cudaFuncSetAttribute(ttt_scan_mma,
                         cudaFuncAttributeMaxDynamicSharedMemorySize, SCAN2_SMEM);
    cudaFuncSetAttribute(gemm_kv_kernel,
                         cudaFuncAttributeMaxDynamicSharedMemorySize, H2_SMEM);
    cudaFuncSetAttribute(gemm_h1_kernel,
                         cudaFuncAttributeMaxDynamicSharedMemorySize, H2_SMEM);

    // 1. all fp32->fp16 conversions in one launch (x, Wk, Wv, Wo)
    cvt_all_kernel<<<CVT_BLKS, 256>>>(x, Wk, Wv, Wo, ahi, wk16, wv16, wo16);

    // 2. k and v GEMMs merged into one launch (z selects weight/output)
    {
        dim3 gg(Ndim / 128, Mrows / 128, 2);   // (16, 64, 2) = 2048 CTAs
        gemm_kv_kernel<<<gg, 256, H2_SMEM>>>(ahi, wk16, wv16, gk, gv);
    }

    // 3. RoPE on k
    {
        const int total = Bsz * Ssz * HEADS * (HDIM / 2);
        rope_kernel<<<(total + 255) / 256, 256>>>(gk);
    }

    // 4. TTT scan -> o
    {
        dim3 sg(Bsz * HEADS, 2);
        ttt_scan_mma<<<sg, 128, SCAN2_SMEM>>>(gk, gv, W0, go);
    }

    // 5. LayerNorm fused with fp16 round
    ln_cvt_kernel<<<Mrows, 256>>>(go, lng, lnb, ahi);

    // 6. out = x + o_ln @ Wo^T  (Wo already converted in step 1)
    {
        dim3 gg(Ndim / 128, Mrows / 128);
        gemm_h1_kernel<<<gg, 256, H2_SMEM>>>(ahi, wo16, out, x);
    }
}